// round 1
// baseline (speedup 1.0000x reference)
#include <cuda_runtime.h>
#include <math.h>
#include <float.h>

#define BATCH 64
#define NPTS  1024
#define KK    16
#define CH    64

// ---------------- scratch (static device globals; no allocation) ----------------
__device__ __align__(16) float g_x1[BATCH * NPTS * CH];
__device__ __align__(16) float g_x2[BATCH * NPTS * CH];
__device__ __align__(16) float g_x3[BATCH * NPTS * CH];
__device__ int g_idx[BATCH * NPTS * KK];

// ---------------- kNN: per block, PB=8 points; warp-per-point selection ----------
template <int D>
__global__ void __launch_bounds__(256) knn_kernel(const float* __restrict__ feat,
                                                  int* __restrict__ idx_out) {
    constexpr int PB = 8;
    __shared__ __align__(16) float dist[PB][NPTS];
    __shared__ __align__(16) float xis[PB][(D < 4) ? 4 : D];
    __shared__ float sqi[PB];

    const int tid = threadIdx.x;          // 256 threads
    const int gbase = blockIdx.x * PB;    // global point base
    const int b = gbase / NPTS;
    const int i0 = gbase % NPTS;
    const float* fb = feat + (size_t)b * NPTS * D;

    // load the 8 query points
    for (int t = tid; t < PB * D; t += 256) {
        int p = t / D, c = t % D;
        xis[p][c] = fb[(i0 + p) * D + c];
    }
    __syncthreads();
    if (tid < PB) {
        float s = 0.f;
        for (int c = 0; c < D; c++) s += xis[tid][c] * xis[tid][c];
        sqi[tid] = s;
    }
    __syncthreads();

    // distances: thread handles 4 j's, computes dist to all 8 query points
    for (int j = tid; j < NPTS; j += 256) {
        const float* fj = fb + (size_t)j * D;
        float sqj = 0.f;
        float dot[PB];
#pragma unroll
        for (int p = 0; p < PB; p++) dot[p] = 0.f;

        if constexpr (D % 4 == 0) {
            const float4* fj4 = (const float4*)fj;
            for (int c4 = 0; c4 < D / 4; c4++) {
                float4 v = fj4[c4];
                sqj += v.x * v.x + v.y * v.y + v.z * v.z + v.w * v.w;
#pragma unroll
                for (int p = 0; p < PB; p++) {
                    float4 xi = *(const float4*)&xis[p][4 * c4];
                    dot[p] += v.x * xi.x + v.y * xi.y + v.z * xi.z + v.w * xi.w;
                }
            }
        } else {
            for (int c = 0; c < D; c++) {
                float v = fj[c];
                sqj += v * v;
#pragma unroll
                for (int p = 0; p < PB; p++) dot[p] += v * xis[p][c];
            }
        }
#pragma unroll
        for (int p = 0; p < PB; p++) dist[p][j] = sqi[p] + sqj - 2.f * dot[p];
    }
    __syncthreads();

    // selection: warp g picks 16 smallest (ties -> smaller index, like lax.top_k)
    const int g = tid >> 5, lane = tid & 31;
    float* row = dist[g];
    for (int k = 0; k < KK; k++) {
        float bv = FLT_MAX;
        int bi = NPTS;  // sentinel larger than any real index
        for (int t = lane; t < NPTS; t += 32) {
            float v = row[t];
            if (v < bv || (v == bv && t < bi)) { bv = v; bi = t; }
        }
#pragma unroll
        for (int o = 16; o > 0; o >>= 1) {
            float ov = __shfl_xor_sync(0xffffffffu, bv, o);
            int oi = __shfl_xor_sync(0xffffffffu, bi, o);
            if (ov < bv || (ov == bv && oi < bi)) { bv = ov; bi = oi; }
        }
        if (lane == 0) idx_out[((size_t)(b * NPTS + i0 + g)) * KK + k] = bi;
        if ((bi & 31) == lane) row[bi] = FLT_MAX;
        __syncwarp();
    }
}

// ---------------- EdgeConv: relu(e@w1+b1)@w2+b2, max over K ---------------------
// e = [x_i, x_j - x_i]  =>  h1 = base_i + sum_j xj * w1[D:,:],
// base_i = b1 + x_i * (w1[:D,:] - w1[D:,:])
template <int D>
__global__ void __launch_bounds__(256) edgeconv_kernel(
    const float* __restrict__ feat, const int* __restrict__ idx,
    const float* __restrict__ w1, const float* __restrict__ b1,
    const float* __restrict__ w2, const float* __restrict__ b2,
    float* __restrict__ out) {
    constexpr int PTS = 8;
    extern __shared__ float s[];
    float* w1s = s;                           // 2*D*CH
    float* w2s = w1s + 2 * D * CH;            // CH*CH
    float* b1s = w2s + CH * CH;               // CH
    float* b2s = b1s + CH;                    // CH
    float* xis = b2s + CH;                    // PTS*D
    float* xjs = xis + PTS * D;               // PTS*KK*D
    float* h1s = xjs + PTS * KK * D;          // PTS*KK*CH
    int* nbr = (int*)(h1s + PTS * KK * CH);   // PTS*KK

    const int tid = threadIdx.x;  // 256 = 8 warps
    const int p = tid >> 5, lane = tid & 31;
    const int gbase = blockIdx.x * PTS;
    const int b = gbase / NPTS;
    const int i = (gbase % NPTS) + p;
    const float* fb = feat + (size_t)b * NPTS * D;

    for (int t = tid; t < 2 * D * CH; t += 256) w1s[t] = w1[t];
    for (int t = tid; t < CH * CH; t += 256) w2s[t] = w2[t];
    if (tid < CH) { b1s[tid] = b1[tid]; b2s[tid] = b2[tid]; }

    if (lane < KK) nbr[p * KK + lane] = idx[((size_t)(b * NPTS + i)) * KK + lane];
    __syncwarp();
    for (int t = lane; t < D; t += 32) xis[p * D + t] = fb[i * D + t];
    for (int t = lane; t < KK * D; t += 32) {
        int nb = t / D, c = t % D;
        xjs[p * KK * D + t] = fb[(size_t)nbr[p * KK + nb] * D + c];
    }
    __syncthreads();

    const int k0 = 2 * lane;  // each lane owns 2 output channels
    // base
    float bx = b1s[k0], by = b1s[k0 + 1];
    for (int j = 0; j < D; j++) {
        float xv = xis[p * D + j];
        float2 wa = *(const float2*)&w1s[j * CH + k0];
        float2 wb = *(const float2*)&w1s[(D + j) * CH + k0];
        bx += xv * (wa.x - wb.x);
        by += xv * (wa.y - wb.y);
    }
    float2 acc[KK];
#pragma unroll
    for (int nb = 0; nb < KK; nb++) acc[nb] = make_float2(0.f, 0.f);
    for (int j = 0; j < D; j++) {
        float2 w = *(const float2*)&w1s[(D + j) * CH + k0];
        const float* xr = &xjs[p * KK * D + j];
#pragma unroll
        for (int nb = 0; nb < KK; nb++) {
            float xj = xr[nb * D];
            acc[nb].x += xj * w.x;
            acc[nb].y += xj * w.y;
        }
    }
#pragma unroll
    for (int nb = 0; nb < KK; nb++) {
        h1s[p * KK * CH + nb * CH + k0]     = fmaxf(bx + acc[nb].x, 0.f);
        h1s[p * KK * CH + nb * CH + k0 + 1] = fmaxf(by + acc[nb].y, 0.f);
    }
    __syncwarp();  // h1s for point p written/read only by warp p

    // stage 2: h1 @ w2, then max over neighbors
#pragma unroll
    for (int nb = 0; nb < KK; nb++) acc[nb] = make_float2(0.f, 0.f);
    for (int j = 0; j < CH; j++) {
        float2 w = *(const float2*)&w2s[j * CH + k0];
        const float* hr = &h1s[p * KK * CH + j];
#pragma unroll
        for (int nb = 0; nb < KK; nb++) {
            float hv = hr[nb * CH];
            acc[nb].x += hv * w.x;
            acc[nb].y += hv * w.y;
        }
    }
    float mx = -FLT_MAX, my = -FLT_MAX;
#pragma unroll
    for (int nb = 0; nb < KK; nb++) {
        mx = fmaxf(mx, acc[nb].x);
        my = fmaxf(my, acc[nb].y);
    }
    size_t ob = ((size_t)(b * NPTS + i)) * CH;
    out[ob + k0]     = mx + b2s[k0];
    out[ob + k0 + 1] = my + b2s[k0 + 1];
}

// ---------------- final MLP: 192 -> 128 -> 64 -> 32 -> 2, log_softmax ------------
__global__ void __launch_bounds__(512) mlp_kernel(
    const float* __restrict__ x1, const float* __restrict__ x2,
    const float* __restrict__ x3,
    const float* __restrict__ mw1, const float* __restrict__ mb1,
    const float* __restrict__ mw2, const float* __restrict__ mb2,
    const float* __restrict__ mw3, const float* __restrict__ mb3,
    const float* __restrict__ mw4, const float* __restrict__ mb4,
    float* __restrict__ out) {
    extern __shared__ float s[];
    float* w1s = s;               // 192*128 = 24576
    float* w2s = w1s + 24576;     // 128*64  = 8192
    float* w3s = w2s + 8192;      // 64*32   = 2048
    float* w4s = w3s + 2048;      // 32*2    = 64
    float* b1s = w4s + 64;        // 128
    float* b2s = b1s + 128;       // 64
    float* b3s = b2s + 64;        // 32
    float* b4s = b3s + 32;        // 2
    float* fbuf = b4s + 2;        // 16 warps * 192
    float* hbuf = fbuf + 16 * 192;// 16 warps * 128

    const int tid = threadIdx.x;  // 512 = 16 warps
    const int w = tid >> 5, lane = tid & 31;
    for (int t = tid; t < 24576; t += 512) w1s[t] = mw1[t];
    for (int t = tid; t < 8192; t += 512) w2s[t] = mw2[t];
    for (int t = tid; t < 2048; t += 512) w3s[t] = mw3[t];
    if (tid < 64) w4s[tid] = mw4[tid];
    if (tid < 128) b1s[tid] = mb1[tid];
    if (tid < 64) b2s[tid] = mb2[tid];
    if (tid < 32) b3s[tid] = mb3[tid];
    if (tid < 2) b4s[tid] = mb4[tid];
    __syncthreads();

    const int ptsPerBlock = (BATCH * NPTS) / gridDim.x;
    const int pbase = blockIdx.x * ptsPerBlock;
    float* f = fbuf + w * 192;
    float* h = hbuf + w * 128;

    for (int pt = pbase + w; pt < pbase + ptsPerBlock; pt += 16) {
        for (int t = lane; t < 64; t += 32) {
            f[t]       = x1[(size_t)pt * 64 + t];
            f[64 + t]  = x2[(size_t)pt * 64 + t];
            f[128 + t] = x3[(size_t)pt * 64 + t];
        }
        __syncwarp();
        // layer 1: 192 -> 128, lane owns 4 channels
        float4 a1 = *(const float4*)&b1s[4 * lane];
        for (int j = 0; j < 192; j++) {
            float xv = f[j];
            float4 wv = *(const float4*)&w1s[j * 128 + 4 * lane];
            a1.x += xv * wv.x; a1.y += xv * wv.y; a1.z += xv * wv.z; a1.w += xv * wv.w;
        }
        h[4 * lane]     = fmaxf(a1.x, 0.f);
        h[4 * lane + 1] = fmaxf(a1.y, 0.f);
        h[4 * lane + 2] = fmaxf(a1.z, 0.f);
        h[4 * lane + 3] = fmaxf(a1.w, 0.f);
        __syncwarp();
        // layer 2: 128 -> 64, lane owns 2 channels; result into f[0:64]
        float2 a2 = *(const float2*)&b2s[2 * lane];
        for (int j = 0; j < 128; j++) {
            float hv = h[j];
            float2 wv = *(const float2*)&w2s[j * 64 + 2 * lane];
            a2.x += hv * wv.x; a2.y += hv * wv.y;
        }
        __syncwarp();
        f[2 * lane]     = fmaxf(a2.x, 0.f);
        f[2 * lane + 1] = fmaxf(a2.y, 0.f);
        __syncwarp();
        // layer 3: 64 -> 32, lane owns 1 channel; result into h[0:32]
        float a3 = b3s[lane];
        for (int j = 0; j < 64; j++) a3 += f[j] * w3s[j * 32 + lane];
        a3 = fmaxf(a3, 0.f);
        __syncwarp();
        h[lane] = a3;
        __syncwarp();
        // layer 4 + log_softmax (2 classes)
        float o = 0.f;
        if (lane < 2) {
            o = b4s[lane];
            for (int j = 0; j < 32; j++) o += h[j] * w4s[j * 2 + lane];
        }
        float oo = __shfl_xor_sync(0xffffffffu, o, 1);
        if (lane < 2) {
            float mm = fmaxf(o, oo);
            float lse = mm + logf(expf(o - mm) + expf(oo - mm));
            out[(size_t)pt * 2 + lane] = o - lse;
        }
        __syncwarp();
    }
}

// ---------------- launch -------------------------------------------------------
static constexpr size_t ec_smem(int D) {
    return (size_t)(2 * D * CH + CH * CH + 2 * CH + 8 * D + 8 * KK * D +
                    8 * KK * CH + 8 * KK) * 4;
}
static constexpr size_t MLP_SMEM =
    (size_t)(24576 + 8192 + 2048 + 64 + 128 + 64 + 32 + 2 + 16 * 192 + 16 * 128) * 4;

extern "C" void kernel_launch(void* const* d_in, const int* in_sizes, int n_in,
                              void* d_out, int out_size) {
    (void)in_sizes; (void)n_in; (void)out_size;
    const float* x    = (const float*)d_in[0];
    const float* c1w1 = (const float*)d_in[1];
    const float* c1b1 = (const float*)d_in[2];
    const float* c1w2 = (const float*)d_in[3];
    const float* c1b2 = (const float*)d_in[4];
    const float* c2w1 = (const float*)d_in[5];
    const float* c2b1 = (const float*)d_in[6];
    const float* c2w2 = (const float*)d_in[7];
    const float* c2b2 = (const float*)d_in[8];
    const float* c3w1 = (const float*)d_in[9];
    const float* c3b1 = (const float*)d_in[10];
    const float* c3w2 = (const float*)d_in[11];
    const float* c3b2 = (const float*)d_in[12];
    const float* mw1  = (const float*)d_in[13];
    const float* mb1  = (const float*)d_in[14];
    const float* mw2  = (const float*)d_in[15];
    const float* mb2  = (const float*)d_in[16];
    const float* mw3  = (const float*)d_in[17];
    const float* mb3  = (const float*)d_in[18];
    const float* mw4  = (const float*)d_in[19];
    const float* mb4  = (const float*)d_in[20];
    float* outp = (float*)d_out;

    float *x1p, *x2p, *x3p;
    int* idxp;
    cudaGetSymbolAddress((void**)&x1p, g_x1);
    cudaGetSymbolAddress((void**)&x2p, g_x2);
    cudaGetSymbolAddress((void**)&x3p, g_x3);
    cudaGetSymbolAddress((void**)&idxp, g_idx);

    cudaFuncSetAttribute(edgeconv_kernel<1>,
                         cudaFuncAttributeMaxDynamicSharedMemorySize, (int)ec_smem(1));
    cudaFuncSetAttribute(edgeconv_kernel<64>,
                         cudaFuncAttributeMaxDynamicSharedMemorySize, (int)ec_smem(64));
    cudaFuncSetAttribute(mlp_kernel,
                         cudaFuncAttributeMaxDynamicSharedMemorySize, (int)MLP_SMEM);

    const int nblk = BATCH * NPTS / 8;  // 8192

    knn_kernel<1><<<nblk, 256>>>(x, idxp);
    edgeconv_kernel<1><<<nblk, 256, ec_smem(1)>>>(x, idxp, c1w1, c1b1, c1w2, c1b2, x1p);
    knn_kernel<64><<<nblk, 256>>>(x1p, idxp);
    edgeconv_kernel<64><<<nblk, 256, ec_smem(64)>>>(x1p, idxp, c2w1, c2b1, c2w2, c2b2, x2p);
    knn_kernel<64><<<nblk, 256>>>(x2p, idxp);
    edgeconv_kernel<64><<<nblk, 256, ec_smem(64)>>>(x2p, idxp, c3w1, c3b1, c3w2, c3b2, x3p);
    mlp_kernel<<<128, 512, MLP_SMEM>>>(x1p, x2p, x3p, mw1, mb1, mw2, mb2,
                                       mw3, mb3, mw4, mb4, outp);
}

// round 3
// speedup vs baseline: 1.1191x; 1.1191x over previous
#include <cuda_runtime.h>
#include <math.h>
#include <float.h>

#define BATCH 64
#define NPTS  1024
#define KK    16
#define CH    64

// ---------------- scratch (static device globals; no allocation) ----------------
__device__ __align__(16) float g_x1[BATCH * NPTS * CH];
__device__ __align__(16) float g_x2[BATCH * NPTS * CH];
__device__ __align__(16) float g_x3[BATCH * NPTS * CH];
__device__ int g_idx[BATCH * NPTS * KK];

// ---------------- kNN: per block, PB=8 points; warp-per-point selection ----------
template <int D>
__global__ void __launch_bounds__(256) knn_kernel(const float* __restrict__ feat,
                                                  int* __restrict__ idx_out) {
    constexpr int PB = 8;
    __shared__ __align__(16) float dist[PB][NPTS];
    __shared__ __align__(16) float xis[PB][(D < 4) ? 4 : D];
    __shared__ float sqi[PB];

    const int tid = threadIdx.x;          // 256 threads
    const int gbase = blockIdx.x * PB;    // global point base
    const int b = gbase / NPTS;
    const int i0 = gbase % NPTS;
    const float* fb = feat + (size_t)b * NPTS * D;

    // load the 8 query points
    for (int t = tid; t < PB * D; t += 256) {
        int p = t / D, c = t % D;
        xis[p][c] = fb[(i0 + p) * D + c];
    }
    __syncthreads();
    if (tid < PB) {
        float s = 0.f;
        for (int c = 0; c < D; c++) s += xis[tid][c] * xis[tid][c];
        sqi[tid] = s;
    }
    __syncthreads();

    // distances: compute dist to all 8 query points
    for (int j = tid; j < NPTS; j += 256) {
        const float* fj = fb + (size_t)j * D;
        float sqj = 0.f;
        float dot[PB];
#pragma unroll
        for (int p = 0; p < PB; p++) dot[p] = 0.f;

        if constexpr (D % 4 == 0) {
            const float4* fj4 = (const float4*)fj;
#pragma unroll 4
            for (int c4 = 0; c4 < D / 4; c4++) {
                float4 v = fj4[c4];
                sqj += v.x * v.x + v.y * v.y + v.z * v.z + v.w * v.w;
#pragma unroll
                for (int p = 0; p < PB; p++) {
                    float4 xi = *(const float4*)&xis[p][4 * c4];
                    dot[p] += v.x * xi.x + v.y * xi.y + v.z * xi.z + v.w * xi.w;
                }
            }
        } else {
            for (int c = 0; c < D; c++) {
                float v = fj[c];
                sqj += v * v;
#pragma unroll
                for (int p = 0; p < PB; p++) dot[p] += v * xis[p][c];
            }
        }
#pragma unroll
        for (int p = 0; p < PB; p++) dist[p][j] = sqi[p] + sqj - 2.f * dot[p];
    }
    __syncthreads();

    // selection: warp g picks 16 smallest (ties -> smaller index, like lax.top_k)
    const int g = tid >> 5, lane = tid & 31;
    float* row = dist[g];
    for (int k = 0; k < KK; k++) {
        float bv = FLT_MAX;
        int bi = NPTS;  // sentinel larger than any real index
        for (int t = lane; t < NPTS; t += 32) {
            float v = row[t];
            if (v < bv || (v == bv && t < bi)) { bv = v; bi = t; }
        }
#pragma unroll
        for (int o = 16; o > 0; o >>= 1) {
            float ov = __shfl_xor_sync(0xffffffffu, bv, o);
            int oi = __shfl_xor_sync(0xffffffffu, bi, o);
            if (ov < bv || (ov == bv && oi < bi)) { bv = ov; bi = oi; }
        }
        if (lane == 0) idx_out[((size_t)(b * NPTS + i0 + g)) * KK + k] = bi;
        if ((bi & 31) == lane) row[bi] = FLT_MAX;
        __syncwarp();
    }
}

// ---------------- EdgeConv: relu(e@w1+b1)@w2+b2, max over K ---------------------
// e = [x_i, x_j - x_i]  =>  h1 = base_i + sum_j xj * w1[D:,:],
// base_i = b1 + x_i * (w1[:D,:] - w1[D:,:])
// Neighbors in chunks of NB=8 (smaller h1 staging -> 2 blocks/SM);
// inner loops use float4 broadcast LDS with j unrolled x4.
template <int D>
__global__ void __launch_bounds__(256, 2) edgeconv_kernel(
    const float* __restrict__ feat, const int* __restrict__ idx,
    const float* __restrict__ w1, const float* __restrict__ b1,
    const float* __restrict__ w2, const float* __restrict__ b2,
    float* __restrict__ out) {
    constexpr int PTS = 8;
    constexpr int NB = 8;  // neighbor chunk
    extern __shared__ float s[];
    float* w1bs = s;                           // D*CH   (w1[D:,:])
    float* wdfs = w1bs + D * CH;               // D*CH   (w1[:D,:]-w1[D:,:])
    float* w2s  = wdfs + D * CH;               // CH*CH
    float* b1s  = w2s + CH * CH;               // CH
    float* b2s  = b1s + CH;                    // CH
    float* xis  = b2s + CH;                    // PTS*D  (D padded to mult of 4 below)
    float* xjs  = xis + PTS * ((D + 3) & ~3);  // PTS*KK*D
    float* h1c  = xjs + PTS * KK * ((D + 3) & ~3); // PTS*NB*CH
    int* nbr    = (int*)(h1c + PTS * NB * CH); // PTS*KK

    const int tid = threadIdx.x;  // 256 = 8 warps
    const int p = tid >> 5, lane = tid & 31;
    const int gbase = blockIdx.x * PTS;
    const int b = gbase / NPTS;
    const int i = (gbase % NPTS) + p;
    const float* fb = feat + (size_t)b * NPTS * D;

    for (int t = tid; t < D * CH; t += 256) {
        float wa = w1[t];
        float wb = w1[D * CH + t];
        w1bs[t] = wb;
        wdfs[t] = wa - wb;
    }
    for (int t = tid; t < CH * CH; t += 256) w2s[t] = w2[t];
    if (tid < CH) { b1s[tid] = b1[tid]; b2s[tid] = b2[tid]; }

    if (lane < KK) nbr[p * KK + lane] = idx[((size_t)(b * NPTS + i)) * KK + lane];
    __syncwarp();
    for (int t = lane; t < D; t += 32) xis[p * D + t] = fb[i * D + t];
    for (int t = lane; t < KK * D; t += 32) {
        int nb = t / D, c = t % D;
        xjs[p * KK * D + t] = fb[(size_t)nbr[p * KK + nb] * D + c];
    }
    __syncthreads();

    const int k0 = 2 * lane;  // each lane owns 2 output channels
    // base_i = b1 + x_i * wdf
    float bx = b1s[k0], by = b1s[k0 + 1];
    for (int j = 0; j < D; j++) {
        float xv = xis[p * D + j];
        float2 wd = *(const float2*)&wdfs[j * CH + k0];
        bx = fmaf(xv, wd.x, bx);
        by = fmaf(xv, wd.y, by);
    }

    float mx = -FLT_MAX, my = -FLT_MAX;

    for (int c0 = 0; c0 < KK; c0 += NB) {
        float2 acc[NB];
#pragma unroll
        for (int nb = 0; nb < NB; nb++) acc[nb] = make_float2(0.f, 0.f);

        if constexpr (D % 4 == 0) {
            const float* xbase = &xjs[p * KK * D + c0 * D];
            for (int j = 0; j < D; j += 4) {
                const float* wb = &w1bs[j * CH + k0];
                float2 wv0 = *(const float2*)(wb);
                float2 wv1 = *(const float2*)(wb + CH);
                float2 wv2 = *(const float2*)(wb + 2 * CH);
                float2 wv3 = *(const float2*)(wb + 3 * CH);
#pragma unroll
                for (int nb = 0; nb < NB; nb++) {
                    float4 xv = *(const float4*)(xbase + nb * D + j);
                    acc[nb].x = fmaf(xv.x, wv0.x, acc[nb].x);
                    acc[nb].y = fmaf(xv.x, wv0.y, acc[nb].y);
                    acc[nb].x = fmaf(xv.y, wv1.x, acc[nb].x);
                    acc[nb].y = fmaf(xv.y, wv1.y, acc[nb].y);
                    acc[nb].x = fmaf(xv.z, wv2.x, acc[nb].x);
                    acc[nb].y = fmaf(xv.z, wv2.y, acc[nb].y);
                    acc[nb].x = fmaf(xv.w, wv3.x, acc[nb].x);
                    acc[nb].y = fmaf(xv.w, wv3.y, acc[nb].y);
                }
            }
        } else {
            for (int j = 0; j < D; j++) {
                float2 w = *(const float2*)&w1bs[j * CH + k0];
                const float* xr = &xjs[p * KK * D + c0 * D + j];
#pragma unroll
                for (int nb = 0; nb < NB; nb++) {
                    float xj = xr[nb * D];
                    acc[nb].x = fmaf(xj, w.x, acc[nb].x);
                    acc[nb].y = fmaf(xj, w.y, acc[nb].y);
                }
            }
        }
        // write h1 chunk (relu), own warp only
#pragma unroll
        for (int nb = 0; nb < NB; nb++) {
            float2 h;
            h.x = fmaxf(bx + acc[nb].x, 0.f);
            h.y = fmaxf(by + acc[nb].y, 0.f);
            *(float2*)&h1c[(p * NB + nb) * CH + k0] = h;
        }
        __syncwarp();

        // stage 2 on this chunk: h1 @ w2
#pragma unroll
        for (int nb = 0; nb < NB; nb++) acc[nb] = make_float2(0.f, 0.f);
        const float* hbase = &h1c[p * NB * CH];
        for (int j = 0; j < CH; j += 4) {
            const float* wb = &w2s[j * CH + k0];
            float2 wv0 = *(const float2*)(wb);
            float2 wv1 = *(const float2*)(wb + CH);
            float2 wv2 = *(const float2*)(wb + 2 * CH);
            float2 wv3 = *(const float2*)(wb + 3 * CH);
#pragma unroll
            for (int nb = 0; nb < NB; nb++) {
                float4 hv = *(const float4*)(hbase + nb * CH + j);
                acc[nb].x = fmaf(hv.x, wv0.x, acc[nb].x);
                acc[nb].y = fmaf(hv.x, wv0.y, acc[nb].y);
                acc[nb].x = fmaf(hv.y, wv1.x, acc[nb].x);
                acc[nb].y = fmaf(hv.y, wv1.y, acc[nb].y);
                acc[nb].x = fmaf(hv.z, wv2.x, acc[nb].x);
                acc[nb].y = fmaf(hv.z, wv2.y, acc[nb].y);
                acc[nb].x = fmaf(hv.w, wv3.x, acc[nb].x);
                acc[nb].y = fmaf(hv.w, wv3.y, acc[nb].y);
            }
        }
#pragma unroll
        for (int nb = 0; nb < NB; nb++) {
            mx = fmaxf(mx, acc[nb].x);
            my = fmaxf(my, acc[nb].y);
        }
        __syncwarp();  // before next chunk overwrites h1c
    }

    size_t ob = ((size_t)(b * NPTS + i)) * CH;
    out[ob + k0]     = mx + b2s[k0];
    out[ob + k0 + 1] = my + b2s[k0 + 1];
}

// ---------------- final MLP: 192 -> 128 -> 64 -> 32 -> 2, log_softmax ------------
__global__ void __launch_bounds__(512) mlp_kernel(
    const float* __restrict__ x1, const float* __restrict__ x2,
    const float* __restrict__ x3,
    const float* __restrict__ mw1, const float* __restrict__ mb1,
    const float* __restrict__ mw2, const float* __restrict__ mb2,
    const float* __restrict__ mw3, const float* __restrict__ mb3,
    const float* __restrict__ mw4, const float* __restrict__ mb4,
    float* __restrict__ out) {
    extern __shared__ float s[];
    float* w1s = s;               // 192*128 = 24576
    float* w2s = w1s + 24576;     // 128*64  = 8192
    float* w3s = w2s + 8192;      // 64*32   = 2048
    float* w4s = w3s + 2048;      // 32*2    = 64
    float* b1s = w4s + 64;        // 128
    float* b2s = b1s + 128;       // 64
    float* b3s = b2s + 64;        // 32
    float* b4s = b3s + 32;        // 4 (2 used + 2 pad -> keep fbuf 16B-aligned)
    float* fbuf = b4s + 4;        // 16 warps * 192   (offset now mult of 4)
    float* hbuf = fbuf + 16 * 192;// 16 warps * 128

    const int tid = threadIdx.x;  // 512 = 16 warps
    const int w = tid >> 5, lane = tid & 31;
    for (int t = tid; t < 24576; t += 512) w1s[t] = mw1[t];
    for (int t = tid; t < 8192; t += 512) w2s[t] = mw2[t];
    for (int t = tid; t < 2048; t += 512) w3s[t] = mw3[t];
    if (tid < 64) w4s[tid] = mw4[tid];
    if (tid < 128) b1s[tid] = mb1[tid];
    if (tid < 64) b2s[tid] = mb2[tid];
    if (tid < 32) b3s[tid] = mb3[tid];
    if (tid < 2) b4s[tid] = mb4[tid];
    __syncthreads();

    const int ptsPerBlock = (BATCH * NPTS) / gridDim.x;
    const int pbase = blockIdx.x * ptsPerBlock;
    float* f = fbuf + w * 192;
    float* h = hbuf + w * 128;

    for (int pt = pbase + w; pt < pbase + ptsPerBlock; pt += 16) {
        for (int t = lane; t < 64; t += 32) {
            f[t]       = x1[(size_t)pt * 64 + t];
            f[64 + t]  = x2[(size_t)pt * 64 + t];
            f[128 + t] = x3[(size_t)pt * 64 + t];
        }
        __syncwarp();
        // layer 1: 192 -> 128, lane owns 4 channels, j unrolled x4
        float4 a1 = *(const float4*)&b1s[4 * lane];
        for (int j = 0; j < 192; j += 4) {
            float4 xv = *(const float4*)&f[j];
            const float* wb = &w1s[j * 128 + 4 * lane];
            float4 w0 = *(const float4*)(wb);
            float4 w1v = *(const float4*)(wb + 128);
            float4 w2v = *(const float4*)(wb + 256);
            float4 w3v = *(const float4*)(wb + 384);
            a1.x = fmaf(xv.x, w0.x, a1.x); a1.y = fmaf(xv.x, w0.y, a1.y);
            a1.z = fmaf(xv.x, w0.z, a1.z); a1.w = fmaf(xv.x, w0.w, a1.w);
            a1.x = fmaf(xv.y, w1v.x, a1.x); a1.y = fmaf(xv.y, w1v.y, a1.y);
            a1.z = fmaf(xv.y, w1v.z, a1.z); a1.w = fmaf(xv.y, w1v.w, a1.w);
            a1.x = fmaf(xv.z, w2v.x, a1.x); a1.y = fmaf(xv.z, w2v.y, a1.y);
            a1.z = fmaf(xv.z, w2v.z, a1.z); a1.w = fmaf(xv.z, w2v.w, a1.w);
            a1.x = fmaf(xv.w, w3v.x, a1.x); a1.y = fmaf(xv.w, w3v.y, a1.y);
            a1.z = fmaf(xv.w, w3v.z, a1.z); a1.w = fmaf(xv.w, w3v.w, a1.w);
        }
        h[4 * lane]     = fmaxf(a1.x, 0.f);
        h[4 * lane + 1] = fmaxf(a1.y, 0.f);
        h[4 * lane + 2] = fmaxf(a1.z, 0.f);
        h[4 * lane + 3] = fmaxf(a1.w, 0.f);
        __syncwarp();
        // layer 2: 128 -> 64, lane owns 2 channels; result into f[0:64]
        float2 a2 = *(const float2*)&b2s[2 * lane];
        for (int j = 0; j < 128; j += 4) {
            float4 hv = *(const float4*)&h[j];
            const float* wb = &w2s[j * 64 + 2 * lane];
            float2 w0 = *(const float2*)(wb);
            float2 w1v = *(const float2*)(wb + 64);
            float2 w2v = *(const float2*)(wb + 128);
            float2 w3v = *(const float2*)(wb + 192);
            a2.x = fmaf(hv.x, w0.x, a2.x); a2.y = fmaf(hv.x, w0.y, a2.y);
            a2.x = fmaf(hv.y, w1v.x, a2.x); a2.y = fmaf(hv.y, w1v.y, a2.y);
            a2.x = fmaf(hv.z, w2v.x, a2.x); a2.y = fmaf(hv.z, w2v.y, a2.y);
            a2.x = fmaf(hv.w, w3v.x, a2.x); a2.y = fmaf(hv.w, w3v.y, a2.y);
        }
        __syncwarp();
        f[2 * lane]     = fmaxf(a2.x, 0.f);
        f[2 * lane + 1] = fmaxf(a2.y, 0.f);
        __syncwarp();
        // layer 3: 64 -> 32, lane owns 1 channel; result into h[0:32]
        float a3 = b3s[lane];
        for (int j = 0; j < 64; j++) a3 = fmaf(f[j], w3s[j * 32 + lane], a3);
        a3 = fmaxf(a3, 0.f);
        __syncwarp();
        h[lane] = a3;
        __syncwarp();
        // layer 4 + log_softmax (2 classes)
        float o = 0.f;
        if (lane < 2) {
            o = b4s[lane];
            for (int j = 0; j < 32; j++) o = fmaf(h[j], w4s[j * 2 + lane], o);
        }
        float oo = __shfl_xor_sync(0xffffffffu, o, 1);
        if (lane < 2) {
            float mm = fmaxf(o, oo);
            float lse = mm + logf(expf(o - mm) + expf(oo - mm));
            out[(size_t)pt * 2 + lane] = o - lse;
        }
        __syncwarp();
    }
}

// ---------------- launch -------------------------------------------------------
static constexpr size_t ec_smem(int D) {
    int Dp = (D + 3) & ~3;
    return (size_t)(2 * D * CH + CH * CH + 2 * CH + 8 * Dp + 8 * KK * Dp +
                    8 * 8 * CH + 8 * KK) * 4;
}
static constexpr size_t MLP_SMEM =
    (size_t)(24576 + 8192 + 2048 + 64 + 128 + 64 + 32 + 4 + 16 * 192 + 16 * 128) * 4;

extern "C" void kernel_launch(void* const* d_in, const int* in_sizes, int n_in,
                              void* d_out, int out_size) {
    (void)in_sizes; (void)n_in; (void)out_size;
    const float* x    = (const float*)d_in[0];
    const float* c1w1 = (const float*)d_in[1];
    const float* c1b1 = (const float*)d_in[2];
    const float* c1w2 = (const float*)d_in[3];
    const float* c1b2 = (const float*)d_in[4];
    const float* c2w1 = (const float*)d_in[5];
    const float* c2b1 = (const float*)d_in[6];
    const float* c2w2 = (const float*)d_in[7];
    const float* c2b2 = (const float*)d_in[8];
    const float* c3w1 = (const float*)d_in[9];
    const float* c3b1 = (const float*)d_in[10];
    const float* c3w2 = (const float*)d_in[11];
    const float* c3b2 = (const float*)d_in[12];
    const float* mw1  = (const float*)d_in[13];
    const float* mb1  = (const float*)d_in[14];
    const float* mw2  = (const float*)d_in[15];
    const float* mb2  = (const float*)d_in[16];
    const float* mw3  = (const float*)d_in[17];
    const float* mb3  = (const float*)d_in[18];
    const float* mw4  = (const float*)d_in[19];
    const float* mb4  = (const float*)d_in[20];
    float* outp = (float*)d_out;

    float *x1p, *x2p, *x3p;
    int* idxp;
    cudaGetSymbolAddress((void**)&x1p, g_x1);
    cudaGetSymbolAddress((void**)&x2p, g_x2);
    cudaGetSymbolAddress((void**)&x3p, g_x3);
    cudaGetSymbolAddress((void**)&idxp, g_idx);

    cudaFuncSetAttribute(edgeconv_kernel<1>,
                         cudaFuncAttributeMaxDynamicSharedMemorySize, (int)ec_smem(1));
    cudaFuncSetAttribute(edgeconv_kernel<64>,
                         cudaFuncAttributeMaxDynamicSharedMemorySize, (int)ec_smem(64));
    cudaFuncSetAttribute(mlp_kernel,
                         cudaFuncAttributeMaxDynamicSharedMemorySize, (int)MLP_SMEM);

    const int nblk = BATCH * NPTS / 8;  // 8192

    knn_kernel<1><<<nblk, 256>>>(x, idxp);
    edgeconv_kernel<1><<<nblk, 256, ec_smem(1)>>>(x, idxp, c1w1, c1b1, c1w2, c1b2, x1p);
    knn_kernel<64><<<nblk, 256>>>(x1p, idxp);
    edgeconv_kernel<64><<<nblk, 256, ec_smem(64)>>>(x1p, idxp, c2w1, c2b1, c2w2, c2b2, x2p);
    knn_kernel<64><<<nblk, 256>>>(x2p, idxp);
    edgeconv_kernel<64><<<nblk, 256, ec_smem(64)>>>(x2p, idxp, c3w1, c3b1, c3w2, c3b2, x3p);
    mlp_kernel<<<128, 512, MLP_SMEM>>>(x1p, x2p, x3p, mw1, mb1, mw2, mb2,
                                       mw3, mb3, mw4, mb4, outp);
}

// round 4
// speedup vs baseline: 1.3006x; 1.1622x over previous
#include <cuda_runtime.h>
#include <math.h>
#include <float.h>

#define BATCH 64
#define NPTS  1024
#define KK    16
#define CH    64

// ---------------- scratch (static device globals; no allocation) ----------------
__device__ __align__(16) float g_x1[BATCH * NPTS * CH];
__device__ __align__(16) float g_x2[BATCH * NPTS * CH];
__device__ __align__(16) float g_x3[BATCH * NPTS * CH];
__device__ int g_idx[BATCH * NPTS * KK];

// ---------------- kNN: per block, PB=8 points; register-resident selection -------
template <int D>
__global__ void __launch_bounds__(256) knn_kernel(const float* __restrict__ feat,
                                                  int* __restrict__ idx_out) {
    constexpr int PB = 8;
    __shared__ __align__(16) float dist[PB][NPTS];
    __shared__ __align__(16) float xis[PB][(D < 4) ? 4 : D];
    __shared__ float sqi[PB];

    const int tid = threadIdx.x;          // 256 threads
    const int gbase = blockIdx.x * PB;    // global point base
    const int b = gbase / NPTS;
    const int i0 = gbase % NPTS;
    const float* fb = feat + (size_t)b * NPTS * D;

    // load the 8 query points
    for (int t = tid; t < PB * D; t += 256) {
        int p = t / D, c = t % D;
        xis[p][c] = fb[(i0 + p) * D + c];
    }
    __syncthreads();
    if (tid < PB) {
        float s = 0.f;
        for (int c = 0; c < D; c++) s += xis[tid][c] * xis[tid][c];
        sqi[tid] = s;
    }
    __syncthreads();

    // distances: each thread computes dist of its j's to all 8 query points
    for (int j = tid; j < NPTS; j += 256) {
        const float* fj = fb + (size_t)j * D;
        float sqj = 0.f;
        float dot[PB];
#pragma unroll
        for (int p = 0; p < PB; p++) dot[p] = 0.f;

        if constexpr (D % 4 == 0) {
            const float4* fj4 = (const float4*)fj;
#pragma unroll 4
            for (int c4 = 0; c4 < D / 4; c4++) {
                float4 v = fj4[c4];
                sqj += v.x * v.x + v.y * v.y + v.z * v.z + v.w * v.w;
#pragma unroll
                for (int p = 0; p < PB; p++) {
                    float4 xi = *(const float4*)&xis[p][4 * c4];
                    dot[p] += v.x * xi.x + v.y * xi.y + v.z * xi.z + v.w * xi.w;
                }
            }
        } else {
            for (int c = 0; c < D; c++) {
                float v = fj[c];
                sqj += v * v;
#pragma unroll
                for (int p = 0; p < PB; p++) dot[p] += v * xis[p][c];
            }
        }
#pragma unroll
        for (int p = 0; p < PB; p++) dist[p][j] = sqi[p] + sqj - 2.f * dot[p];
    }
    __syncthreads();

    // selection: warp g picks 16 smallest for point g.
    // Each lane caches its 32 strided row elements in registers; all argmin
    // rounds run on registers (ties -> smaller index, matching lax.top_k).
    const int g = tid >> 5, lane = tid & 31;
    const float* row = dist[g];
    float v[32];
#pragma unroll
    for (int r = 0; r < 32; r++) v[r] = row[lane + 32 * r];

    int* outp = &idx_out[((size_t)(b * NPTS + i0 + g)) * KK];
    for (int k = 0; k < KK; k++) {
        // lane-local argmin (ascending r => ascending index, strict < keeps
        // the smallest index among equal values)
        float bv = v[0];
        int br = 0;
#pragma unroll
        for (int r = 1; r < 32; r++) {
            if (v[r] < bv) { bv = v[r]; br = r; }
        }
        int bi = lane + 32 * br;
        // warp argmin with index tie-break
#pragma unroll
        for (int o = 16; o > 0; o >>= 1) {
            float ov = __shfl_xor_sync(0xffffffffu, bv, o);
            int oi = __shfl_xor_sync(0xffffffffu, bi, o);
            if (ov < bv || (ov == bv && oi < bi)) { bv = ov; bi = oi; }
        }
        if (lane == 0) outp[k] = bi;
        // winner lane invalidates its element (predicated register update)
        if ((bi & 31) == lane) {
            int rr = bi >> 5;
#pragma unroll
            for (int r = 0; r < 32; r++)
                if (r == rr) v[r] = FLT_MAX;
        }
    }
}

// ---------------- EdgeConv: relu(e@w1+b1)@w2+b2, max over K ---------------------
// e = [x_i, x_j - x_i]  =>  h1 = base_i + sum_j xj * w1[D:,:],
// base_i = b1 + x_i * (w1[:D,:] - w1[D:,:])
// Each block: 8 warps x GROUPS sequential points (weights amortized across 32
// points); per-warp buffers -> no inter-group barriers. Neighbors in chunks of
// NB=8; inner loops use float4 broadcast LDS with j unrolled x4.
template <int D>
__global__ void __launch_bounds__(256, 2) edgeconv_kernel(
    const float* __restrict__ feat, const int* __restrict__ idx,
    const float* __restrict__ w1, const float* __restrict__ b1,
    const float* __restrict__ w2, const float* __restrict__ b2,
    float* __restrict__ out) {
    constexpr int PTS = 8;     // warps per block
    constexpr int NB = 8;      // neighbor chunk
    constexpr int GROUPS = 4;  // sequential points per warp
    constexpr int Dp = (D + 3) & ~3;
    extern __shared__ float s[];
    float* w1bs = s;                           // D*CH   (w1[D:,:])
    float* wdfs = w1bs + D * CH;               // D*CH   (w1[:D,:]-w1[D:,:])
    float* w2s  = wdfs + D * CH;               // CH*CH
    float* b1s  = w2s + CH * CH;               // CH
    float* b2s  = b1s + CH;                    // CH
    float* xis  = b2s + CH;                    // PTS*Dp
    float* xjs  = xis + PTS * Dp;              // PTS*KK*Dp
    float* h1c  = xjs + PTS * KK * Dp;         // PTS*NB*CH
    int* nbr    = (int*)(h1c + PTS * NB * CH); // PTS*KK

    const int tid = threadIdx.x;  // 256 = 8 warps
    const int p = tid >> 5, lane = tid & 31;

    for (int t = tid; t < D * CH; t += 256) {
        float wa = w1[t];
        float wb = w1[D * CH + t];
        w1bs[t] = wb;
        wdfs[t] = wa - wb;
    }
    for (int t = tid; t < CH * CH; t += 256) w2s[t] = w2[t];
    if (tid < CH) { b1s[tid] = b1[tid]; b2s[tid] = b2[tid]; }
    __syncthreads();

    const int k0 = 2 * lane;  // each lane owns 2 output channels

    for (int grp = 0; grp < GROUPS; grp++) {
        const int gbase = blockIdx.x * (PTS * GROUPS) + grp * PTS;
        const int b = gbase / NPTS;
        const int i = (gbase % NPTS) + p;
        const float* fb = feat + (size_t)b * NPTS * D;

        if (lane < KK) nbr[p * KK + lane] = idx[((size_t)(b * NPTS + i)) * KK + lane];
        __syncwarp();
        for (int t = lane; t < D; t += 32) xis[p * D + t] = fb[i * D + t];
        for (int t = lane; t < KK * D; t += 32) {
            int nb = t / D, c = t % D;
            xjs[p * KK * D + t] = fb[(size_t)nbr[p * KK + nb] * D + c];
        }
        __syncwarp();

        // base_i = b1 + x_i * wdf
        float bx = b1s[k0], by = b1s[k0 + 1];
        for (int j = 0; j < D; j++) {
            float xv = xis[p * D + j];
            float2 wd = *(const float2*)&wdfs[j * CH + k0];
            bx = fmaf(xv, wd.x, bx);
            by = fmaf(xv, wd.y, by);
        }

        float mx = -FLT_MAX, my = -FLT_MAX;

        for (int c0 = 0; c0 < KK; c0 += NB) {
            float2 acc[NB];
#pragma unroll
            for (int nb = 0; nb < NB; nb++) acc[nb] = make_float2(0.f, 0.f);

            if constexpr (D % 4 == 0) {
                const float* xbase = &xjs[p * KK * D + c0 * D];
                for (int j = 0; j < D; j += 4) {
                    const float* wb = &w1bs[j * CH + k0];
                    float2 wv0 = *(const float2*)(wb);
                    float2 wv1 = *(const float2*)(wb + CH);
                    float2 wv2 = *(const float2*)(wb + 2 * CH);
                    float2 wv3 = *(const float2*)(wb + 3 * CH);
#pragma unroll
                    for (int nb = 0; nb < NB; nb++) {
                        float4 xv = *(const float4*)(xbase + nb * D + j);
                        acc[nb].x = fmaf(xv.x, wv0.x, acc[nb].x);
                        acc[nb].y = fmaf(xv.x, wv0.y, acc[nb].y);
                        acc[nb].x = fmaf(xv.y, wv1.x, acc[nb].x);
                        acc[nb].y = fmaf(xv.y, wv1.y, acc[nb].y);
                        acc[nb].x = fmaf(xv.z, wv2.x, acc[nb].x);
                        acc[nb].y = fmaf(xv.z, wv2.y, acc[nb].y);
                        acc[nb].x = fmaf(xv.w, wv3.x, acc[nb].x);
                        acc[nb].y = fmaf(xv.w, wv3.y, acc[nb].y);
                    }
                }
            } else {
                for (int j = 0; j < D; j++) {
                    float2 w = *(const float2*)&w1bs[j * CH + k0];
                    const float* xr = &xjs[p * KK * D + c0 * D + j];
#pragma unroll
                    for (int nb = 0; nb < NB; nb++) {
                        float xj = xr[nb * D];
                        acc[nb].x = fmaf(xj, w.x, acc[nb].x);
                        acc[nb].y = fmaf(xj, w.y, acc[nb].y);
                    }
                }
            }
            // write h1 chunk (relu), own warp only
#pragma unroll
            for (int nb = 0; nb < NB; nb++) {
                float2 h;
                h.x = fmaxf(bx + acc[nb].x, 0.f);
                h.y = fmaxf(by + acc[nb].y, 0.f);
                *(float2*)&h1c[(p * NB + nb) * CH + k0] = h;
            }
            __syncwarp();

            // stage 2 on this chunk: h1 @ w2
#pragma unroll
            for (int nb = 0; nb < NB; nb++) acc[nb] = make_float2(0.f, 0.f);
            const float* hbase = &h1c[p * NB * CH];
            for (int j = 0; j < CH; j += 4) {
                const float* wb = &w2s[j * CH + k0];
                float2 wv0 = *(const float2*)(wb);
                float2 wv1 = *(const float2*)(wb + CH);
                float2 wv2 = *(const float2*)(wb + 2 * CH);
                float2 wv3 = *(const float2*)(wb + 3 * CH);
#pragma unroll
                for (int nb = 0; nb < NB; nb++) {
                    float4 hv = *(const float4*)(hbase + nb * CH + j);
                    acc[nb].x = fmaf(hv.x, wv0.x, acc[nb].x);
                    acc[nb].y = fmaf(hv.x, wv0.y, acc[nb].y);
                    acc[nb].x = fmaf(hv.y, wv1.x, acc[nb].x);
                    acc[nb].y = fmaf(hv.y, wv1.y, acc[nb].y);
                    acc[nb].x = fmaf(hv.z, wv2.x, acc[nb].x);
                    acc[nb].y = fmaf(hv.z, wv2.y, acc[nb].y);
                    acc[nb].x = fmaf(hv.w, wv3.x, acc[nb].x);
                    acc[nb].y = fmaf(hv.w, wv3.y, acc[nb].y);
                }
            }
#pragma unroll
            for (int nb = 0; nb < NB; nb++) {
                mx = fmaxf(mx, acc[nb].x);
                my = fmaxf(my, acc[nb].y);
            }
            __syncwarp();  // before next chunk overwrites h1c
        }

        size_t ob = ((size_t)(b * NPTS + i)) * CH;
        out[ob + k0]     = mx + b2s[k0];
        out[ob + k0 + 1] = my + b2s[k0 + 1];
    }
}

// ---------------- final MLP: 192 -> 128 -> 64 -> 32 -> 2, log_softmax ------------
__global__ void __launch_bounds__(512) mlp_kernel(
    const float* __restrict__ x1, const float* __restrict__ x2,
    const float* __restrict__ x3,
    const float* __restrict__ mw1, const float* __restrict__ mb1,
    const float* __restrict__ mw2, const float* __restrict__ mb2,
    const float* __restrict__ mw3, const float* __restrict__ mb3,
    const float* __restrict__ mw4, const float* __restrict__ mb4,
    float* __restrict__ out) {
    extern __shared__ float s[];
    float* w1s = s;               // 192*128 = 24576
    float* w2s = w1s + 24576;     // 128*64  = 8192
    float* w3s = w2s + 8192;      // 64*32   = 2048
    float* w4s = w3s + 2048;      // 32*2    = 64
    float* b1s = w4s + 64;        // 128
    float* b2s = b1s + 128;       // 64
    float* b3s = b2s + 64;        // 32
    float* b4s = b3s + 32;        // 4 (2 used + 2 pad -> keep fbuf 16B-aligned)
    float* fbuf = b4s + 4;        // 16 warps * 192
    float* hbuf = fbuf + 16 * 192;// 16 warps * 128

    const int tid = threadIdx.x;  // 512 = 16 warps
    const int w = tid >> 5, lane = tid & 31;
    for (int t = tid; t < 24576; t += 512) w1s[t] = mw1[t];
    for (int t = tid; t < 8192; t += 512) w2s[t] = mw2[t];
    for (int t = tid; t < 2048; t += 512) w3s[t] = mw3[t];
    if (tid < 64) w4s[tid] = mw4[tid];
    if (tid < 128) b1s[tid] = mb1[tid];
    if (tid < 64) b2s[tid] = mb2[tid];
    if (tid < 32) b3s[tid] = mb3[tid];
    if (tid < 2) b4s[tid] = mb4[tid];
    __syncthreads();

    const int ptsPerBlock = (BATCH * NPTS) / gridDim.x;
    const int pbase = blockIdx.x * ptsPerBlock;
    float* f = fbuf + w * 192;
    float* h = hbuf + w * 128;

    for (int pt = pbase + w; pt < pbase + ptsPerBlock; pt += 16) {
        for (int t = lane; t < 64; t += 32) {
            f[t]       = x1[(size_t)pt * 64 + t];
            f[64 + t]  = x2[(size_t)pt * 64 + t];
            f[128 + t] = x3[(size_t)pt * 64 + t];
        }
        __syncwarp();
        // layer 1: 192 -> 128, lane owns 4 channels, j unrolled x4
        float4 a1 = *(const float4*)&b1s[4 * lane];
        for (int j = 0; j < 192; j += 4) {
            float4 xv = *(const float4*)&f[j];
            const float* wb = &w1s[j * 128 + 4 * lane];
            float4 w0 = *(const float4*)(wb);
            float4 w1v = *(const float4*)(wb + 128);
            float4 w2v = *(const float4*)(wb + 256);
            float4 w3v = *(const float4*)(wb + 384);
            a1.x = fmaf(xv.x, w0.x, a1.x); a1.y = fmaf(xv.x, w0.y, a1.y);
            a1.z = fmaf(xv.x, w0.z, a1.z); a1.w = fmaf(xv.x, w0.w, a1.w);
            a1.x = fmaf(xv.y, w1v.x, a1.x); a1.y = fmaf(xv.y, w1v.y, a1.y);
            a1.z = fmaf(xv.y, w1v.z, a1.z); a1.w = fmaf(xv.y, w1v.w, a1.w);
            a1.x = fmaf(xv.z, w2v.x, a1.x); a1.y = fmaf(xv.z, w2v.y, a1.y);
            a1.z = fmaf(xv.z, w2v.z, a1.z); a1.w = fmaf(xv.z, w2v.w, a1.w);
            a1.x = fmaf(xv.w, w3v.x, a1.x); a1.y = fmaf(xv.w, w3v.y, a1.y);
            a1.z = fmaf(xv.w, w3v.z, a1.z); a1.w = fmaf(xv.w, w3v.w, a1.w);
        }
        h[4 * lane]     = fmaxf(a1.x, 0.f);
        h[4 * lane + 1] = fmaxf(a1.y, 0.f);
        h[4 * lane + 2] = fmaxf(a1.z, 0.f);
        h[4 * lane + 3] = fmaxf(a1.w, 0.f);
        __syncwarp();
        // layer 2: 128 -> 64, lane owns 2 channels; result into f[0:64]
        float2 a2 = *(const float2*)&b2s[2 * lane];
        for (int j = 0; j < 128; j += 4) {
            float4 hv = *(const float4*)&h[j];
            const float* wb = &w2s[j * 64 + 2 * lane];
            float2 w0 = *(const float2*)(wb);
            float2 w1v = *(const float2*)(wb + 64);
            float2 w2v = *(const float2*)(wb + 128);
            float2 w3v = *(const float2*)(wb + 192);
            a2.x = fmaf(hv.x, w0.x, a2.x); a2.y = fmaf(hv.x, w0.y, a2.y);
            a2.x = fmaf(hv.y, w1v.x, a2.x); a2.y = fmaf(hv.y, w1v.y, a2.y);
            a2.x = fmaf(hv.z, w2v.x, a2.x); a2.y = fmaf(hv.z, w2v.y, a2.y);
            a2.x = fmaf(hv.w, w3v.x, a2.x); a2.y = fmaf(hv.w, w3v.y, a2.y);
        }
        __syncwarp();
        f[2 * lane]     = fmaxf(a2.x, 0.f);
        f[2 * lane + 1] = fmaxf(a2.y, 0.f);
        __syncwarp();
        // layer 3: 64 -> 32, lane owns 1 channel; result into h[0:32]
        float a3 = b3s[lane];
        for (int j = 0; j < 64; j++) a3 = fmaf(f[j], w3s[j * 32 + lane], a3);
        a3 = fmaxf(a3, 0.f);
        __syncwarp();
        h[lane] = a3;
        __syncwarp();
        // layer 4 + log_softmax (2 classes)
        float o = 0.f;
        if (lane < 2) {
            o = b4s[lane];
            for (int j = 0; j < 32; j++) o = fmaf(h[j], w4s[j * 2 + lane], o);
        }
        float oo = __shfl_xor_sync(0xffffffffu, o, 1);
        if (lane < 2) {
            float mm = fmaxf(o, oo);
            float lse = mm + logf(expf(o - mm) + expf(oo - mm));
            out[(size_t)pt * 2 + lane] = o - lse;
        }
        __syncwarp();
    }
}

// ---------------- launch -------------------------------------------------------
static constexpr size_t ec_smem(int D) {
    int Dp = (D + 3) & ~3;
    return (size_t)(2 * D * CH + CH * CH + 2 * CH + 8 * Dp + 8 * KK * Dp +
                    8 * 8 * CH + 8 * KK) * 4;
}
static constexpr size_t MLP_SMEM =
    (size_t)(24576 + 8192 + 2048 + 64 + 128 + 64 + 32 + 4 + 16 * 192 + 16 * 128) * 4;

extern "C" void kernel_launch(void* const* d_in, const int* in_sizes, int n_in,
                              void* d_out, int out_size) {
    (void)in_sizes; (void)n_in; (void)out_size;
    const float* x    = (const float*)d_in[0];
    const float* c1w1 = (const float*)d_in[1];
    const float* c1b1 = (const float*)d_in[2];
    const float* c1w2 = (const float*)d_in[3];
    const float* c1b2 = (const float*)d_in[4];
    const float* c2w1 = (const float*)d_in[5];
    const float* c2b1 = (const float*)d_in[6];
    const float* c2w2 = (const float*)d_in[7];
    const float* c2b2 = (const float*)d_in[8];
    const float* c3w1 = (const float*)d_in[9];
    const float* c3b1 = (const float*)d_in[10];
    const float* c3w2 = (const float*)d_in[11];
    const float* c3b2 = (const float*)d_in[12];
    const float* mw1  = (const float*)d_in[13];
    const float* mb1  = (const float*)d_in[14];
    const float* mw2  = (const float*)d_in[15];
    const float* mb2  = (const float*)d_in[16];
    const float* mw3  = (const float*)d_in[17];
    const float* mb3  = (const float*)d_in[18];
    const float* mw4  = (const float*)d_in[19];
    const float* mb4  = (const float*)d_in[20];
    float* outp = (float*)d_out;

    float *x1p, *x2p, *x3p;
    int* idxp;
    cudaGetSymbolAddress((void**)&x1p, g_x1);
    cudaGetSymbolAddress((void**)&x2p, g_x2);
    cudaGetSymbolAddress((void**)&x3p, g_x3);
    cudaGetSymbolAddress((void**)&idxp, g_idx);

    cudaFuncSetAttribute(edgeconv_kernel<1>,
                         cudaFuncAttributeMaxDynamicSharedMemorySize, (int)ec_smem(1));
    cudaFuncSetAttribute(edgeconv_kernel<64>,
                         cudaFuncAttributeMaxDynamicSharedMemorySize, (int)ec_smem(64));
    cudaFuncSetAttribute(mlp_kernel,
                         cudaFuncAttributeMaxDynamicSharedMemorySize, (int)MLP_SMEM);

    const int nblk_knn = BATCH * NPTS / 8;   // 8192
    const int nblk_ec  = BATCH * NPTS / 32;  // 2048 (8 warps x 4 points)

    knn_kernel<1><<<nblk_knn, 256>>>(x, idxp);
    edgeconv_kernel<1><<<nblk_ec, 256, ec_smem(1)>>>(x, idxp, c1w1, c1b1, c1w2, c1b2, x1p);
    knn_kernel<64><<<nblk_knn, 256>>>(x1p, idxp);
    edgeconv_kernel<64><<<nblk_ec, 256, ec_smem(64)>>>(x1p, idxp, c2w1, c2b1, c2w2, c2b2, x2p);
    knn_kernel<64><<<nblk_knn, 256>>>(x2p, idxp);
    edgeconv_kernel<64><<<nblk_ec, 256, ec_smem(64)>>>(x2p, idxp, c3w1, c3b1, c3w2, c3b2, x3p);
    mlp_kernel<<<128, 512, MLP_SMEM>>>(x1p, x2p, x3p, mw1, mb1, mw2, mb2,
                                       mw3, mb3, mw4, mb4, outp);
}

// round 5
// speedup vs baseline: 1.4362x; 1.1043x over previous
#include <cuda_runtime.h>
#include <math.h>
#include <float.h>

#define BATCH 64
#define NPTS  1024
#define KK    16
#define CH    64

// ---------------- scratch (static device globals; no allocation) ----------------
__device__ __align__(16) float g_x1[BATCH * NPTS * CH];
__device__ __align__(16) float g_x2[BATCH * NPTS * CH];
__device__ __align__(16) float g_x3[BATCH * NPTS * CH];
__device__ int g_idx[BATCH * NPTS * KK];

// ---------------- kNN: PB=8 points/block; j-register-blocked distance GEMM;
// ---------------- register-resident warp-per-point selection --------------------
template <int D>
__global__ void __launch_bounds__(256) knn_kernel(const float* __restrict__ feat,
                                                  int* __restrict__ idx_out) {
    constexpr int PB = 8;
    __shared__ __align__(16) float dist[PB][NPTS];
    __shared__ __align__(16) float xis[PB][(D < 4) ? 4 : D];
    __shared__ float sqi[PB];

    const int tid = threadIdx.x;          // 256 threads
    const int gbase = blockIdx.x * PB;    // global point base
    const int b = gbase / NPTS;
    const int i0 = gbase % NPTS;
    const float* fb = feat + (size_t)b * NPTS * D;

    // load the 8 query points
    for (int t = tid; t < PB * D; t += 256) {
        int p = t / D, c = t % D;
        xis[p][c] = fb[(i0 + p) * D + c];
    }
    __syncthreads();
    if (tid < PB) {
        float s = 0.f;
        for (int c = 0; c < D; c++) s += xis[tid][c] * xis[tid][c];
        sqi[tid] = s;
    }
    __syncthreads();

    if constexpr (D % 4 == 0) {
        // each thread owns 4 consecutive j rows: 12 loads per k-chunk for 144 FMA
        const int j0 = tid * 4;  // 256*4 = 1024 = NPTS
        float dot[PB][4];
        float sqj[4];
#pragma unroll
        for (int p = 0; p < PB; p++)
#pragma unroll
            for (int jj = 0; jj < 4; jj++) dot[p][jj] = 0.f;
#pragma unroll
        for (int jj = 0; jj < 4; jj++) sqj[jj] = 0.f;

        for (int c4 = 0; c4 < D / 4; c4++) {
            float4 xj[4];
#pragma unroll
            for (int jj = 0; jj < 4; jj++) {
                xj[jj] = *(const float4*)(fb + (size_t)(j0 + jj) * D + 4 * c4);
                sqj[jj] += xj[jj].x * xj[jj].x + xj[jj].y * xj[jj].y +
                           xj[jj].z * xj[jj].z + xj[jj].w * xj[jj].w;
            }
#pragma unroll
            for (int p = 0; p < PB; p++) {
                float4 xi = *(const float4*)&xis[p][4 * c4];
#pragma unroll
                for (int jj = 0; jj < 4; jj++) {
                    dot[p][jj] = fmaf(xj[jj].x, xi.x, dot[p][jj]);
                    dot[p][jj] = fmaf(xj[jj].y, xi.y, dot[p][jj]);
                    dot[p][jj] = fmaf(xj[jj].z, xi.z, dot[p][jj]);
                    dot[p][jj] = fmaf(xj[jj].w, xi.w, dot[p][jj]);
                }
            }
        }
#pragma unroll
        for (int p = 0; p < PB; p++) {
            float4 dv;
            dv.x = sqi[p] + sqj[0] - 2.f * dot[p][0];
            dv.y = sqi[p] + sqj[1] - 2.f * dot[p][1];
            dv.z = sqi[p] + sqj[2] - 2.f * dot[p][2];
            dv.w = sqi[p] + sqj[3] - 2.f * dot[p][3];
            *(float4*)&dist[p][j0] = dv;
        }
    } else {
        for (int j = tid; j < NPTS; j += 256) {
            const float* fj = fb + (size_t)j * D;
            float sqj = 0.f;
            float dot[PB];
#pragma unroll
            for (int p = 0; p < PB; p++) dot[p] = 0.f;
            for (int c = 0; c < D; c++) {
                float v = fj[c];
                sqj += v * v;
#pragma unroll
                for (int p = 0; p < PB; p++) dot[p] += v * xis[p][c];
            }
#pragma unroll
            for (int p = 0; p < PB; p++) dist[p][j] = sqi[p] + sqj - 2.f * dot[p];
        }
    }
    __syncthreads();

    // selection: warp g picks 16 smallest for point g.
    // Each lane caches its 32 strided row elements in registers; all argmin
    // rounds run on registers (ties -> smaller index, matching lax.top_k).
    const int g = tid >> 5, lane = tid & 31;
    const float* row = dist[g];
    float v[32];
#pragma unroll
    for (int r = 0; r < 32; r++) v[r] = row[lane + 32 * r];

    int* outp = &idx_out[((size_t)(b * NPTS + i0 + g)) * KK];
    for (int k = 0; k < KK; k++) {
        // lane-local argmin (ascending r => ascending index, strict < keeps
        // the smallest index among equal values)
        float bv = v[0];
        int br = 0;
#pragma unroll
        for (int r = 1; r < 32; r++) {
            if (v[r] < bv) { bv = v[r]; br = r; }
        }
        int bi = lane + 32 * br;
        // warp argmin with index tie-break
#pragma unroll
        for (int o = 16; o > 0; o >>= 1) {
            float ov = __shfl_xor_sync(0xffffffffu, bv, o);
            int oi = __shfl_xor_sync(0xffffffffu, bi, o);
            if (ov < bv || (ov == bv && oi < bi)) { bv = ov; bi = oi; }
        }
        if (lane == 0) outp[k] = bi;
        // winner lane invalidates its element (predicated register update)
        if ((bi & 31) == lane) {
            int rr = bi >> 5;
#pragma unroll
            for (int r = 0; r < 32; r++)
                if (r == rr) v[r] = FLT_MAX;
        }
    }
}

// ---------------- EdgeConv: relu(e@w1+b1)@w2+b2, max over K ---------------------
// e = [x_i, x_j - x_i]  =>  h1 = base_i + sum_j xj * w1[D:,:],
// base_i = b1 + x_i * (w1[:D,:] - w1[D:,:])
// Each block: 8 warps x GROUPS sequential points; per-warp buffers.
template <int D>
__global__ void __launch_bounds__(256, 2) edgeconv_kernel(
    const float* __restrict__ feat, const int* __restrict__ idx,
    const float* __restrict__ w1, const float* __restrict__ b1,
    const float* __restrict__ w2, const float* __restrict__ b2,
    float* __restrict__ out) {
    constexpr int PTS = 8;     // warps per block
    constexpr int NB = 8;      // neighbor chunk
    constexpr int GROUPS = 4;  // sequential points per warp
    constexpr int Dp = (D + 3) & ~3;
    extern __shared__ float s[];
    float* w1bs = s;                           // D*CH   (w1[D:,:])
    float* wdfs = w1bs + D * CH;               // D*CH   (w1[:D,:]-w1[D:,:])
    float* w2s  = wdfs + D * CH;               // CH*CH
    float* b1s  = w2s + CH * CH;               // CH
    float* b2s  = b1s + CH;                    // CH
    float* xis  = b2s + CH;                    // PTS*Dp
    float* xjs  = xis + PTS * Dp;              // PTS*KK*Dp
    float* h1c  = xjs + PTS * KK * Dp;         // PTS*NB*CH
    int* nbr    = (int*)(h1c + PTS * NB * CH); // PTS*KK

    const int tid = threadIdx.x;  // 256 = 8 warps
    const int p = tid >> 5, lane = tid & 31;

    for (int t = tid; t < D * CH; t += 256) {
        float wa = w1[t];
        float wb = w1[D * CH + t];
        w1bs[t] = wb;
        wdfs[t] = wa - wb;
    }
    for (int t = tid; t < CH * CH; t += 256) w2s[t] = w2[t];
    if (tid < CH) { b1s[tid] = b1[tid]; b2s[tid] = b2[tid]; }
    __syncthreads();

    const int k0 = 2 * lane;  // each lane owns 2 output channels

    for (int grp = 0; grp < GROUPS; grp++) {
        const int gbase = blockIdx.x * (PTS * GROUPS) + grp * PTS;
        const int b = gbase / NPTS;
        const int i = (gbase % NPTS) + p;
        const float* fb = feat + (size_t)b * NPTS * D;

        if (lane < KK) nbr[p * KK + lane] = idx[((size_t)(b * NPTS + i)) * KK + lane];
        __syncwarp();
        for (int t = lane; t < D; t += 32) xis[p * D + t] = fb[i * D + t];
        for (int t = lane; t < KK * D; t += 32) {
            int nb = t / D, c = t % D;
            xjs[p * KK * D + t] = fb[(size_t)nbr[p * KK + nb] * D + c];
        }
        __syncwarp();

        // base_i = b1 + x_i * wdf
        float bx = b1s[k0], by = b1s[k0 + 1];
        for (int j = 0; j < D; j++) {
            float xv = xis[p * D + j];
            float2 wd = *(const float2*)&wdfs[j * CH + k0];
            bx = fmaf(xv, wd.x, bx);
            by = fmaf(xv, wd.y, by);
        }

        float mx = -FLT_MAX, my = -FLT_MAX;

        for (int c0 = 0; c0 < KK; c0 += NB) {
            float2 acc[NB];
#pragma unroll
            for (int nb = 0; nb < NB; nb++) acc[nb] = make_float2(0.f, 0.f);

            if constexpr (D % 4 == 0) {
                const float* xbase = &xjs[p * KK * D + c0 * D];
                for (int j = 0; j < D; j += 4) {
                    const float* wb = &w1bs[j * CH + k0];
                    float2 wv0 = *(const float2*)(wb);
                    float2 wv1 = *(const float2*)(wb + CH);
                    float2 wv2 = *(const float2*)(wb + 2 * CH);
                    float2 wv3 = *(const float2*)(wb + 3 * CH);
#pragma unroll
                    for (int nb = 0; nb < NB; nb++) {
                        float4 xv = *(const float4*)(xbase + nb * D + j);
                        acc[nb].x = fmaf(xv.x, wv0.x, acc[nb].x);
                        acc[nb].y = fmaf(xv.x, wv0.y, acc[nb].y);
                        acc[nb].x = fmaf(xv.y, wv1.x, acc[nb].x);
                        acc[nb].y = fmaf(xv.y, wv1.y, acc[nb].y);
                        acc[nb].x = fmaf(xv.z, wv2.x, acc[nb].x);
                        acc[nb].y = fmaf(xv.z, wv2.y, acc[nb].y);
                        acc[nb].x = fmaf(xv.w, wv3.x, acc[nb].x);
                        acc[nb].y = fmaf(xv.w, wv3.y, acc[nb].y);
                    }
                }
            } else {
                for (int j = 0; j < D; j++) {
                    float2 w = *(const float2*)&w1bs[j * CH + k0];
                    const float* xr = &xjs[p * KK * D + c0 * D + j];
#pragma unroll
                    for (int nb = 0; nb < NB; nb++) {
                        float xj = xr[nb * D];
                        acc[nb].x = fmaf(xj, w.x, acc[nb].x);
                        acc[nb].y = fmaf(xj, w.y, acc[nb].y);
                    }
                }
            }
            // write h1 chunk (relu), own warp only
#pragma unroll
            for (int nb = 0; nb < NB; nb++) {
                float2 h;
                h.x = fmaxf(bx + acc[nb].x, 0.f);
                h.y = fmaxf(by + acc[nb].y, 0.f);
                *(float2*)&h1c[(p * NB + nb) * CH + k0] = h;
            }
            __syncwarp();

            // stage 2 on this chunk: h1 @ w2
#pragma unroll
            for (int nb = 0; nb < NB; nb++) acc[nb] = make_float2(0.f, 0.f);
            const float* hbase = &h1c[p * NB * CH];
            for (int j = 0; j < CH; j += 4) {
                const float* wb = &w2s[j * CH + k0];
                float2 wv0 = *(const float2*)(wb);
                float2 wv1 = *(const float2*)(wb + CH);
                float2 wv2 = *(const float2*)(wb + 2 * CH);
                float2 wv3 = *(const float2*)(wb + 3 * CH);
#pragma unroll
                for (int nb = 0; nb < NB; nb++) {
                    float4 hv = *(const float4*)(hbase + nb * CH + j);
                    acc[nb].x = fmaf(hv.x, wv0.x, acc[nb].x);
                    acc[nb].y = fmaf(hv.x, wv0.y, acc[nb].y);
                    acc[nb].x = fmaf(hv.y, wv1.x, acc[nb].x);
                    acc[nb].y = fmaf(hv.y, wv1.y, acc[nb].y);
                    acc[nb].x = fmaf(hv.z, wv2.x, acc[nb].x);
                    acc[nb].y = fmaf(hv.z, wv2.y, acc[nb].y);
                    acc[nb].x = fmaf(hv.w, wv3.x, acc[nb].x);
                    acc[nb].y = fmaf(hv.w, wv3.y, acc[nb].y);
                }
            }
#pragma unroll
            for (int nb = 0; nb < NB; nb++) {
                mx = fmaxf(mx, acc[nb].x);
                my = fmaxf(my, acc[nb].y);
            }
            __syncwarp();  // before next chunk overwrites h1c
        }

        size_t ob = ((size_t)(b * NPTS + i)) * CH;
        out[ob + k0]     = mx + b2s[k0];
        out[ob + k0 + 1] = my + b2s[k0 + 1];
    }
}

// ---------------- final MLP: 192 -> 128 -> 64 -> 32 -> 2, log_softmax ------------
__global__ void __launch_bounds__(512) mlp_kernel(
    const float* __restrict__ x1, const float* __restrict__ x2,
    const float* __restrict__ x3,
    const float* __restrict__ mw1, const float* __restrict__ mb1,
    const float* __restrict__ mw2, const float* __restrict__ mb2,
    const float* __restrict__ mw3, const float* __restrict__ mb3,
    const float* __restrict__ mw4, const float* __restrict__ mb4,
    float* __restrict__ out) {
    extern __shared__ float s[];
    float* w1s = s;               // 192*128 = 24576
    float* w2s = w1s + 24576;     // 128*64  = 8192
    float* w3s = w2s + 8192;      // 64*32   = 2048
    float* w4s = w3s + 2048;      // 32*2    = 64
    float* b1s = w4s + 64;        // 128
    float* b2s = b1s + 128;       // 64
    float* b3s = b2s + 64;        // 32
    float* b4s = b3s + 32;        // 4 (2 used + 2 pad -> keep fbuf 16B-aligned)
    float* fbuf = b4s + 4;        // 16 warps * 192
    float* hbuf = fbuf + 16 * 192;// 16 warps * 128

    const int tid = threadIdx.x;  // 512 = 16 warps
    const int w = tid >> 5, lane = tid & 31;
    for (int t = tid; t < 24576; t += 512) w1s[t] = mw1[t];
    for (int t = tid; t < 8192; t += 512) w2s[t] = mw2[t];
    for (int t = tid; t < 2048; t += 512) w3s[t] = mw3[t];
    if (tid < 64) w4s[tid] = mw4[tid];
    if (tid < 128) b1s[tid] = mb1[tid];
    if (tid < 64) b2s[tid] = mb2[tid];
    if (tid < 32) b3s[tid] = mb3[tid];
    if (tid < 2) b4s[tid] = mb4[tid];
    __syncthreads();

    const int ptsPerBlock = (BATCH * NPTS) / gridDim.x;
    const int pbase = blockIdx.x * ptsPerBlock;
    float* f = fbuf + w * 192;
    float* h = hbuf + w * 128;

    for (int pt = pbase + w; pt < pbase + ptsPerBlock; pt += 16) {
        for (int t = lane; t < 64; t += 32) {
            f[t]       = x1[(size_t)pt * 64 + t];
            f[64 + t]  = x2[(size_t)pt * 64 + t];
            f[128 + t] = x3[(size_t)pt * 64 + t];
        }
        __syncwarp();
        // layer 1: 192 -> 128, lane owns 4 channels, j unrolled x4
        float4 a1 = *(const float4*)&b1s[4 * lane];
        for (int j = 0; j < 192; j += 4) {
            float4 xv = *(const float4*)&f[j];
            const float* wb = &w1s[j * 128 + 4 * lane];
            float4 w0 = *(const float4*)(wb);
            float4 w1v = *(const float4*)(wb + 128);
            float4 w2v = *(const float4*)(wb + 256);
            float4 w3v = *(const float4*)(wb + 384);
            a1.x = fmaf(xv.x, w0.x, a1.x); a1.y = fmaf(xv.x, w0.y, a1.y);
            a1.z = fmaf(xv.x, w0.z, a1.z); a1.w = fmaf(xv.x, w0.w, a1.w);
            a1.x = fmaf(xv.y, w1v.x, a1.x); a1.y = fmaf(xv.y, w1v.y, a1.y);
            a1.z = fmaf(xv.y, w1v.z, a1.z); a1.w = fmaf(xv.y, w1v.w, a1.w);
            a1.x = fmaf(xv.z, w2v.x, a1.x); a1.y = fmaf(xv.z, w2v.y, a1.y);
            a1.z = fmaf(xv.z, w2v.z, a1.z); a1.w = fmaf(xv.z, w2v.w, a1.w);
            a1.x = fmaf(xv.w, w3v.x, a1.x); a1.y = fmaf(xv.w, w3v.y, a1.y);
            a1.z = fmaf(xv.w, w3v.z, a1.z); a1.w = fmaf(xv.w, w3v.w, a1.w);
        }
        h[4 * lane]     = fmaxf(a1.x, 0.f);
        h[4 * lane + 1] = fmaxf(a1.y, 0.f);
        h[4 * lane + 2] = fmaxf(a1.z, 0.f);
        h[4 * lane + 3] = fmaxf(a1.w, 0.f);
        __syncwarp();
        // layer 2: 128 -> 64, lane owns 2 channels; result into f[0:64]
        float2 a2 = *(const float2*)&b2s[2 * lane];
        for (int j = 0; j < 128; j += 4) {
            float4 hv = *(const float4*)&h[j];
            const float* wb = &w2s[j * 64 + 2 * lane];
            float2 w0 = *(const float2*)(wb);
            float2 w1v = *(const float2*)(wb + 64);
            float2 w2v = *(const float2*)(wb + 128);
            float2 w3v = *(const float2*)(wb + 192);
            a2.x = fmaf(hv.x, w0.x, a2.x); a2.y = fmaf(hv.x, w0.y, a2.y);
            a2.x = fmaf(hv.y, w1v.x, a2.x); a2.y = fmaf(hv.y, w1v.y, a2.y);
            a2.x = fmaf(hv.z, w2v.x, a2.x); a2.y = fmaf(hv.z, w2v.y, a2.y);
            a2.x = fmaf(hv.w, w3v.x, a2.x); a2.y = fmaf(hv.w, w3v.y, a2.y);
        }
        __syncwarp();
        f[2 * lane]     = fmaxf(a2.x, 0.f);
        f[2 * lane + 1] = fmaxf(a2.y, 0.f);
        __syncwarp();
        // layer 3: 64 -> 32, lane owns 1 channel; result into h[0:32]
        float a3 = b3s[lane];
        for (int j = 0; j < 64; j++) a3 = fmaf(f[j], w3s[j * 32 + lane], a3);
        a3 = fmaxf(a3, 0.f);
        __syncwarp();
        h[lane] = a3;
        __syncwarp();
        // layer 4 + log_softmax (2 classes)
        float o = 0.f;
        if (lane < 2) {
            o = b4s[lane];
            for (int j = 0; j < 32; j++) o = fmaf(h[j], w4s[j * 2 + lane], o);
        }
        float oo = __shfl_xor_sync(0xffffffffu, o, 1);
        if (lane < 2) {
            float mm = fmaxf(o, oo);
            float lse = mm + logf(expf(o - mm) + expf(oo - mm));
            out[(size_t)pt * 2 + lane] = o - lse;
        }
        __syncwarp();
    }
}

// ---------------- launch -------------------------------------------------------
static constexpr size_t ec_smem(int D) {
    int Dp = (D + 3) & ~3;
    return (size_t)(2 * D * CH + CH * CH + 2 * CH + 8 * Dp + 8 * KK * Dp +
                    8 * 8 * CH + 8 * KK) * 4;
}
static constexpr size_t MLP_SMEM =
    (size_t)(24576 + 8192 + 2048 + 64 + 128 + 64 + 32 + 4 + 16 * 192 + 16 * 128) * 4;

extern "C" void kernel_launch(void* const* d_in, const int* in_sizes, int n_in,
                              void* d_out, int out_size) {
    (void)in_sizes; (void)n_in; (void)out_size;
    const float* x    = (const float*)d_in[0];
    const float* c1w1 = (const float*)d_in[1];
    const float* c1b1 = (const float*)d_in[2];
    const float* c1w2 = (const float*)d_in[3];
    const float* c1b2 = (const float*)d_in[4];
    const float* c2w1 = (const float*)d_in[5];
    const float* c2b1 = (const float*)d_in[6];
    const float* c2w2 = (const float*)d_in[7];
    const float* c2b2 = (const float*)d_in[8];
    const float* c3w1 = (const float*)d_in[9];
    const float* c3b1 = (const float*)d_in[10];
    const float* c3w2 = (const float*)d_in[11];
    const float* c3b2 = (const float*)d_in[12];
    const float* mw1  = (const float*)d_in[13];
    const float* mb1  = (const float*)d_in[14];
    const float* mw2  = (const float*)d_in[15];
    const float* mb2  = (const float*)d_in[16];
    const float* mw3  = (const float*)d_in[17];
    const float* mb3  = (const float*)d_in[18];
    const float* mw4  = (const float*)d_in[19];
    const float* mb4  = (const float*)d_in[20];
    float* outp = (float*)d_out;

    float *x1p, *x2p, *x3p;
    int* idxp;
    cudaGetSymbolAddress((void**)&x1p, g_x1);
    cudaGetSymbolAddress((void**)&x2p, g_x2);
    cudaGetSymbolAddress((void**)&x3p, g_x3);
    cudaGetSymbolAddress((void**)&idxp, g_idx);

    cudaFuncSetAttribute(edgeconv_kernel<1>,
                         cudaFuncAttributeMaxDynamicSharedMemorySize, (int)ec_smem(1));
    cudaFuncSetAttribute(edgeconv_kernel<64>,
                         cudaFuncAttributeMaxDynamicSharedMemorySize, (int)ec_smem(64));
    cudaFuncSetAttribute(mlp_kernel,
                         cudaFuncAttributeMaxDynamicSharedMemorySize, (int)MLP_SMEM);

    const int nblk_knn = BATCH * NPTS / 8;   // 8192
    const int nblk_ec  = BATCH * NPTS / 32;  // 2048 (8 warps x 4 points)

    knn_kernel<1><<<nblk_knn, 256>>>(x, idxp);
    edgeconv_kernel<1><<<nblk_ec, 256, ec_smem(1)>>>(x, idxp, c1w1, c1b1, c1w2, c1b2, x1p);
    knn_kernel<64><<<nblk_knn, 256>>>(x1p, idxp);
    edgeconv_kernel<64><<<nblk_ec, 256, ec_smem(64)>>>(x1p, idxp, c2w1, c2b1, c2w2, c2b2, x2p);
    knn_kernel<64><<<nblk_knn, 256>>>(x2p, idxp);
    edgeconv_kernel<64><<<nblk_ec, 256, ec_smem(64)>>>(x2p, idxp, c3w1, c3b1, c3w2, c3b2, x3p);
    mlp_kernel<<<128, 512, MLP_SMEM>>>(x1p, x2p, x3p, mw1, mb1, mw2, mb2,
                                       mw3, mb3, mw4, mb4, outp);
}

// round 6
// speedup vs baseline: 1.5328x; 1.0672x over previous
#include <cuda_runtime.h>
#include <math.h>
#include <float.h>

#define BATCH 64
#define NPTS  1024
#define KK    16
#define CH    64

// ---------------- scratch (static device globals; no allocation) ----------------
__device__ __align__(16) float g_x1[BATCH * NPTS * CH];
__device__ __align__(16) float g_x2[BATCH * NPTS * CH];
__device__ __align__(16) float g_x3[BATCH * NPTS * CH];
__device__ __align__(16) float g_base[BATCH * NPTS * CH];
__device__ int g_idx[BATCH * NPTS * KK];

// ---------------- kNN: PB=8 points/block; j-register-blocked distance GEMM;
// ---------------- register-resident warp-per-point selection --------------------
template <int D>
__global__ void __launch_bounds__(256) knn_kernel(const float* __restrict__ feat,
                                                  int* __restrict__ idx_out) {
    constexpr int PB = 8;
    __shared__ __align__(16) float dist[PB][NPTS];
    __shared__ __align__(16) float xis[PB][(D < 4) ? 4 : D];
    __shared__ float sqi[PB];

    const int tid = threadIdx.x;          // 256 threads
    const int gbase = blockIdx.x * PB;    // global point base
    const int b = gbase / NPTS;
    const int i0 = gbase % NPTS;
    const float* fb = feat + (size_t)b * NPTS * D;

    // load the 8 query points
    for (int t = tid; t < PB * D; t += 256) {
        int p = t / D, c = t % D;
        xis[p][c] = fb[(i0 + p) * D + c];
    }
    __syncthreads();
    if (tid < PB) {
        float s = 0.f;
        for (int c = 0; c < D; c++) s += xis[tid][c] * xis[tid][c];
        sqi[tid] = s;
    }
    __syncthreads();

    if constexpr (D % 4 == 0) {
        // each thread owns 4 consecutive j rows
        const int j0 = tid * 4;  // 256*4 = 1024 = NPTS
        float dot[PB][4];
        float sqj[4];
#pragma unroll
        for (int p = 0; p < PB; p++)
#pragma unroll
            for (int jj = 0; jj < 4; jj++) dot[p][jj] = 0.f;
#pragma unroll
        for (int jj = 0; jj < 4; jj++) sqj[jj] = 0.f;

        for (int c4 = 0; c4 < D / 4; c4++) {
            float4 xj[4];
#pragma unroll
            for (int jj = 0; jj < 4; jj++) {
                xj[jj] = *(const float4*)(fb + (size_t)(j0 + jj) * D + 4 * c4);
                sqj[jj] += xj[jj].x * xj[jj].x + xj[jj].y * xj[jj].y +
                           xj[jj].z * xj[jj].z + xj[jj].w * xj[jj].w;
            }
#pragma unroll
            for (int p = 0; p < PB; p++) {
                float4 xi = *(const float4*)&xis[p][4 * c4];
#pragma unroll
                for (int jj = 0; jj < 4; jj++) {
                    dot[p][jj] = fmaf(xj[jj].x, xi.x, dot[p][jj]);
                    dot[p][jj] = fmaf(xj[jj].y, xi.y, dot[p][jj]);
                    dot[p][jj] = fmaf(xj[jj].z, xi.z, dot[p][jj]);
                    dot[p][jj] = fmaf(xj[jj].w, xi.w, dot[p][jj]);
                }
            }
        }
#pragma unroll
        for (int p = 0; p < PB; p++) {
            float4 dv;
            dv.x = sqi[p] + sqj[0] - 2.f * dot[p][0];
            dv.y = sqi[p] + sqj[1] - 2.f * dot[p][1];
            dv.z = sqi[p] + sqj[2] - 2.f * dot[p][2];
            dv.w = sqi[p] + sqj[3] - 2.f * dot[p][3];
            *(float4*)&dist[p][j0] = dv;
        }
    } else {
        for (int j = tid; j < NPTS; j += 256) {
            const float* fj = fb + (size_t)j * D;
            float sqj = 0.f;
            float dot[PB];
#pragma unroll
            for (int p = 0; p < PB; p++) dot[p] = 0.f;
            for (int c = 0; c < D; c++) {
                float v = fj[c];
                sqj += v * v;
#pragma unroll
                for (int p = 0; p < PB; p++) dot[p] += v * xis[p][c];
            }
#pragma unroll
            for (int p = 0; p < PB; p++) dist[p][j] = sqi[p] + sqj - 2.f * dot[p];
        }
    }
    __syncthreads();

    // selection: warp g picks 16 smallest for point g (register-resident rows,
    // ties -> smaller index, matching lax.top_k).
    const int g = tid >> 5, lane = tid & 31;
    const float* row = dist[g];
    float v[32];
#pragma unroll
    for (int r = 0; r < 32; r++) v[r] = row[lane + 32 * r];

    int* outp = &idx_out[((size_t)(b * NPTS + i0 + g)) * KK];
    for (int k = 0; k < KK; k++) {
        float bv = v[0];
        int br = 0;
#pragma unroll
        for (int r = 1; r < 32; r++) {
            if (v[r] < bv) { bv = v[r]; br = r; }
        }
        int bi = lane + 32 * br;
#pragma unroll
        for (int o = 16; o > 0; o >>= 1) {
            float ov = __shfl_xor_sync(0xffffffffu, bv, o);
            int oi = __shfl_xor_sync(0xffffffffu, bi, o);
            if (ov < bv || (ov == bv && oi < bi)) { bv = ov; bi = oi; }
        }
        if (lane == 0) outp[k] = bi;
        if ((bi & 31) == lane) {
            int rr = bi >> 5;
#pragma unroll
            for (int r = 0; r < 32; r++)
                if (r == rr) v[r] = FLT_MAX;
        }
    }
}

// ---------------- base precompute: base = b1 + x_i * (w1[:D,:] - w1[D:,:]) ------
// One warp per point, 8 points per warp, 64 points per block.
template <int D>
__global__ void __launch_bounds__(256) base_kernel(
    const float* __restrict__ feat, const float* __restrict__ w1,
    const float* __restrict__ b1, float* __restrict__ baseo) {
    __shared__ float wdfs[D * CH];
    __shared__ float b1s[CH];
    const int tid = threadIdx.x, p = tid >> 5, lane = tid & 31;
    for (int t = tid; t < D * CH; t += 256) wdfs[t] = w1[t] - w1[D * CH + t];
    if (tid < CH) b1s[tid] = b1[tid];
    __syncthreads();
    const int k0 = 2 * lane;
    for (int g = 0; g < 8; g++) {
        int i = blockIdx.x * 64 + g * 8 + p;
        const float* fx = feat + (size_t)i * D;
        float bx = b1s[k0], by = b1s[k0 + 1];
        if constexpr (D == 1) {
            float xv = fx[0];
            float2 wd = *(const float2*)&wdfs[k0];
            bx = fmaf(xv, wd.x, bx);
            by = fmaf(xv, wd.y, by);
        } else {
            // D multiple of 32 (here 64): lanes hold x in registers, shuffle-broadcast
            float xr[D / 32];
#pragma unroll
            for (int h = 0; h < D / 32; h++) xr[h] = fx[h * 32 + lane];
#pragma unroll
            for (int h = 0; h < D / 32; h++) {
                for (int j = 0; j < 32; j++) {
                    float xv = __shfl_sync(0xffffffffu, xr[h], j);
                    float2 wd = *(const float2*)&wdfs[(h * 32 + j) * CH + k0];
                    bx = fmaf(xv, wd.x, bx);
                    by = fmaf(xv, wd.y, by);
                }
            }
        }
        *(float2*)&baseo[(size_t)i * CH + k0] = make_float2(bx, by);
    }
}

// ---------------- EdgeConv: relu(e@w1+b1)@w2+b2, max over K ---------------------
// h1 = base_i + sum_j xj * w1[D:,:]  (base precomputed by base_kernel)
// Neighbors gathered + processed in chunks of NB=8; smem ~66KB -> 3 blocks/SM.
template <int D>
__global__ void __launch_bounds__(256, 3) edgeconv_kernel(
    const float* __restrict__ feat, const int* __restrict__ idx,
    const float* __restrict__ basep,
    const float* __restrict__ w1, const float* __restrict__ w2,
    const float* __restrict__ b2, float* __restrict__ out) {
    constexpr int PTS = 8;     // warps per block
    constexpr int NB = 8;      // neighbor chunk
    constexpr int GROUPS = 4;  // sequential points per warp
    constexpr int Dp = (D + 3) & ~3;
    extern __shared__ float s[];
    float* w1bs = s;                           // D*CH   (w1[D:,:])
    float* w2s  = w1bs + D * CH;               // CH*CH
    float* b2s  = w2s + CH * CH;               // CH
    float* xjs  = b2s + CH;                    // PTS*NB*Dp (chunk buffer)
    float* h1c  = xjs + PTS * NB * Dp;         // PTS*NB*CH
    int* nbr    = (int*)(h1c + PTS * NB * CH); // PTS*KK

    const int tid = threadIdx.x;  // 256 = 8 warps
    const int p = tid >> 5, lane = tid & 31;

    for (int t = tid; t < D * CH; t += 256) w1bs[t] = w1[D * CH + t];
    for (int t = tid; t < CH * CH; t += 256) w2s[t] = w2[t];
    if (tid < CH) b2s[tid] = b2[tid];
    __syncthreads();

    const int k0 = 2 * lane;  // each lane owns 2 output channels

    for (int grp = 0; grp < GROUPS; grp++) {
        const int gbase = blockIdx.x * (PTS * GROUPS) + grp * PTS;
        const int b = gbase / NPTS;
        const int i = (gbase % NPTS) + p;
        const int gi = b * NPTS + i;
        const float* fb = feat + (size_t)b * NPTS * D;

        if (lane < KK) nbr[p * KK + lane] = idx[(size_t)gi * KK + lane];
        __syncwarp();

        float2 bse = *(const float2*)&basep[(size_t)gi * CH + k0];
        float bx = bse.x, by = bse.y;
        float mx = -FLT_MAX, my = -FLT_MAX;

        for (int c0 = 0; c0 < KK; c0 += NB) {
            // gather this chunk's neighbor features
            if constexpr (D % 4 == 0) {
                // vectorized: NB rows of D/4 float4s
                for (int t = lane; t < NB * (D / 4); t += 32) {
                    int nb = t / (D / 4), c4 = t % (D / 4);
                    float4 vv = *(const float4*)(fb +
                        (size_t)nbr[p * KK + c0 + nb] * D + 4 * c4);
                    *(float4*)&xjs[p * NB * D + nb * D + 4 * c4] = vv;
                }
            } else {
                for (int t = lane; t < NB * D; t += 32) {
                    int nb = t / D, c = t % D;
                    xjs[p * NB * D + t] = fb[(size_t)nbr[p * KK + c0 + nb] * D + c];
                }
            }
            __syncwarp();

            float2 acc[NB];
#pragma unroll
            for (int nb = 0; nb < NB; nb++) acc[nb] = make_float2(0.f, 0.f);

            if constexpr (D % 4 == 0) {
                const float* xbase = &xjs[p * NB * D];
                for (int j = 0; j < D; j += 4) {
                    const float* wb = &w1bs[j * CH + k0];
                    float2 wv0 = *(const float2*)(wb);
                    float2 wv1 = *(const float2*)(wb + CH);
                    float2 wv2 = *(const float2*)(wb + 2 * CH);
                    float2 wv3 = *(const float2*)(wb + 3 * CH);
#pragma unroll
                    for (int nb = 0; nb < NB; nb++) {
                        float4 xv = *(const float4*)(xbase + nb * D + j);
                        acc[nb].x = fmaf(xv.x, wv0.x, acc[nb].x);
                        acc[nb].y = fmaf(xv.x, wv0.y, acc[nb].y);
                        acc[nb].x = fmaf(xv.y, wv1.x, acc[nb].x);
                        acc[nb].y = fmaf(xv.y, wv1.y, acc[nb].y);
                        acc[nb].x = fmaf(xv.z, wv2.x, acc[nb].x);
                        acc[nb].y = fmaf(xv.z, wv2.y, acc[nb].y);
                        acc[nb].x = fmaf(xv.w, wv3.x, acc[nb].x);
                        acc[nb].y = fmaf(xv.w, wv3.y, acc[nb].y);
                    }
                }
            } else {
                for (int j = 0; j < D; j++) {
                    float2 w = *(const float2*)&w1bs[j * CH + k0];
                    const float* xr = &xjs[p * NB * D + j];
#pragma unroll
                    for (int nb = 0; nb < NB; nb++) {
                        float xj = xr[nb * D];
                        acc[nb].x = fmaf(xj, w.x, acc[nb].x);
                        acc[nb].y = fmaf(xj, w.y, acc[nb].y);
                    }
                }
            }
            // write h1 chunk (relu), own warp only
#pragma unroll
            for (int nb = 0; nb < NB; nb++) {
                float2 h;
                h.x = fmaxf(bx + acc[nb].x, 0.f);
                h.y = fmaxf(by + acc[nb].y, 0.f);
                *(float2*)&h1c[(p * NB + nb) * CH + k0] = h;
            }
            __syncwarp();

            // stage 2 on this chunk: h1 @ w2
#pragma unroll
            for (int nb = 0; nb < NB; nb++) acc[nb] = make_float2(0.f, 0.f);
            const float* hbase = &h1c[p * NB * CH];
            for (int j = 0; j < CH; j += 4) {
                const float* wb = &w2s[j * CH + k0];
                float2 wv0 = *(const float2*)(wb);
                float2 wv1 = *(const float2*)(wb + CH);
                float2 wv2 = *(const float2*)(wb + 2 * CH);
                float2 wv3 = *(const float2*)(wb + 3 * CH);
#pragma unroll
                for (int nb = 0; nb < NB; nb++) {
                    float4 hv = *(const float4*)(hbase + nb * CH + j);
                    acc[nb].x = fmaf(hv.x, wv0.x, acc[nb].x);
                    acc[nb].y = fmaf(hv.x, wv0.y, acc[nb].y);
                    acc[nb].x = fmaf(hv.y, wv1.x, acc[nb].x);
                    acc[nb].y = fmaf(hv.y, wv1.y, acc[nb].y);
                    acc[nb].x = fmaf(hv.z, wv2.x, acc[nb].x);
                    acc[nb].y = fmaf(hv.z, wv2.y, acc[nb].y);
                    acc[nb].x = fmaf(hv.w, wv3.x, acc[nb].x);
                    acc[nb].y = fmaf(hv.w, wv3.y, acc[nb].y);
                }
            }
#pragma unroll
            for (int nb = 0; nb < NB; nb++) {
                mx = fmaxf(mx, acc[nb].x);
                my = fmaxf(my, acc[nb].y);
            }
            __syncwarp();  // before next chunk overwrites xjs/h1c
        }

        size_t ob = (size_t)gi * CH;
        out[ob + k0]     = mx + b2s[k0];
        out[ob + k0 + 1] = my + b2s[k0 + 1];
    }
}

// ---------------- final MLP: 192 -> 128 -> 64 -> 32 -> 2, log_softmax ------------
__global__ void __launch_bounds__(512) mlp_kernel(
    const float* __restrict__ x1, const float* __restrict__ x2,
    const float* __restrict__ x3,
    const float* __restrict__ mw1, const float* __restrict__ mb1,
    const float* __restrict__ mw2, const float* __restrict__ mb2,
    const float* __restrict__ mw3, const float* __restrict__ mb3,
    const float* __restrict__ mw4, const float* __restrict__ mb4,
    float* __restrict__ out) {
    extern __shared__ float s[];
    float* w1s = s;               // 192*128 = 24576
    float* w2s = w1s + 24576;     // 128*64  = 8192
    float* w3s = w2s + 8192;      // 64*32   = 2048
    float* w4s = w3s + 2048;      // 32*2    = 64
    float* b1s = w4s + 64;        // 128
    float* b2s = b1s + 128;       // 64
    float* b3s = b2s + 64;        // 32
    float* b4s = b3s + 32;        // 4 (pad -> fbuf 16B-aligned)
    float* fbuf = b4s + 4;        // 16 warps * 192
    float* hbuf = fbuf + 16 * 192;// 16 warps * 128

    const int tid = threadIdx.x;  // 512 = 16 warps
    const int w = tid >> 5, lane = tid & 31;
    for (int t = tid; t < 24576; t += 512) w1s[t] = mw1[t];
    for (int t = tid; t < 8192; t += 512) w2s[t] = mw2[t];
    for (int t = tid; t < 2048; t += 512) w3s[t] = mw3[t];
    if (tid < 64) w4s[tid] = mw4[tid];
    if (tid < 128) b1s[tid] = mb1[tid];
    if (tid < 64) b2s[tid] = mb2[tid];
    if (tid < 32) b3s[tid] = mb3[tid];
    if (tid < 2) b4s[tid] = mb4[tid];
    __syncthreads();

    const int ptsPerBlock = (BATCH * NPTS) / gridDim.x;
    const int pbase = blockIdx.x * ptsPerBlock;
    float* f = fbuf + w * 192;
    float* h = hbuf + w * 128;

    for (int pt = pbase + w; pt < pbase + ptsPerBlock; pt += 16) {
        for (int t = lane; t < 64; t += 32) {
            f[t]       = x1[(size_t)pt * 64 + t];
            f[64 + t]  = x2[(size_t)pt * 64 + t];
            f[128 + t] = x3[(size_t)pt * 64 + t];
        }
        __syncwarp();
        // layer 1: 192 -> 128
        float4 a1 = *(const float4*)&b1s[4 * lane];
        for (int j = 0; j < 192; j += 4) {
            float4 xv = *(const float4*)&f[j];
            const float* wb = &w1s[j * 128 + 4 * lane];
            float4 w0 = *(const float4*)(wb);
            float4 w1v = *(const float4*)(wb + 128);
            float4 w2v = *(const float4*)(wb + 256);
            float4 w3v = *(const float4*)(wb + 384);
            a1.x = fmaf(xv.x, w0.x, a1.x); a1.y = fmaf(xv.x, w0.y, a1.y);
            a1.z = fmaf(xv.x, w0.z, a1.z); a1.w = fmaf(xv.x, w0.w, a1.w);
            a1.x = fmaf(xv.y, w1v.x, a1.x); a1.y = fmaf(xv.y, w1v.y, a1.y);
            a1.z = fmaf(xv.y, w1v.z, a1.z); a1.w = fmaf(xv.y, w1v.w, a1.w);
            a1.x = fmaf(xv.z, w2v.x, a1.x); a1.y = fmaf(xv.z, w2v.y, a1.y);
            a1.z = fmaf(xv.z, w2v.z, a1.z); a1.w = fmaf(xv.z, w2v.w, a1.w);
            a1.x = fmaf(xv.w, w3v.x, a1.x); a1.y = fmaf(xv.w, w3v.y, a1.y);
            a1.z = fmaf(xv.w, w3v.z, a1.z); a1.w = fmaf(xv.w, w3v.w, a1.w);
        }
        h[4 * lane]     = fmaxf(a1.x, 0.f);
        h[4 * lane + 1] = fmaxf(a1.y, 0.f);
        h[4 * lane + 2] = fmaxf(a1.z, 0.f);
        h[4 * lane + 3] = fmaxf(a1.w, 0.f);
        __syncwarp();
        // layer 2: 128 -> 64
        float2 a2 = *(const float2*)&b2s[2 * lane];
        for (int j = 0; j < 128; j += 4) {
            float4 hv = *(const float4*)&h[j];
            const float* wb = &w2s[j * 64 + 2 * lane];
            float2 w0 = *(const float2*)(wb);
            float2 w1v = *(const float2*)(wb + 64);
            float2 w2v = *(const float2*)(wb + 128);
            float2 w3v = *(const float2*)(wb + 192);
            a2.x = fmaf(hv.x, w0.x, a2.x); a2.y = fmaf(hv.x, w0.y, a2.y);
            a2.x = fmaf(hv.y, w1v.x, a2.x); a2.y = fmaf(hv.y, w1v.y, a2.y);
            a2.x = fmaf(hv.z, w2v.x, a2.x); a2.y = fmaf(hv.z, w2v.y, a2.y);
            a2.x = fmaf(hv.w, w3v.x, a2.x); a2.y = fmaf(hv.w, w3v.y, a2.y);
        }
        __syncwarp();
        f[2 * lane]     = fmaxf(a2.x, 0.f);
        f[2 * lane + 1] = fmaxf(a2.y, 0.f);
        __syncwarp();
        // layer 3: 64 -> 32
        float a3 = b3s[lane];
        for (int j = 0; j < 64; j++) a3 = fmaf(f[j], w3s[j * 32 + lane], a3);
        a3 = fmaxf(a3, 0.f);
        __syncwarp();
        h[lane] = a3;
        __syncwarp();
        // layer 4 + log_softmax (2 classes)
        float o = 0.f;
        if (lane < 2) {
            o = b4s[lane];
            for (int j = 0; j < 32; j++) o = fmaf(h[j], w4s[j * 2 + lane], o);
        }
        float oo = __shfl_xor_sync(0xffffffffu, o, 1);
        if (lane < 2) {
            float mm = fmaxf(o, oo);
            float lse = mm + logf(expf(o - mm) + expf(oo - mm));
            out[(size_t)pt * 2 + lane] = o - lse;
        }
        __syncwarp();
    }
}

// ---------------- launch -------------------------------------------------------
static constexpr size_t ec_smem(int D) {
    int Dp = (D + 3) & ~3;
    return (size_t)(D * CH + CH * CH + CH + 8 * 8 * Dp + 8 * 8 * CH + 8 * KK) * 4;
}
static constexpr size_t MLP_SMEM =
    (size_t)(24576 + 8192 + 2048 + 64 + 128 + 64 + 32 + 4 + 16 * 192 + 16 * 128) * 4;

extern "C" void kernel_launch(void* const* d_in, const int* in_sizes, int n_in,
                              void* d_out, int out_size) {
    (void)in_sizes; (void)n_in; (void)out_size;
    const float* x    = (const float*)d_in[0];
    const float* c1w1 = (const float*)d_in[1];
    const float* c1b1 = (const float*)d_in[2];
    const float* c1w2 = (const float*)d_in[3];
    const float* c1b2 = (const float*)d_in[4];
    const float* c2w1 = (const float*)d_in[5];
    const float* c2b1 = (const float*)d_in[6];
    const float* c2w2 = (const float*)d_in[7];
    const float* c2b2 = (const float*)d_in[8];
    const float* c3w1 = (const float*)d_in[9];
    const float* c3b1 = (const float*)d_in[10];
    const float* c3w2 = (const float*)d_in[11];
    const float* c3b2 = (const float*)d_in[12];
    const float* mw1  = (const float*)d_in[13];
    const float* mb1  = (const float*)d_in[14];
    const float* mw2  = (const float*)d_in[15];
    const float* mb2  = (const float*)d_in[16];
    const float* mw3  = (const float*)d_in[17];
    const float* mb3  = (const float*)d_in[18];
    const float* mw4  = (const float*)d_in[19];
    const float* mb4  = (const float*)d_in[20];
    float* outp = (float*)d_out;

    float *x1p, *x2p, *x3p, *basep;
    int* idxp;
    cudaGetSymbolAddress((void**)&x1p, g_x1);
    cudaGetSymbolAddress((void**)&x2p, g_x2);
    cudaGetSymbolAddress((void**)&x3p, g_x3);
    cudaGetSymbolAddress((void**)&basep, g_base);
    cudaGetSymbolAddress((void**)&idxp, g_idx);

    cudaFuncSetAttribute(edgeconv_kernel<1>,
                         cudaFuncAttributeMaxDynamicSharedMemorySize, (int)ec_smem(1));
    cudaFuncSetAttribute(edgeconv_kernel<64>,
                         cudaFuncAttributeMaxDynamicSharedMemorySize, (int)ec_smem(64));
    cudaFuncSetAttribute(mlp_kernel,
                         cudaFuncAttributeMaxDynamicSharedMemorySize, (int)MLP_SMEM);

    const int nblk_knn  = BATCH * NPTS / 8;   // 8192
    const int nblk_ec   = BATCH * NPTS / 32;  // 2048
    const int nblk_base = BATCH * NPTS / 64;  // 1024

    knn_kernel<1><<<nblk_knn, 256>>>(x, idxp);
    base_kernel<1><<<nblk_base, 256>>>(x, c1w1, c1b1, basep);
    edgeconv_kernel<1><<<nblk_ec, 256, ec_smem(1)>>>(x, idxp, basep, c1w1, c1w2, c1b2, x1p);

    knn_kernel<64><<<nblk_knn, 256>>>(x1p, idxp);
    base_kernel<64><<<nblk_base, 256>>>(x1p, c2w1, c2b1, basep);
    edgeconv_kernel<64><<<nblk_ec, 256, ec_smem(64)>>>(x1p, idxp, basep, c2w1, c2w2, c2b2, x2p);

    knn_kernel<64><<<nblk_knn, 256>>>(x2p, idxp);
    base_kernel<64><<<nblk_base, 256>>>(x2p, c3w1, c3b1, basep);
    edgeconv_kernel<64><<<nblk_ec, 256, ec_smem(64)>>>(x2p, idxp, basep, c3w1, c3w2, c3b2, x3p);

    mlp_kernel<<<128, 512, MLP_SMEM>>>(x1p, x2p, x3p, mw1, mb1, mw2, mb2,
                                       mw3, mb3, mw4, mb4, outp);
}

// round 7
// speedup vs baseline: 1.7195x; 1.1218x over previous
#include <cuda_runtime.h>
#include <math.h>
#include <float.h>

#define BATCH 64
#define NPTS  1024
#define KK    16
#define CH    64

// ---------------- scratch (static device globals; no allocation) ----------------
__device__ __align__(16) float g_x1[BATCH * NPTS * CH];
__device__ __align__(16) float g_x2[BATCH * NPTS * CH];
__device__ __align__(16) float g_x3[BATCH * NPTS * CH];
__device__ __align__(16) float g_xt[BATCH * NPTS * CH];   // transposed features
__device__ __align__(16) float g_base[BATCH * NPTS * CH];
__device__ int g_idx[BATCH * NPTS * KK];

// ---------------- kNN (D=1): original row-major path (already coalesced) --------
template <int D>
__global__ void __launch_bounds__(256) knn_kernel(const float* __restrict__ feat,
                                                  int* __restrict__ idx_out) {
    constexpr int PB = 8;
    __shared__ __align__(16) float dist[PB][NPTS];
    __shared__ __align__(16) float xis[PB][(D < 4) ? 4 : D];
    __shared__ float sqi[PB];

    const int tid = threadIdx.x;          // 256 threads
    const int gbase = blockIdx.x * PB;
    const int b = gbase / NPTS;
    const int i0 = gbase % NPTS;
    const float* fb = feat + (size_t)b * NPTS * D;

    for (int t = tid; t < PB * D; t += 256) {
        int p = t / D, c = t % D;
        xis[p][c] = fb[(i0 + p) * D + c];
    }
    __syncthreads();
    if (tid < PB) {
        float s = 0.f;
        for (int c = 0; c < D; c++) s += xis[tid][c] * xis[tid][c];
        sqi[tid] = s;
    }
    __syncthreads();

    for (int j = tid; j < NPTS; j += 256) {
        const float* fj = fb + (size_t)j * D;
        float sqj = 0.f;
        float dot[PB];
#pragma unroll
        for (int p = 0; p < PB; p++) dot[p] = 0.f;
        for (int c = 0; c < D; c++) {
            float v = fj[c];
            sqj += v * v;
#pragma unroll
            for (int p = 0; p < PB; p++) dot[p] += v * xis[p][c];
        }
#pragma unroll
        for (int p = 0; p < PB; p++) dist[p][j] = sqi[p] + sqj - 2.f * dot[p];
    }
    __syncthreads();

    // selection: warp g picks 16 smallest (register-resident, ties -> smaller idx)
    const int g = tid >> 5, lane = tid & 31;
    const float* row = dist[g];
    float v[32];
#pragma unroll
    for (int r = 0; r < 32; r++) v[r] = row[lane + 32 * r];

    int* outp = &idx_out[((size_t)(b * NPTS + i0 + g)) * KK];
    for (int k = 0; k < KK; k++) {
        float bv = v[0];
        int br = 0;
#pragma unroll
        for (int r = 1; r < 32; r++) {
            if (v[r] < bv) { bv = v[r]; br = r; }
        }
        int bi = lane + 32 * br;
#pragma unroll
        for (int o = 16; o > 0; o >>= 1) {
            float ov = __shfl_xor_sync(0xffffffffu, bv, o);
            int oi = __shfl_xor_sync(0xffffffffu, bi, o);
            if (ov < bv || (ov == bv && oi < bi)) { bv = ov; bi = oi; }
        }
        if (lane == 0) outp[k] = bi;
        if ((bi & 31) == lane) {
            int rr = bi >> 5;
#pragma unroll
            for (int r = 0; r < 32; r++)
                if (r == rr) v[r] = FLT_MAX;
        }
    }
}

// ---------------- transpose: [NPTS, CH] -> [CH, NPTS] per batch ------------------
// Block handles 64 rows x 64 channels; smem tile padded -> conflict-free.
__global__ void __launch_bounds__(256) transpose_kernel(const float* __restrict__ feat,
                                                        float* __restrict__ featT) {
    __shared__ float tile[64 * 65];
    const int tid = threadIdx.x;
    const int bpB = NPTS / 64;  // 16 blocks per batch
    const int b = blockIdx.x / bpB;
    const int row0 = (blockIdx.x % bpB) * 64;
    const float* fb = feat + ((size_t)b * NPTS + row0) * CH;
    for (int t = tid; t < 64 * 64; t += 256) {
        int r = t >> 6, c = t & 63;            // reads coalesced over c
        tile[c * 65 + r] = fb[r * CH + c];
    }
    __syncthreads();
    float* ob = featT + (size_t)b * CH * NPTS + row0;
    for (int t = tid; t < 64 * 64; t += 256) {
        int c = t >> 6, r = t & 63;            // writes coalesced over r
        ob[(size_t)c * NPTS + r] = tile[c * 65 + r];
    }
}

// ---------------- kNN (CH=64) on transposed features: coalesced loads -----------
__global__ void __launch_bounds__(256, 4) knn_t_kernel(const float* __restrict__ featT,
                                                       int* __restrict__ idx_out) {
    constexpr int PB = 8;
    __shared__ __align__(16) float dist[PB][NPTS];
    __shared__ __align__(16) float xqT[CH * PB];  // [c][p]
    __shared__ float sqi[PB];

    const int tid = threadIdx.x;
    const int gbase = blockIdx.x * PB;
    const int b = gbase / NPTS;
    const int i0 = gbase % NPTS;
    const float* ftb = featT + (size_t)b * CH * NPTS;

    // stage the 8 query columns: xqT[c*8+p] = ftb[c*NPTS + i0+p]
    for (int t = tid; t < CH * PB; t += 256) {
        int c = t >> 3, p = t & 7;
        xqT[t] = ftb[(size_t)c * NPTS + i0 + p];
    }
    __syncthreads();
    if (tid < PB) {
        float s = 0.f;
        for (int c = 0; c < CH; c++) { float q = xqT[c * 8 + tid]; s = fmaf(q, q, s); }
        sqi[tid] = s;
    }
    __syncthreads();

    // distance: thread owns 4 consecutive j; loads coalesced across lanes
    const float4* ft4 = (const float4*)ftb;  // [c][NPTS/4]
    float dot[PB][4];
    float sqj[4];
#pragma unroll
    for (int p = 0; p < PB; p++)
#pragma unroll
        for (int jj = 0; jj < 4; jj++) dot[p][jj] = 0.f;
#pragma unroll
    for (int jj = 0; jj < 4; jj++) sqj[jj] = 0.f;

    for (int c = 0; c < CH; c++) {
        float4 v = ft4[c * (NPTS / 4) + tid];
        sqj[0] = fmaf(v.x, v.x, sqj[0]);
        sqj[1] = fmaf(v.y, v.y, sqj[1]);
        sqj[2] = fmaf(v.z, v.z, sqj[2]);
        sqj[3] = fmaf(v.w, v.w, sqj[3]);
        float4 q0 = *(const float4*)&xqT[c * 8];
        float4 q1 = *(const float4*)&xqT[c * 8 + 4];
        float q[8] = {q0.x, q0.y, q0.z, q0.w, q1.x, q1.y, q1.z, q1.w};
#pragma unroll
        for (int p = 0; p < PB; p++) {
            dot[p][0] = fmaf(v.x, q[p], dot[p][0]);
            dot[p][1] = fmaf(v.y, q[p], dot[p][1]);
            dot[p][2] = fmaf(v.z, q[p], dot[p][2]);
            dot[p][3] = fmaf(v.w, q[p], dot[p][3]);
        }
    }
    const int j0 = tid * 4;
#pragma unroll
    for (int p = 0; p < PB; p++) {
        float4 dv;
        dv.x = sqi[p] + sqj[0] - 2.f * dot[p][0];
        dv.y = sqi[p] + sqj[1] - 2.f * dot[p][1];
        dv.z = sqi[p] + sqj[2] - 2.f * dot[p][2];
        dv.w = sqi[p] + sqj[3] - 2.f * dot[p][3];
        *(float4*)&dist[p][j0] = dv;
    }
    __syncthreads();

    // selection (identical to knn_kernel)
    const int g = tid >> 5, lane = tid & 31;
    const float* row = dist[g];
    float v[32];
#pragma unroll
    for (int r = 0; r < 32; r++) v[r] = row[lane + 32 * r];

    int* outp = &idx_out[((size_t)(b * NPTS + i0 + g)) * KK];
    for (int k = 0; k < KK; k++) {
        float bv = v[0];
        int br = 0;
#pragma unroll
        for (int r = 1; r < 32; r++) {
            if (v[r] < bv) { bv = v[r]; br = r; }
        }
        int bi = lane + 32 * br;
#pragma unroll
        for (int o = 16; o > 0; o >>= 1) {
            float ov = __shfl_xor_sync(0xffffffffu, bv, o);
            int oi = __shfl_xor_sync(0xffffffffu, bi, o);
            if (ov < bv || (ov == bv && oi < bi)) { bv = ov; bi = oi; }
        }
        if (lane == 0) outp[k] = bi;
        if ((bi & 31) == lane) {
            int rr = bi >> 5;
#pragma unroll
            for (int r = 0; r < 32; r++)
                if (r == rr) v[r] = FLT_MAX;
        }
    }
}

// ---------------- base precompute: base = b1 + x_i * (w1[:D,:] - w1[D:,:]) ------
template <int D>
__global__ void __launch_bounds__(256) base_kernel(
    const float* __restrict__ feat, const float* __restrict__ w1,
    const float* __restrict__ b1, float* __restrict__ baseo) {
    __shared__ float wdfs[D * CH];
    __shared__ float b1s[CH];
    const int tid = threadIdx.x, p = tid >> 5, lane = tid & 31;
    for (int t = tid; t < D * CH; t += 256) wdfs[t] = w1[t] - w1[D * CH + t];
    if (tid < CH) b1s[tid] = b1[tid];
    __syncthreads();
    const int k0 = 2 * lane;
    for (int g = 0; g < 8; g++) {
        int i = blockIdx.x * 64 + g * 8 + p;
        const float* fx = feat + (size_t)i * D;
        float bx = b1s[k0], by = b1s[k0 + 1];
        if constexpr (D == 1) {
            float xv = fx[0];
            float2 wd = *(const float2*)&wdfs[k0];
            bx = fmaf(xv, wd.x, bx);
            by = fmaf(xv, wd.y, by);
        } else {
            float xr[D / 32];
#pragma unroll
            for (int h = 0; h < D / 32; h++) xr[h] = fx[h * 32 + lane];
#pragma unroll
            for (int h = 0; h < D / 32; h++) {
                for (int j = 0; j < 32; j++) {
                    float xv = __shfl_sync(0xffffffffu, xr[h], j);
                    float2 wd = *(const float2*)&wdfs[(h * 32 + j) * CH + k0];
                    bx = fmaf(xv, wd.x, bx);
                    by = fmaf(xv, wd.y, by);
                }
            }
        }
        *(float2*)&baseo[(size_t)i * CH + k0] = make_float2(bx, by);
    }
}

// ---------------- EdgeConv: relu(e@w1+b1)@w2+b2, max over K ---------------------
template <int D>
__global__ void __launch_bounds__(256, 3) edgeconv_kernel(
    const float* __restrict__ feat, const int* __restrict__ idx,
    const float* __restrict__ basep,
    const float* __restrict__ w1, const float* __restrict__ w2,
    const float* __restrict__ b2, float* __restrict__ out) {
    constexpr int PTS = 8;
    constexpr int NB = 8;
    constexpr int GROUPS = 4;
    constexpr int Dp = (D + 3) & ~3;
    extern __shared__ float s[];
    float* w1bs = s;                           // D*CH   (w1[D:,:])
    float* w2s  = w1bs + D * CH;               // CH*CH
    float* b2s  = w2s + CH * CH;               // CH
    float* xjs  = b2s + CH;                    // PTS*NB*Dp
    float* h1c  = xjs + PTS * NB * Dp;         // PTS*NB*CH
    int* nbr    = (int*)(h1c + PTS * NB * CH); // PTS*KK

    const int tid = threadIdx.x;
    const int p = tid >> 5, lane = tid & 31;

    for (int t = tid; t < D * CH; t += 256) w1bs[t] = w1[D * CH + t];
    for (int t = tid; t < CH * CH; t += 256) w2s[t] = w2[t];
    if (tid < CH) b2s[tid] = b2[tid];
    __syncthreads();

    const int k0 = 2 * lane;

    for (int grp = 0; grp < GROUPS; grp++) {
        const int gbase = blockIdx.x * (PTS * GROUPS) + grp * PTS;
        const int b = gbase / NPTS;
        const int i = (gbase % NPTS) + p;
        const int gi = b * NPTS + i;
        const float* fb = feat + (size_t)b * NPTS * D;

        if (lane < KK) nbr[p * KK + lane] = idx[(size_t)gi * KK + lane];
        __syncwarp();

        float2 bse = *(const float2*)&basep[(size_t)gi * CH + k0];
        float bx = bse.x, by = bse.y;
        float mx = -FLT_MAX, my = -FLT_MAX;

        for (int c0 = 0; c0 < KK; c0 += NB) {
            if constexpr (D % 4 == 0) {
                for (int t = lane; t < NB * (D / 4); t += 32) {
                    int nb = t / (D / 4), c4 = t % (D / 4);
                    float4 vv = *(const float4*)(fb +
                        (size_t)nbr[p * KK + c0 + nb] * D + 4 * c4);
                    *(float4*)&xjs[p * NB * D + nb * D + 4 * c4] = vv;
                }
            } else {
                for (int t = lane; t < NB * D; t += 32) {
                    int nb = t / D, c = t % D;
                    xjs[p * NB * D + t] = fb[(size_t)nbr[p * KK + c0 + nb] * D + c];
                }
            }
            __syncwarp();

            float2 acc[NB];
#pragma unroll
            for (int nb = 0; nb < NB; nb++) acc[nb] = make_float2(0.f, 0.f);

            if constexpr (D % 4 == 0) {
                const float* xbase = &xjs[p * NB * D];
                for (int j = 0; j < D; j += 4) {
                    const float* wb = &w1bs[j * CH + k0];
                    float2 wv0 = *(const float2*)(wb);
                    float2 wv1 = *(const float2*)(wb + CH);
                    float2 wv2 = *(const float2*)(wb + 2 * CH);
                    float2 wv3 = *(const float2*)(wb + 3 * CH);
#pragma unroll
                    for (int nb = 0; nb < NB; nb++) {
                        float4 xv = *(const float4*)(xbase + nb * D + j);
                        acc[nb].x = fmaf(xv.x, wv0.x, acc[nb].x);
                        acc[nb].y = fmaf(xv.x, wv0.y, acc[nb].y);
                        acc[nb].x = fmaf(xv.y, wv1.x, acc[nb].x);
                        acc[nb].y = fmaf(xv.y, wv1.y, acc[nb].y);
                        acc[nb].x = fmaf(xv.z, wv2.x, acc[nb].x);
                        acc[nb].y = fmaf(xv.z, wv2.y, acc[nb].y);
                        acc[nb].x = fmaf(xv.w, wv3.x, acc[nb].x);
                        acc[nb].y = fmaf(xv.w, wv3.y, acc[nb].y);
                    }
                }
            } else {
                for (int j = 0; j < D; j++) {
                    float2 w = *(const float2*)&w1bs[j * CH + k0];
                    const float* xr = &xjs[p * NB * D + j];
#pragma unroll
                    for (int nb = 0; nb < NB; nb++) {
                        float xj = xr[nb * D];
                        acc[nb].x = fmaf(xj, w.x, acc[nb].x);
                        acc[nb].y = fmaf(xj, w.y, acc[nb].y);
                    }
                }
            }
#pragma unroll
            for (int nb = 0; nb < NB; nb++) {
                float2 h;
                h.x = fmaxf(bx + acc[nb].x, 0.f);
                h.y = fmaxf(by + acc[nb].y, 0.f);
                *(float2*)&h1c[(p * NB + nb) * CH + k0] = h;
            }
            __syncwarp();

#pragma unroll
            for (int nb = 0; nb < NB; nb++) acc[nb] = make_float2(0.f, 0.f);
            const float* hbase = &h1c[p * NB * CH];
            for (int j = 0; j < CH; j += 4) {
                const float* wb = &w2s[j * CH + k0];
                float2 wv0 = *(const float2*)(wb);
                float2 wv1 = *(const float2*)(wb + CH);
                float2 wv2 = *(const float2*)(wb + 2 * CH);
                float2 wv3 = *(const float2*)(wb + 3 * CH);
#pragma unroll
                for (int nb = 0; nb < NB; nb++) {
                    float4 hv = *(const float4*)(hbase + nb * CH + j);
                    acc[nb].x = fmaf(hv.x, wv0.x, acc[nb].x);
                    acc[nb].y = fmaf(hv.x, wv0.y, acc[nb].y);
                    acc[nb].x = fmaf(hv.y, wv1.x, acc[nb].x);
                    acc[nb].y = fmaf(hv.y, wv1.y, acc[nb].y);
                    acc[nb].x = fmaf(hv.z, wv2.x, acc[nb].x);
                    acc[nb].y = fmaf(hv.z, wv2.y, acc[nb].y);
                    acc[nb].x = fmaf(hv.w, wv3.x, acc[nb].x);
                    acc[nb].y = fmaf(hv.w, wv3.y, acc[nb].y);
                }
            }
#pragma unroll
            for (int nb = 0; nb < NB; nb++) {
                mx = fmaxf(mx, acc[nb].x);
                my = fmaxf(my, acc[nb].y);
            }
            __syncwarp();
        }

        size_t ob = (size_t)gi * CH;
        out[ob + k0]     = mx + b2s[k0];
        out[ob + k0 + 1] = my + b2s[k0 + 1];
    }
}

// ---------------- final MLP: 192 -> 128 -> 64 -> 32 -> 2, log_softmax ------------
__global__ void __launch_bounds__(512) mlp_kernel(
    const float* __restrict__ x1, const float* __restrict__ x2,
    const float* __restrict__ x3,
    const float* __restrict__ mw1, const float* __restrict__ mb1,
    const float* __restrict__ mw2, const float* __restrict__ mb2,
    const float* __restrict__ mw3, const float* __restrict__ mb3,
    const float* __restrict__ mw4, const float* __restrict__ mb4,
    float* __restrict__ out) {
    extern __shared__ float s[];
    float* w1s = s;
    float* w2s = w1s + 24576;
    float* w3s = w2s + 8192;
    float* w4s = w3s + 2048;
    float* b1s = w4s + 64;
    float* b2s = b1s + 128;
    float* b3s = b2s + 64;
    float* b4s = b3s + 32;
    float* fbuf = b4s + 4;
    float* hbuf = fbuf + 16 * 192;

    const int tid = threadIdx.x;
    const int w = tid >> 5, lane = tid & 31;
    for (int t = tid; t < 24576; t += 512) w1s[t] = mw1[t];
    for (int t = tid; t < 8192; t += 512) w2s[t] = mw2[t];
    for (int t = tid; t < 2048; t += 512) w3s[t] = mw3[t];
    if (tid < 64) w4s[tid] = mw4[tid];
    if (tid < 128) b1s[tid] = mb1[tid];
    if (tid < 64) b2s[tid] = mb2[tid];
    if (tid < 32) b3s[tid] = mb3[tid];
    if (tid < 2) b4s[tid] = mb4[tid];
    __syncthreads();

    const int ptsPerBlock = (BATCH * NPTS) / gridDim.x;
    const int pbase = blockIdx.x * ptsPerBlock;
    float* f = fbuf + w * 192;
    float* h = hbuf + w * 128;

    for (int pt = pbase + w; pt < pbase + ptsPerBlock; pt += 16) {
        for (int t = lane; t < 64; t += 32) {
            f[t]       = x1[(size_t)pt * 64 + t];
            f[64 + t]  = x2[(size_t)pt * 64 + t];
            f[128 + t] = x3[(size_t)pt * 64 + t];
        }
        __syncwarp();
        float4 a1 = *(const float4*)&b1s[4 * lane];
        for (int j = 0; j < 192; j += 4) {
            float4 xv = *(const float4*)&f[j];
            const float* wb = &w1s[j * 128 + 4 * lane];
            float4 w0 = *(const float4*)(wb);
            float4 w1v = *(const float4*)(wb + 128);
            float4 w2v = *(const float4*)(wb + 256);
            float4 w3v = *(const float4*)(wb + 384);
            a1.x = fmaf(xv.x, w0.x, a1.x); a1.y = fmaf(xv.x, w0.y, a1.y);
            a1.z = fmaf(xv.x, w0.z, a1.z); a1.w = fmaf(xv.x, w0.w, a1.w);
            a1.x = fmaf(xv.y, w1v.x, a1.x); a1.y = fmaf(xv.y, w1v.y, a1.y);
            a1.z = fmaf(xv.y, w1v.z, a1.z); a1.w = fmaf(xv.y, w1v.w, a1.w);
            a1.x = fmaf(xv.z, w2v.x, a1.x); a1.y = fmaf(xv.z, w2v.y, a1.y);
            a1.z = fmaf(xv.z, w2v.z, a1.z); a1.w = fmaf(xv.z, w2v.w, a1.w);
            a1.x = fmaf(xv.w, w3v.x, a1.x); a1.y = fmaf(xv.w, w3v.y, a1.y);
            a1.z = fmaf(xv.w, w3v.z, a1.z); a1.w = fmaf(xv.w, w3v.w, a1.w);
        }
        h[4 * lane]     = fmaxf(a1.x, 0.f);
        h[4 * lane + 1] = fmaxf(a1.y, 0.f);
        h[4 * lane + 2] = fmaxf(a1.z, 0.f);
        h[4 * lane + 3] = fmaxf(a1.w, 0.f);
        __syncwarp();
        float2 a2 = *(const float2*)&b2s[2 * lane];
        for (int j = 0; j < 128; j += 4) {
            float4 hv = *(const float4*)&h[j];
            const float* wb = &w2s[j * 64 + 2 * lane];
            float2 w0 = *(const float2*)(wb);
            float2 w1v = *(const float2*)(wb + 64);
            float2 w2v = *(const float2*)(wb + 128);
            float2 w3v = *(const float2*)(wb + 192);
            a2.x = fmaf(hv.x, w0.x, a2.x); a2.y = fmaf(hv.x, w0.y, a2.y);
            a2.x = fmaf(hv.y, w1v.x, a2.x); a2.y = fmaf(hv.y, w1v.y, a2.y);
            a2.x = fmaf(hv.z, w2v.x, a2.x); a2.y = fmaf(hv.z, w2v.y, a2.y);
            a2.x = fmaf(hv.w, w3v.x, a2.x); a2.y = fmaf(hv.w, w3v.y, a2.y);
        }
        __syncwarp();
        f[2 * lane]     = fmaxf(a2.x, 0.f);
        f[2 * lane + 1] = fmaxf(a2.y, 0.f);
        __syncwarp();
        float a3 = b3s[lane];
        for (int j = 0; j < 64; j++) a3 = fmaf(f[j], w3s[j * 32 + lane], a3);
        a3 = fmaxf(a3, 0.f);
        __syncwarp();
        h[lane] = a3;
        __syncwarp();
        float o = 0.f;
        if (lane < 2) {
            o = b4s[lane];
            for (int j = 0; j < 32; j++) o = fmaf(h[j], w4s[j * 2 + lane], o);
        }
        float oo = __shfl_xor_sync(0xffffffffu, o, 1);
        if (lane < 2) {
            float mm = fmaxf(o, oo);
            float lse = mm + logf(expf(o - mm) + expf(oo - mm));
            out[(size_t)pt * 2 + lane] = o - lse;
        }
        __syncwarp();
    }
}

// ---------------- launch -------------------------------------------------------
static constexpr size_t ec_smem(int D) {
    int Dp = (D + 3) & ~3;
    return (size_t)(D * CH + CH * CH + CH + 8 * 8 * Dp + 8 * 8 * CH + 8 * KK) * 4;
}
static constexpr size_t MLP_SMEM =
    (size_t)(24576 + 8192 + 2048 + 64 + 128 + 64 + 32 + 4 + 16 * 192 + 16 * 128) * 4;

extern "C" void kernel_launch(void* const* d_in, const int* in_sizes, int n_in,
                              void* d_out, int out_size) {
    (void)in_sizes; (void)n_in; (void)out_size;
    const float* x    = (const float*)d_in[0];
    const float* c1w1 = (const float*)d_in[1];
    const float* c1b1 = (const float*)d_in[2];
    const float* c1w2 = (const float*)d_in[3];
    const float* c1b2 = (const float*)d_in[4];
    const float* c2w1 = (const float*)d_in[5];
    const float* c2b1 = (const float*)d_in[6];
    const float* c2w2 = (const float*)d_in[7];
    const float* c2b2 = (const float*)d_in[8];
    const float* c3w1 = (const float*)d_in[9];
    const float* c3b1 = (const float*)d_in[10];
    const float* c3w2 = (const float*)d_in[11];
    const float* c3b2 = (const float*)d_in[12];
    const float* mw1  = (const float*)d_in[13];
    const float* mb1  = (const float*)d_in[14];
    const float* mw2  = (const float*)d_in[15];
    const float* mb2  = (const float*)d_in[16];
    const float* mw3  = (const float*)d_in[17];
    const float* mb3  = (const float*)d_in[18];
    const float* mw4  = (const float*)d_in[19];
    const float* mb4  = (const float*)d_in[20];
    float* outp = (float*)d_out;

    float *x1p, *x2p, *x3p, *xtp, *basep;
    int* idxp;
    cudaGetSymbolAddress((void**)&x1p, g_x1);
    cudaGetSymbolAddress((void**)&x2p, g_x2);
    cudaGetSymbolAddress((void**)&x3p, g_x3);
    cudaGetSymbolAddress((void**)&xtp, g_xt);
    cudaGetSymbolAddress((void**)&basep, g_base);
    cudaGetSymbolAddress((void**)&idxp, g_idx);

    cudaFuncSetAttribute(edgeconv_kernel<1>,
                         cudaFuncAttributeMaxDynamicSharedMemorySize, (int)ec_smem(1));
    cudaFuncSetAttribute(edgeconv_kernel<64>,
                         cudaFuncAttributeMaxDynamicSharedMemorySize, (int)ec_smem(64));
    cudaFuncSetAttribute(mlp_kernel,
                         cudaFuncAttributeMaxDynamicSharedMemorySize, (int)MLP_SMEM);

    const int nblk_knn  = BATCH * NPTS / 8;   // 8192
    const int nblk_ec   = BATCH * NPTS / 32;  // 2048
    const int nblk_base = BATCH * NPTS / 64;  // 1024
    const int nblk_tr   = BATCH * (NPTS / 64);// 1024

    knn_kernel<1><<<nblk_knn, 256>>>(x, idxp);
    base_kernel<1><<<nblk_base, 256>>>(x, c1w1, c1b1, basep);
    edgeconv_kernel<1><<<nblk_ec, 256, ec_smem(1)>>>(x, idxp, basep, c1w1, c1w2, c1b2, x1p);

    transpose_kernel<<<nblk_tr, 256>>>(x1p, xtp);
    knn_t_kernel<<<nblk_knn, 256>>>(xtp, idxp);
    base_kernel<64><<<nblk_base, 256>>>(x1p, c2w1, c2b1, basep);
    edgeconv_kernel<64><<<nblk_ec, 256, ec_smem(64)>>>(x1p, idxp, basep, c2w1, c2w2, c2b2, x2p);

    transpose_kernel<<<nblk_tr, 256>>>(x2p, xtp);
    knn_t_kernel<<<nblk_knn, 256>>>(xtp, idxp);
    base_kernel<64><<<nblk_base, 256>>>(x2p, c3w1, c3b1, basep);
    edgeconv_kernel<64><<<nblk_ec, 256, ec_smem(64)>>>(x2p, idxp, basep, c3w1, c3w2, c3b2, x3p);

    mlp_kernel<<<128, 512, MLP_SMEM>>>(x1p, x2p, x3p, mw1, mb1, mw2, mb2,
                                       mw3, mb3, mw4, mb4, outp);
}

// round 8
// speedup vs baseline: 1.9981x; 1.1621x over previous
#include <cuda_runtime.h>
#include <math.h>
#include <float.h>

#define BATCH 64
#define NPTS  1024
#define KK    16
#define CH    64

// ---------------- scratch (static device globals; no allocation) ----------------
__device__ __align__(16) float g_x1[BATCH * NPTS * CH];
__device__ __align__(16) float g_x2[BATCH * NPTS * CH];
__device__ __align__(16) float g_x3[BATCH * NPTS * CH];
__device__ __align__(16) float g_xt[BATCH * NPTS * CH];   // transposed features
__device__ __align__(16) float g_base[BATCH * NPTS * CH];
__device__ int g_idx[BATCH * NPTS * KK];

// ---------------- warp top-16 selection (exact lex (value, index) order) --------
// Bitonic sort of 32 (value,index) pairs across lanes, ascending lexicographic.
// Indices are unique -> strict total order, no tie ambiguity.
__device__ __forceinline__ void bitonic32(float& sv, int& si, int lane) {
#pragma unroll
    for (int size = 2; size <= 32; size <<= 1) {
#pragma unroll
        for (int stride = size >> 1; stride > 0; stride >>= 1) {
            float ov = __shfl_xor_sync(0xffffffffu, sv, stride);
            int oi = __shfl_xor_sync(0xffffffffu, si, stride);
            bool dirDesc = (lane & size) != 0;
            bool iAmLower = (lane & stride) == 0;
            bool wantSmaller = iAmLower != dirDesc;
            bool otherLess = (ov < sv) || (ov == sv && oi < si);
            if (wantSmaller == otherLess) { sv = ov; si = oi; }
        }
    }
}

// row: this warp's NPTS distance row in smem (may be clobbered).
// Selects the 16 lexicographically-smallest (value,index) pairs; writes their
// indices (set equal to lax.top_k's set; order unimportant downstream).
__device__ __forceinline__ void warp_select16(float* row, int lane,
                                              int* __restrict__ outp) {
    float v[32];
#pragma unroll
    for (int r = 0; r < 32; r++) v[r] = row[lane + 32 * r];

    // lane-local lex argmin (ascending r + strict < => smallest index kept)
    float lv = v[0];
    int li = lane;
#pragma unroll
    for (int r = 1; r < 32; r++) {
        if (v[r] < lv) { lv = v[r]; li = lane + 32 * r; }
    }
    // sort the 32 lane minima; 16th smallest is a bound for all top-16 elements
    float sv = lv; int si = li;
    bitonic32(sv, si, lane);
    float Tv = __shfl_sync(0xffffffffu, sv, 15);
    int   Ti = __shfl_sync(0xffffffffu, si, 15);

    // count candidates lex-<= T
    int cnt = 0;
#pragma unroll
    for (int r = 0; r < 32; r++) {
        int idx = lane + 32 * r;
        bool le = (v[r] < Tv) || (v[r] == Tv && idx <= Ti);
        cnt += le ? 1 : 0;
    }
    int total = __reduce_add_sync(0xffffffffu, cnt);

    if (total <= 32) {
        // exclusive prefix over lane counts
        int pre = cnt;
#pragma unroll
        for (int o = 1; o < 32; o <<= 1) {
            int n = __shfl_up_sync(0xffffffffu, pre, o);
            if (lane >= o) pre += n;
        }
        pre -= cnt;
        // compact candidates into the (now reusable) head of the row
        float* candV = row;
        int* candI = (int*)(row + 32);
        int off = pre;
#pragma unroll
        for (int r = 0; r < 32; r++) {
            int idx = lane + 32 * r;
            bool le = (v[r] < Tv) || (v[r] == Tv && idx <= Ti);
            if (le) { candV[off] = v[r]; candI[off] = idx; off++; }
        }
        __syncwarp();
        float cv = FLT_MAX;
        int ci = 0x7FFFFFFF;
        if (lane < total) { cv = candV[lane]; ci = candI[lane]; }
        bitonic32(cv, ci, lane);
        if (lane < KK) outp[lane] = ci;
    } else {
        // rare fallback: exact 16-round argmin loop (original path)
        for (int k = 0; k < KK; k++) {
            float bv = v[0];
            int br = 0;
#pragma unroll
            for (int r = 1; r < 32; r++) {
                if (v[r] < bv) { bv = v[r]; br = r; }
            }
            int bi = lane + 32 * br;
#pragma unroll
            for (int o = 16; o > 0; o >>= 1) {
                float ov = __shfl_xor_sync(0xffffffffu, bv, o);
                int oi = __shfl_xor_sync(0xffffffffu, bi, o);
                if (ov < bv || (ov == bv && oi < bi)) { bv = ov; bi = oi; }
            }
            if (lane == 0) outp[k] = bi;
            if ((bi & 31) == lane) {
                int rr = bi >> 5;
#pragma unroll
                for (int r = 0; r < 32; r++)
                    if (r == rr) v[r] = FLT_MAX;
            }
        }
    }
}

// ---------------- kNN (D=1): row-major distance + fast selection ----------------
template <int D>
__global__ void __launch_bounds__(256) knn_kernel(const float* __restrict__ feat,
                                                  int* __restrict__ idx_out) {
    constexpr int PB = 8;
    __shared__ __align__(16) float dist[PB][NPTS];
    __shared__ __align__(16) float xis[PB][(D < 4) ? 4 : D];
    __shared__ float sqi[PB];

    const int tid = threadIdx.x;
    const int gbase = blockIdx.x * PB;
    const int b = gbase / NPTS;
    const int i0 = gbase % NPTS;
    const float* fb = feat + (size_t)b * NPTS * D;

    for (int t = tid; t < PB * D; t += 256) {
        int p = t / D, c = t % D;
        xis[p][c] = fb[(i0 + p) * D + c];
    }
    __syncthreads();
    if (tid < PB) {
        float s = 0.f;
        for (int c = 0; c < D; c++) s += xis[tid][c] * xis[tid][c];
        sqi[tid] = s;
    }
    __syncthreads();

    for (int j = tid; j < NPTS; j += 256) {
        const float* fj = fb + (size_t)j * D;
        float sqj = 0.f;
        float dot[PB];
#pragma unroll
        for (int p = 0; p < PB; p++) dot[p] = 0.f;
        for (int c = 0; c < D; c++) {
            float v = fj[c];
            sqj += v * v;
#pragma unroll
            for (int p = 0; p < PB; p++) dot[p] += v * xis[p][c];
        }
#pragma unroll
        for (int p = 0; p < PB; p++) dist[p][j] = sqi[p] + sqj - 2.f * dot[p];
    }
    __syncthreads();

    const int g = tid >> 5, lane = tid & 31;
    warp_select16(dist[g], lane, &idx_out[((size_t)(b * NPTS + i0 + g)) * KK]);
}

// ---------------- transpose: [NPTS, CH] -> [CH, NPTS] per batch ------------------
__global__ void __launch_bounds__(256) transpose_kernel(const float* __restrict__ feat,
                                                        float* __restrict__ featT) {
    __shared__ float tile[64 * 65];
    const int tid = threadIdx.x;
    const int bpB = NPTS / 64;
    const int b = blockIdx.x / bpB;
    const int row0 = (blockIdx.x % bpB) * 64;
    const float* fb = feat + ((size_t)b * NPTS + row0) * CH;
    for (int t = tid; t < 64 * 64; t += 256) {
        int r = t >> 6, c = t & 63;
        tile[c * 65 + r] = fb[r * CH + c];
    }
    __syncthreads();
    float* ob = featT + (size_t)b * CH * NPTS + row0;
    for (int t = tid; t < 64 * 64; t += 256) {
        int c = t >> 6, r = t & 63;
        ob[(size_t)c * NPTS + r] = tile[c * 65 + r];
    }
}

// ---------------- kNN (CH=64) on transposed features: coalesced loads -----------
__global__ void __launch_bounds__(256, 4) knn_t_kernel(const float* __restrict__ featT,
                                                       int* __restrict__ idx_out) {
    constexpr int PB = 8;
    __shared__ __align__(16) float dist[PB][NPTS];
    __shared__ __align__(16) float xqT[CH * PB];
    __shared__ float sqi[PB];

    const int tid = threadIdx.x;
    const int gbase = blockIdx.x * PB;
    const int b = gbase / NPTS;
    const int i0 = gbase % NPTS;
    const float* ftb = featT + (size_t)b * CH * NPTS;

    for (int t = tid; t < CH * PB; t += 256) {
        int c = t >> 3, p = t & 7;
        xqT[t] = ftb[(size_t)c * NPTS + i0 + p];
    }
    __syncthreads();
    if (tid < PB) {
        float s = 0.f;
        for (int c = 0; c < CH; c++) { float q = xqT[c * 8 + tid]; s = fmaf(q, q, s); }
        sqi[tid] = s;
    }
    __syncthreads();

    const float4* ft4 = (const float4*)ftb;
    float dot[PB][4];
    float sqj[4];
#pragma unroll
    for (int p = 0; p < PB; p++)
#pragma unroll
        for (int jj = 0; jj < 4; jj++) dot[p][jj] = 0.f;
#pragma unroll
    for (int jj = 0; jj < 4; jj++) sqj[jj] = 0.f;

    for (int c = 0; c < CH; c++) {
        float4 v = ft4[c * (NPTS / 4) + tid];
        sqj[0] = fmaf(v.x, v.x, sqj[0]);
        sqj[1] = fmaf(v.y, v.y, sqj[1]);
        sqj[2] = fmaf(v.z, v.z, sqj[2]);
        sqj[3] = fmaf(v.w, v.w, sqj[3]);
        float4 q0 = *(const float4*)&xqT[c * 8];
        float4 q1 = *(const float4*)&xqT[c * 8 + 4];
        float q[8] = {q0.x, q0.y, q0.z, q0.w, q1.x, q1.y, q1.z, q1.w};
#pragma unroll
        for (int p = 0; p < PB; p++) {
            dot[p][0] = fmaf(v.x, q[p], dot[p][0]);
            dot[p][1] = fmaf(v.y, q[p], dot[p][1]);
            dot[p][2] = fmaf(v.z, q[p], dot[p][2]);
            dot[p][3] = fmaf(v.w, q[p], dot[p][3]);
        }
    }
    const int j0 = tid * 4;
#pragma unroll
    for (int p = 0; p < PB; p++) {
        float4 dv;
        dv.x = sqi[p] + sqj[0] - 2.f * dot[p][0];
        dv.y = sqi[p] + sqj[1] - 2.f * dot[p][1];
        dv.z = sqi[p] + sqj[2] - 2.f * dot[p][2];
        dv.w = sqi[p] + sqj[3] - 2.f * dot[p][3];
        *(float4*)&dist[p][j0] = dv;
    }
    __syncthreads();

    const int g = tid >> 5, lane = tid & 31;
    warp_select16(dist[g], lane, &idx_out[((size_t)(b * NPTS + i0 + g)) * KK]);
}

// ---------------- base precompute: base = b1 + x_i * (w1[:D,:] - w1[D:,:]) ------
template <int D>
__global__ void __launch_bounds__(256) base_kernel(
    const float* __restrict__ feat, const float* __restrict__ w1,
    const float* __restrict__ b1, float* __restrict__ baseo) {
    __shared__ float wdfs[D * CH];
    __shared__ float b1s[CH];
    const int tid = threadIdx.x, p = tid >> 5, lane = tid & 31;
    for (int t = tid; t < D * CH; t += 256) wdfs[t] = w1[t] - w1[D * CH + t];
    if (tid < CH) b1s[tid] = b1[tid];
    __syncthreads();
    const int k0 = 2 * lane;
    for (int g = 0; g < 8; g++) {
        int i = blockIdx.x * 64 + g * 8 + p;
        const float* fx = feat + (size_t)i * D;
        float bx = b1s[k0], by = b1s[k0 + 1];
        if constexpr (D == 1) {
            float xv = fx[0];
            float2 wd = *(const float2*)&wdfs[k0];
            bx = fmaf(xv, wd.x, bx);
            by = fmaf(xv, wd.y, by);
        } else {
            float xr[D / 32];
#pragma unroll
            for (int h = 0; h < D / 32; h++) xr[h] = fx[h * 32 + lane];
#pragma unroll
            for (int h = 0; h < D / 32; h++) {
                for (int j = 0; j < 32; j++) {
                    float xv = __shfl_sync(0xffffffffu, xr[h], j);
                    float2 wd = *(const float2*)&wdfs[(h * 32 + j) * CH + k0];
                    bx = fmaf(xv, wd.x, bx);
                    by = fmaf(xv, wd.y, by);
                }
            }
        }
        *(float2*)&baseo[(size_t)i * CH + k0] = make_float2(bx, by);
    }
}

// ---------------- EdgeConv: relu(e@w1+b1)@w2+b2, max over K ---------------------
template <int D>
__global__ void __launch_bounds__(256, 3) edgeconv_kernel(
    const float* __restrict__ feat, const int* __restrict__ idx,
    const float* __restrict__ basep,
    const float* __restrict__ w1, const float* __restrict__ w2,
    const float* __restrict__ b2, float* __restrict__ out) {
    constexpr int PTS = 8;
    constexpr int NB = 8;
    constexpr int GROUPS = 4;
    constexpr int Dp = (D + 3) & ~3;
    extern __shared__ float s[];
    float* w1bs = s;
    float* w2s  = w1bs + D * CH;
    float* b2s  = w2s + CH * CH;
    float* xjs  = b2s + CH;
    float* h1c  = xjs + PTS * NB * Dp;
    int* nbr    = (int*)(h1c + PTS * NB * CH);

    const int tid = threadIdx.x;
    const int p = tid >> 5, lane = tid & 31;

    for (int t = tid; t < D * CH; t += 256) w1bs[t] = w1[D * CH + t];
    for (int t = tid; t < CH * CH; t += 256) w2s[t] = w2[t];
    if (tid < CH) b2s[tid] = b2[tid];
    __syncthreads();

    const int k0 = 2 * lane;

    for (int grp = 0; grp < GROUPS; grp++) {
        const int gbase = blockIdx.x * (PTS * GROUPS) + grp * PTS;
        const int b = gbase / NPTS;
        const int i = (gbase % NPTS) + p;
        const int gi = b * NPTS + i;
        const float* fb = feat + (size_t)b * NPTS * D;

        if (lane < KK) nbr[p * KK + lane] = idx[(size_t)gi * KK + lane];
        __syncwarp();

        float2 bse = *(const float2*)&basep[(size_t)gi * CH + k0];
        float bx = bse.x, by = bse.y;
        float mx = -FLT_MAX, my = -FLT_MAX;

        for (int c0 = 0; c0 < KK; c0 += NB) {
            if constexpr (D % 4 == 0) {
                for (int t = lane; t < NB * (D / 4); t += 32) {
                    int nb = t / (D / 4), c4 = t % (D / 4);
                    float4 vv = *(const float4*)(fb +
                        (size_t)nbr[p * KK + c0 + nb] * D + 4 * c4);
                    *(float4*)&xjs[p * NB * D + nb * D + 4 * c4] = vv;
                }
            } else {
                for (int t = lane; t < NB * D; t += 32) {
                    int nb = t / D, c = t % D;
                    xjs[p * NB * D + t] = fb[(size_t)nbr[p * KK + c0 + nb] * D + c];
                }
            }
            __syncwarp();

            float2 acc[NB];
#pragma unroll
            for (int nb = 0; nb < NB; nb++) acc[nb] = make_float2(0.f, 0.f);

            if constexpr (D % 4 == 0) {
                const float* xbase = &xjs[p * NB * D];
                for (int j = 0; j < D; j += 4) {
                    const float* wb = &w1bs[j * CH + k0];
                    float2 wv0 = *(const float2*)(wb);
                    float2 wv1 = *(const float2*)(wb + CH);
                    float2 wv2 = *(const float2*)(wb + 2 * CH);
                    float2 wv3 = *(const float2*)(wb + 3 * CH);
#pragma unroll
                    for (int nb = 0; nb < NB; nb++) {
                        float4 xv = *(const float4*)(xbase + nb * D + j);
                        acc[nb].x = fmaf(xv.x, wv0.x, acc[nb].x);
                        acc[nb].y = fmaf(xv.x, wv0.y, acc[nb].y);
                        acc[nb].x = fmaf(xv.y, wv1.x, acc[nb].x);
                        acc[nb].y = fmaf(xv.y, wv1.y, acc[nb].y);
                        acc[nb].x = fmaf(xv.z, wv2.x, acc[nb].x);
                        acc[nb].y = fmaf(xv.z, wv2.y, acc[nb].y);
                        acc[nb].x = fmaf(xv.w, wv3.x, acc[nb].x);
                        acc[nb].y = fmaf(xv.w, wv3.y, acc[nb].y);
                    }
                }
            } else {
                for (int j = 0; j < D; j++) {
                    float2 w = *(const float2*)&w1bs[j * CH + k0];
                    const float* xr = &xjs[p * NB * D + j];
#pragma unroll
                    for (int nb = 0; nb < NB; nb++) {
                        float xj = xr[nb * D];
                        acc[nb].x = fmaf(xj, w.x, acc[nb].x);
                        acc[nb].y = fmaf(xj, w.y, acc[nb].y);
                    }
                }
            }
#pragma unroll
            for (int nb = 0; nb < NB; nb++) {
                float2 h;
                h.x = fmaxf(bx + acc[nb].x, 0.f);
                h.y = fmaxf(by + acc[nb].y, 0.f);
                *(float2*)&h1c[(p * NB + nb) * CH + k0] = h;
            }
            __syncwarp();

#pragma unroll
            for (int nb = 0; nb < NB; nb++) acc[nb] = make_float2(0.f, 0.f);
            const float* hbase = &h1c[p * NB * CH];
            for (int j = 0; j < CH; j += 4) {
                const float* wb = &w2s[j * CH + k0];
                float2 wv0 = *(const float2*)(wb);
                float2 wv1 = *(const float2*)(wb + CH);
                float2 wv2 = *(const float2*)(wb + 2 * CH);
                float2 wv3 = *(const float2*)(wb + 3 * CH);
#pragma unroll
                for (int nb = 0; nb < NB; nb++) {
                    float4 hv = *(const float4*)(hbase + nb * CH + j);
                    acc[nb].x = fmaf(hv.x, wv0.x, acc[nb].x);
                    acc[nb].y = fmaf(hv.x, wv0.y, acc[nb].y);
                    acc[nb].x = fmaf(hv.y, wv1.x, acc[nb].x);
                    acc[nb].y = fmaf(hv.y, wv1.y, acc[nb].y);
                    acc[nb].x = fmaf(hv.z, wv2.x, acc[nb].x);
                    acc[nb].y = fmaf(hv.z, wv2.y, acc[nb].y);
                    acc[nb].x = fmaf(hv.w, wv3.x, acc[nb].x);
                    acc[nb].y = fmaf(hv.w, wv3.y, acc[nb].y);
                }
            }
#pragma unroll
            for (int nb = 0; nb < NB; nb++) {
                mx = fmaxf(mx, acc[nb].x);
                my = fmaxf(my, acc[nb].y);
            }
            __syncwarp();
        }

        size_t ob = (size_t)gi * CH;
        out[ob + k0]     = mx + b2s[k0];
        out[ob + k0 + 1] = my + b2s[k0 + 1];
    }
}

// ---------------- final MLP: 192 -> 128 -> 64 -> 32 -> 2, log_softmax ------------
__global__ void __launch_bounds__(512) mlp_kernel(
    const float* __restrict__ x1, const float* __restrict__ x2,
    const float* __restrict__ x3,
    const float* __restrict__ mw1, const float* __restrict__ mb1,
    const float* __restrict__ mw2, const float* __restrict__ mb2,
    const float* __restrict__ mw3, const float* __restrict__ mb3,
    const float* __restrict__ mw4, const float* __restrict__ mb4,
    float* __restrict__ out) {
    extern __shared__ float s[];
    float* w1s = s;
    float* w2s = w1s + 24576;
    float* w3s = w2s + 8192;
    float* w4s = w3s + 2048;
    float* b1s = w4s + 64;
    float* b2s = b1s + 128;
    float* b3s = b2s + 64;
    float* b4s = b3s + 32;
    float* fbuf = b4s + 4;
    float* hbuf = fbuf + 16 * 192;

    const int tid = threadIdx.x;
    const int w = tid >> 5, lane = tid & 31;
    for (int t = tid; t < 24576; t += 512) w1s[t] = mw1[t];
    for (int t = tid; t < 8192; t += 512) w2s[t] = mw2[t];
    for (int t = tid; t < 2048; t += 512) w3s[t] = mw3[t];
    if (tid < 64) w4s[tid] = mw4[tid];
    if (tid < 128) b1s[tid] = mb1[tid];
    if (tid < 64) b2s[tid] = mb2[tid];
    if (tid < 32) b3s[tid] = mb3[tid];
    if (tid < 2) b4s[tid] = mb4[tid];
    __syncthreads();

    const int ptsPerBlock = (BATCH * NPTS) / gridDim.x;
    const int pbase = blockIdx.x * ptsPerBlock;
    float* f = fbuf + w * 192;
    float* h = hbuf + w * 128;

    for (int pt = pbase + w; pt < pbase + ptsPerBlock; pt += 16) {
        for (int t = lane; t < 64; t += 32) {
            f[t]       = x1[(size_t)pt * 64 + t];
            f[64 + t]  = x2[(size_t)pt * 64 + t];
            f[128 + t] = x3[(size_t)pt * 64 + t];
        }
        __syncwarp();
        float4 a1 = *(const float4*)&b1s[4 * lane];
        for (int j = 0; j < 192; j += 4) {
            float4 xv = *(const float4*)&f[j];
            const float* wb = &w1s[j * 128 + 4 * lane];
            float4 w0 = *(const float4*)(wb);
            float4 w1v = *(const float4*)(wb + 128);
            float4 w2v = *(const float4*)(wb + 256);
            float4 w3v = *(const float4*)(wb + 384);
            a1.x = fmaf(xv.x, w0.x, a1.x); a1.y = fmaf(xv.x, w0.y, a1.y);
            a1.z = fmaf(xv.x, w0.z, a1.z); a1.w = fmaf(xv.x, w0.w, a1.w);
            a1.x = fmaf(xv.y, w1v.x, a1.x); a1.y = fmaf(xv.y, w1v.y, a1.y);
            a1.z = fmaf(xv.y, w1v.z, a1.z); a1.w = fmaf(xv.y, w1v.w, a1.w);
            a1.x = fmaf(xv.z, w2v.x, a1.x); a1.y = fmaf(xv.z, w2v.y, a1.y);
            a1.z = fmaf(xv.z, w2v.z, a1.z); a1.w = fmaf(xv.z, w2v.w, a1.w);
            a1.x = fmaf(xv.w, w3v.x, a1.x); a1.y = fmaf(xv.w, w3v.y, a1.y);
            a1.z = fmaf(xv.w, w3v.z, a1.z); a1.w = fmaf(xv.w, w3v.w, a1.w);
        }
        h[4 * lane]     = fmaxf(a1.x, 0.f);
        h[4 * lane + 1] = fmaxf(a1.y, 0.f);
        h[4 * lane + 2] = fmaxf(a1.z, 0.f);
        h[4 * lane + 3] = fmaxf(a1.w, 0.f);
        __syncwarp();
        float2 a2 = *(const float2*)&b2s[2 * lane];
        for (int j = 0; j < 128; j += 4) {
            float4 hv = *(const float4*)&h[j];
            const float* wb = &w2s[j * 64 + 2 * lane];
            float2 w0 = *(const float2*)(wb);
            float2 w1v = *(const float2*)(wb + 64);
            float2 w2v = *(const float2*)(wb + 128);
            float2 w3v = *(const float2*)(wb + 192);
            a2.x = fmaf(hv.x, w0.x, a2.x); a2.y = fmaf(hv.x, w0.y, a2.y);
            a2.x = fmaf(hv.y, w1v.x, a2.x); a2.y = fmaf(hv.y, w1v.y, a2.y);
            a2.x = fmaf(hv.z, w2v.x, a2.x); a2.y = fmaf(hv.z, w2v.y, a2.y);
            a2.x = fmaf(hv.w, w3v.x, a2.x); a2.y = fmaf(hv.w, w3v.y, a2.y);
        }
        __syncwarp();
        f[2 * lane]     = fmaxf(a2.x, 0.f);
        f[2 * lane + 1] = fmaxf(a2.y, 0.f);
        __syncwarp();
        float a3 = b3s[lane];
        for (int j = 0; j < 64; j++) a3 = fmaf(f[j], w3s[j * 32 + lane], a3);
        a3 = fmaxf(a3, 0.f);
        __syncwarp();
        h[lane] = a3;
        __syncwarp();
        float o = 0.f;
        if (lane < 2) {
            o = b4s[lane];
            for (int j = 0; j < 32; j++) o = fmaf(h[j], w4s[j * 2 + lane], o);
        }
        float oo = __shfl_xor_sync(0xffffffffu, o, 1);
        if (lane < 2) {
            float mm = fmaxf(o, oo);
            float lse = mm + logf(expf(o - mm) + expf(oo - mm));
            out[(size_t)pt * 2 + lane] = o - lse;
        }
        __syncwarp();
    }
}

// ---------------- launch -------------------------------------------------------
static constexpr size_t ec_smem(int D) {
    int Dp = (D + 3) & ~3;
    return (size_t)(D * CH + CH * CH + CH + 8 * 8 * Dp + 8 * 8 * CH + 8 * KK) * 4;
}
static constexpr size_t MLP_SMEM =
    (size_t)(24576 + 8192 + 2048 + 64 + 128 + 64 + 32 + 4 + 16 * 192 + 16 * 128) * 4;

extern "C" void kernel_launch(void* const* d_in, const int* in_sizes, int n_in,
                              void* d_out, int out_size) {
    (void)in_sizes; (void)n_in; (void)out_size;
    const float* x    = (const float*)d_in[0];
    const float* c1w1 = (const float*)d_in[1];
    const float* c1b1 = (const float*)d_in[2];
    const float* c1w2 = (const float*)d_in[3];
    const float* c1b2 = (const float*)d_in[4];
    const float* c2w1 = (const float*)d_in[5];
    const float* c2b1 = (const float*)d_in[6];
    const float* c2w2 = (const float*)d_in[7];
    const float* c2b2 = (const float*)d_in[8];
    const float* c3w1 = (const float*)d_in[9];
    const float* c3b1 = (const float*)d_in[10];
    const float* c3w2 = (const float*)d_in[11];
    const float* c3b2 = (const float*)d_in[12];
    const float* mw1  = (const float*)d_in[13];
    const float* mb1  = (const float*)d_in[14];
    const float* mw2  = (const float*)d_in[15];
    const float* mb2  = (const float*)d_in[16];
    const float* mw3  = (const float*)d_in[17];
    const float* mb3  = (const float*)d_in[18];
    const float* mw4  = (const float*)d_in[19];
    const float* mb4  = (const float*)d_in[20];
    float* outp = (float*)d_out;

    float *x1p, *x2p, *x3p, *xtp, *basep;
    int* idxp;
    cudaGetSymbolAddress((void**)&x1p, g_x1);
    cudaGetSymbolAddress((void**)&x2p, g_x2);
    cudaGetSymbolAddress((void**)&x3p, g_x3);
    cudaGetSymbolAddress((void**)&xtp, g_xt);
    cudaGetSymbolAddress((void**)&basep, g_base);
    cudaGetSymbolAddress((void**)&idxp, g_idx);

    cudaFuncSetAttribute(edgeconv_kernel<1>,
                         cudaFuncAttributeMaxDynamicSharedMemorySize, (int)ec_smem(1));
    cudaFuncSetAttribute(edgeconv_kernel<64>,
                         cudaFuncAttributeMaxDynamicSharedMemorySize, (int)ec_smem(64));
    cudaFuncSetAttribute(mlp_kernel,
                         cudaFuncAttributeMaxDynamicSharedMemorySize, (int)MLP_SMEM);

    const int nblk_knn  = BATCH * NPTS / 8;   // 8192
    const int nblk_ec   = BATCH * NPTS / 32;  // 2048
    const int nblk_base = BATCH * NPTS / 64;  // 1024
    const int nblk_tr   = BATCH * (NPTS / 64);// 1024

    knn_kernel<1><<<nblk_knn, 256>>>(x, idxp);
    base_kernel<1><<<nblk_base, 256>>>(x, c1w1, c1b1, basep);
    edgeconv_kernel<1><<<nblk_ec, 256, ec_smem(1)>>>(x, idxp, basep, c1w1, c1w2, c1b2, x1p);

    transpose_kernel<<<nblk_tr, 256>>>(x1p, xtp);
    knn_t_kernel<<<nblk_knn, 256>>>(xtp, idxp);
    base_kernel<64><<<nblk_base, 256>>>(x1p, c2w1, c2b1, basep);
    edgeconv_kernel<64><<<nblk_ec, 256, ec_smem(64)>>>(x1p, idxp, basep, c2w1, c2w2, c2b2, x2p);

    transpose_kernel<<<nblk_tr, 256>>>(x2p, xtp);
    knn_t_kernel<<<nblk_knn, 256>>>(xtp, idxp);
    base_kernel<64><<<nblk_base, 256>>>(x2p, c3w1, c3b1, basep);
    edgeconv_kernel<64><<<nblk_ec, 256, ec_smem(64)>>>(x2p, idxp, basep, c3w1, c3w2, c3b2, x3p);

    mlp_kernel<<<128, 512, MLP_SMEM>>>(x1p, x2p, x3p, mw1, mb1, mw2, mb2,
                                       mw3, mb3, mw4, mb4, outp);
}

// round 9
// speedup vs baseline: 2.3650x; 1.1836x over previous
#include <cuda_runtime.h>
#include <math.h>
#include <float.h>

#define BATCH 64
#define NPTS  1024
#define KK    16
#define CH    64

// ---------------- scratch (static device globals; no allocation) ----------------
__device__ __align__(16) float g_x1[BATCH * NPTS * CH];
__device__ __align__(16) float g_x2[BATCH * NPTS * CH];
__device__ __align__(16) float g_x3[BATCH * NPTS * CH];
__device__ __align__(16) float g_xt[BATCH * NPTS * CH];   // transposed features
__device__ __align__(16) float g_base[BATCH * NPTS * CH]; // b1 + x@w1a - x@w1b
__device__ __align__(16) float g_y[BATCH * NPTS * CH];    // x@w1b
__device__ int g_idx[BATCH * NPTS * KK];

// ---------------- warp top-16 selection (exact lex (value, index) order) --------
__device__ __forceinline__ void bitonic32(float& sv, int& si, int lane) {
#pragma unroll
    for (int size = 2; size <= 32; size <<= 1) {
#pragma unroll
        for (int stride = size >> 1; stride > 0; stride >>= 1) {
            float ov = __shfl_xor_sync(0xffffffffu, sv, stride);
            int oi = __shfl_xor_sync(0xffffffffu, si, stride);
            bool dirDesc = (lane & size) != 0;
            bool iAmLower = (lane & stride) == 0;
            bool wantSmaller = iAmLower != dirDesc;
            bool otherLess = (ov < sv) || (ov == sv && oi < si);
            if (wantSmaller == otherLess) { sv = ov; si = oi; }
        }
    }
}

__device__ __forceinline__ void warp_select16(float* row, int lane,
                                              int* __restrict__ outp) {
    float v[32];
#pragma unroll
    for (int r = 0; r < 32; r++) v[r] = row[lane + 32 * r];

    float lv = v[0];
    int li = lane;
#pragma unroll
    for (int r = 1; r < 32; r++) {
        if (v[r] < lv) { lv = v[r]; li = lane + 32 * r; }
    }
    float sv = lv; int si = li;
    bitonic32(sv, si, lane);
    float Tv = __shfl_sync(0xffffffffu, sv, 15);
    int   Ti = __shfl_sync(0xffffffffu, si, 15);

    int cnt = 0;
#pragma unroll
    for (int r = 0; r < 32; r++) {
        int idx = lane + 32 * r;
        bool le = (v[r] < Tv) || (v[r] == Tv && idx <= Ti);
        cnt += le ? 1 : 0;
    }
    int total = __reduce_add_sync(0xffffffffu, cnt);

    if (total <= 32) {
        int pre = cnt;
#pragma unroll
        for (int o = 1; o < 32; o <<= 1) {
            int n = __shfl_up_sync(0xffffffffu, pre, o);
            if (lane >= o) pre += n;
        }
        pre -= cnt;
        float* candV = row;
        int* candI = (int*)(row + 32);
        int off = pre;
#pragma unroll
        for (int r = 0; r < 32; r++) {
            int idx = lane + 32 * r;
            bool le = (v[r] < Tv) || (v[r] == Tv && idx <= Ti);
            if (le) { candV[off] = v[r]; candI[off] = idx; off++; }
        }
        __syncwarp();
        float cv = FLT_MAX;
        int ci = 0x7FFFFFFF;
        if (lane < total) { cv = candV[lane]; ci = candI[lane]; }
        bitonic32(cv, ci, lane);
        if (lane < KK) outp[lane] = ci;
    } else {
        for (int k = 0; k < KK; k++) {
            float bv = v[0];
            int br = 0;
#pragma unroll
            for (int r = 1; r < 32; r++) {
                if (v[r] < bv) { bv = v[r]; br = r; }
            }
            int bi = lane + 32 * br;
#pragma unroll
            for (int o = 16; o > 0; o >>= 1) {
                float ov = __shfl_xor_sync(0xffffffffu, bv, o);
                int oi = __shfl_xor_sync(0xffffffffu, bi, o);
                if (ov < bv || (ov == bv && oi < bi)) { bv = ov; bi = oi; }
            }
            if (lane == 0) outp[k] = bi;
            if ((bi & 31) == lane) {
                int rr = bi >> 5;
#pragma unroll
                for (int r = 0; r < 32; r++)
                    if (r == rr) v[r] = FLT_MAX;
            }
        }
    }
}

// ---------------- kNN (D=1): row-major distance + fast selection ----------------
template <int D>
__global__ void __launch_bounds__(256) knn_kernel(const float* __restrict__ feat,
                                                  int* __restrict__ idx_out) {
    constexpr int PB = 8;
    __shared__ __align__(16) float dist[PB][NPTS];
    __shared__ __align__(16) float xis[PB][(D < 4) ? 4 : D];
    __shared__ float sqi[PB];

    const int tid = threadIdx.x;
    const int gbase = blockIdx.x * PB;
    const int b = gbase / NPTS;
    const int i0 = gbase % NPTS;
    const float* fb = feat + (size_t)b * NPTS * D;

    for (int t = tid; t < PB * D; t += 256) {
        int p = t / D, c = t % D;
        xis[p][c] = fb[(i0 + p) * D + c];
    }
    __syncthreads();
    if (tid < PB) {
        float s = 0.f;
        for (int c = 0; c < D; c++) s += xis[tid][c] * xis[tid][c];
        sqi[tid] = s;
    }
    __syncthreads();

    for (int j = tid; j < NPTS; j += 256) {
        const float* fj = fb + (size_t)j * D;
        float sqj = 0.f;
        float dot[PB];
#pragma unroll
        for (int p = 0; p < PB; p++) dot[p] = 0.f;
        for (int c = 0; c < D; c++) {
            float v = fj[c];
            sqj += v * v;
#pragma unroll
            for (int p = 0; p < PB; p++) dot[p] += v * xis[p][c];
        }
#pragma unroll
        for (int p = 0; p < PB; p++) dist[p][j] = sqi[p] + sqj - 2.f * dot[p];
    }
    __syncthreads();

    const int g = tid >> 5, lane = tid & 31;
    warp_select16(dist[g], lane, &idx_out[((size_t)(b * NPTS + i0 + g)) * KK]);
}

// ---------------- transpose: [NPTS, CH] -> [CH, NPTS] per batch ------------------
__global__ void __launch_bounds__(256) transpose_kernel(const float* __restrict__ feat,
                                                        float* __restrict__ featT) {
    __shared__ float tile[64 * 65];
    const int tid = threadIdx.x;
    const int bpB = NPTS / 64;
    const int b = blockIdx.x / bpB;
    const int row0 = (blockIdx.x % bpB) * 64;
    const float* fb = feat + ((size_t)b * NPTS + row0) * CH;
    for (int t = tid; t < 64 * 64; t += 256) {
        int r = t >> 6, c = t & 63;
        tile[c * 65 + r] = fb[r * CH + c];
    }
    __syncthreads();
    float* ob = featT + (size_t)b * CH * NPTS + row0;
    for (int t = tid; t < 64 * 64; t += 256) {
        int c = t >> 6, r = t & 63;
        ob[(size_t)c * NPTS + r] = tile[c * 65 + r];
    }
}

// ---------------- kNN (CH=64) on transposed features: coalesced loads -----------
__global__ void __launch_bounds__(256, 4) knn_t_kernel(const float* __restrict__ featT,
                                                       int* __restrict__ idx_out) {
    constexpr int PB = 8;
    __shared__ __align__(16) float dist[PB][NPTS];
    __shared__ __align__(16) float xqT[CH * PB];
    __shared__ float sqi[PB];

    const int tid = threadIdx.x;
    const int gbase = blockIdx.x * PB;
    const int b = gbase / NPTS;
    const int i0 = gbase % NPTS;
    const float* ftb = featT + (size_t)b * CH * NPTS;

    for (int t = tid; t < CH * PB; t += 256) {
        int c = t >> 3, p = t & 7;
        xqT[t] = ftb[(size_t)c * NPTS + i0 + p];
    }
    __syncthreads();
    if (tid < PB) {
        float s = 0.f;
        for (int c = 0; c < CH; c++) { float q = xqT[c * 8 + tid]; s = fmaf(q, q, s); }
        sqi[tid] = s;
    }
    __syncthreads();

    const float4* ft4 = (const float4*)ftb;
    float dot[PB][4];
    float sqj[4];
#pragma unroll
    for (int p = 0; p < PB; p++)
#pragma unroll
        for (int jj = 0; jj < 4; jj++) dot[p][jj] = 0.f;
#pragma unroll
    for (int jj = 0; jj < 4; jj++) sqj[jj] = 0.f;

    for (int c = 0; c < CH; c++) {
        float4 v = ft4[c * (NPTS / 4) + tid];
        sqj[0] = fmaf(v.x, v.x, sqj[0]);
        sqj[1] = fmaf(v.y, v.y, sqj[1]);
        sqj[2] = fmaf(v.z, v.z, sqj[2]);
        sqj[3] = fmaf(v.w, v.w, sqj[3]);
        float4 q0 = *(const float4*)&xqT[c * 8];
        float4 q1 = *(const float4*)&xqT[c * 8 + 4];
        float q[8] = {q0.x, q0.y, q0.z, q0.w, q1.x, q1.y, q1.z, q1.w};
#pragma unroll
        for (int p = 0; p < PB; p++) {
            dot[p][0] = fmaf(v.x, q[p], dot[p][0]);
            dot[p][1] = fmaf(v.y, q[p], dot[p][1]);
            dot[p][2] = fmaf(v.z, q[p], dot[p][2]);
            dot[p][3] = fmaf(v.w, q[p], dot[p][3]);
        }
    }
    const int j0 = tid * 4;
#pragma unroll
    for (int p = 0; p < PB; p++) {
        float4 dv;
        dv.x = sqi[p] + sqj[0] - 2.f * dot[p][0];
        dv.y = sqi[p] + sqj[1] - 2.f * dot[p][1];
        dv.z = sqi[p] + sqj[2] - 2.f * dot[p][2];
        dv.w = sqi[p] + sqj[3] - 2.f * dot[p][3];
        *(float4*)&dist[p][j0] = dv;
    }
    __syncthreads();

    const int g = tid >> 5, lane = tid & 31;
    warp_select16(dist[g], lane, &idx_out[((size_t)(b * NPTS + i0 + g)) * KK]);
}

// ---------------- Y/base precompute -------------------------------------------
// Y = x @ w1[D:, :]  (neighbor transform, shared by every edge that uses j)
// base = b1 + x @ w1[:D, :] - Y
template <int D>
__global__ void __launch_bounds__(256) yb_kernel(
    const float* __restrict__ feat, const float* __restrict__ w1,
    const float* __restrict__ b1, float* __restrict__ baseo,
    float* __restrict__ yo) {
    __shared__ float w1as[D * CH];
    __shared__ float w1bs[D * CH];
    __shared__ float b1s[CH];
    const int tid = threadIdx.x, p = tid >> 5, lane = tid & 31;
    for (int t = tid; t < D * CH; t += 256) {
        w1as[t] = w1[t];
        w1bs[t] = w1[D * CH + t];
    }
    if (tid < CH) b1s[tid] = b1[tid];
    __syncthreads();
    const int k0 = 2 * lane;
    for (int g = 0; g < 8; g++) {
        int i = blockIdx.x * 64 + g * 8 + p;
        const float* fx = feat + (size_t)i * D;
        float zx = 0.f, zy = 0.f, yx = 0.f, yy = 0.f;
        if constexpr (D == 1) {
            float xv = fx[0];
            float2 wa = *(const float2*)&w1as[k0];
            float2 wb = *(const float2*)&w1bs[k0];
            zx = xv * wa.x; zy = xv * wa.y;
            yx = xv * wb.x; yy = xv * wb.y;
        } else {
            float xr[D / 32];
#pragma unroll
            for (int h = 0; h < D / 32; h++) xr[h] = fx[h * 32 + lane];
#pragma unroll
            for (int h = 0; h < D / 32; h++) {
                for (int j = 0; j < 32; j++) {
                    float xv = __shfl_sync(0xffffffffu, xr[h], j);
                    float2 wa = *(const float2*)&w1as[(h * 32 + j) * CH + k0];
                    float2 wb = *(const float2*)&w1bs[(h * 32 + j) * CH + k0];
                    zx = fmaf(xv, wa.x, zx); zy = fmaf(xv, wa.y, zy);
                    yx = fmaf(xv, wb.x, yx); yy = fmaf(xv, wb.y, yy);
                }
            }
        }
        *(float2*)&baseo[(size_t)i * CH + k0] =
            make_float2(b1s[k0] + zx - yx, b1s[k0 + 1] + zy - yy);
        *(float2*)&yo[(size_t)i * CH + k0] = make_float2(yx, yy);
    }
}

// ---------------- EdgeConv: h1 = relu(base_i + Y_j); out = max_k h1@w2 + b2 -----
// Stage-1 GEMM eliminated (Y precomputed); D-independent. 4 blocks/SM.
__global__ void __launch_bounds__(256, 4) edgeconv_kernel(
    const int* __restrict__ idx, const float* __restrict__ basep,
    const float* __restrict__ yp, const float* __restrict__ w2,
    const float* __restrict__ b2, float* __restrict__ out) {
    constexpr int PTS = 8;     // warps per block
    constexpr int NB = 8;      // neighbor chunk
    constexpr int GROUPS = 4;  // sequential points per warp
    extern __shared__ float s[];
    float* w2s = s;                           // CH*CH
    float* b2s = w2s + CH * CH;               // CH
    float* ys  = b2s + CH;                    // PTS*NB*CH (gathered Y, relu'd in place)
    int* nbr   = (int*)(ys + PTS * NB * CH);  // PTS*KK

    const int tid = threadIdx.x;  // 256 = 8 warps
    const int p = tid >> 5, lane = tid & 31;

    for (int t = tid; t < CH * CH; t += 256) w2s[t] = w2[t];
    if (tid < CH) b2s[tid] = b2[tid];
    __syncthreads();

    const int k0 = 2 * lane;

    for (int grp = 0; grp < GROUPS; grp++) {
        const int gbase = blockIdx.x * (PTS * GROUPS) + grp * PTS;
        const int b = gbase / NPTS;
        const int i = (gbase % NPTS) + p;
        const int gi = b * NPTS + i;
        const float* yb = yp + (size_t)b * NPTS * CH;

        if (lane < KK) nbr[p * KK + lane] = idx[(size_t)gi * KK + lane];
        __syncwarp();

        float2 bse = *(const float2*)&basep[(size_t)gi * CH + k0];
        float bx = bse.x, by = bse.y;
        float mx = -FLT_MAX, my = -FLT_MAX;

        for (int c0 = 0; c0 < KK; c0 += NB) {
            // gather Y rows for this chunk (coalesced float4)
            for (int t = lane; t < NB * (CH / 4); t += 32) {
                int nb = t >> 4, c4 = t & 15;
                float4 vv = *(const float4*)(yb +
                    (size_t)nbr[p * KK + c0 + nb] * CH + 4 * c4);
                *(float4*)&ys[(p * NB + nb) * CH + 4 * c4] = vv;
            }
            __syncwarp();

            // h1 = relu(base + Y), in place (each lane owns its 2 channels)
#pragma unroll
            for (int nb = 0; nb < NB; nb++) {
                float2 h = *(const float2*)&ys[(p * NB + nb) * CH + k0];
                h.x = fmaxf(bx + h.x, 0.f);
                h.y = fmaxf(by + h.y, 0.f);
                *(float2*)&ys[(p * NB + nb) * CH + k0] = h;
            }
            __syncwarp();

            // stage 2: h1 @ w2
            float2 acc[NB];
#pragma unroll
            for (int nb = 0; nb < NB; nb++) acc[nb] = make_float2(0.f, 0.f);
            const float* hbase = &ys[p * NB * CH];
            for (int j = 0; j < CH; j += 4) {
                const float* wb = &w2s[j * CH + k0];
                float2 wv0 = *(const float2*)(wb);
                float2 wv1 = *(const float2*)(wb + CH);
                float2 wv2 = *(const float2*)(wb + 2 * CH);
                float2 wv3 = *(const float2*)(wb + 3 * CH);
#pragma unroll
                for (int nb = 0; nb < NB; nb++) {
                    float4 hv = *(const float4*)(hbase + nb * CH + j);
                    acc[nb].x = fmaf(hv.x, wv0.x, acc[nb].x);
                    acc[nb].y = fmaf(hv.x, wv0.y, acc[nb].y);
                    acc[nb].x = fmaf(hv.y, wv1.x, acc[nb].x);
                    acc[nb].y = fmaf(hv.y, wv1.y, acc[nb].y);
                    acc[nb].x = fmaf(hv.z, wv2.x, acc[nb].x);
                    acc[nb].y = fmaf(hv.z, wv2.y, acc[nb].y);
                    acc[nb].x = fmaf(hv.w, wv3.x, acc[nb].x);
                    acc[nb].y = fmaf(hv.w, wv3.y, acc[nb].y);
                }
            }
#pragma unroll
            for (int nb = 0; nb < NB; nb++) {
                mx = fmaxf(mx, acc[nb].x);
                my = fmaxf(my, acc[nb].y);
            }
            __syncwarp();  // before next chunk overwrites ys
        }

        size_t ob = (size_t)gi * CH;
        out[ob + k0]     = mx + b2s[k0];
        out[ob + k0 + 1] = my + b2s[k0 + 1];
    }
}

// ---------------- final MLP: 192 -> 128 -> 64 -> 32 -> 2, log_softmax ------------
__global__ void __launch_bounds__(512) mlp_kernel(
    const float* __restrict__ x1, const float* __restrict__ x2,
    const float* __restrict__ x3,
    const float* __restrict__ mw1, const float* __restrict__ mb1,
    const float* __restrict__ mw2, const float* __restrict__ mb2,
    const float* __restrict__ mw3, const float* __restrict__ mb3,
    const float* __restrict__ mw4, const float* __restrict__ mb4,
    float* __restrict__ out) {
    extern __shared__ float s[];
    float* w1s = s;
    float* w2s = w1s + 24576;
    float* w3s = w2s + 8192;
    float* w4s = w3s + 2048;
    float* b1s = w4s + 64;
    float* b2s = b1s + 128;
    float* b3s = b2s + 64;
    float* b4s = b3s + 32;
    float* fbuf = b4s + 4;
    float* hbuf = fbuf + 16 * 192;

    const int tid = threadIdx.x;
    const int w = tid >> 5, lane = tid & 31;
    for (int t = tid; t < 24576; t += 512) w1s[t] = mw1[t];
    for (int t = tid; t < 8192; t += 512) w2s[t] = mw2[t];
    for (int t = tid; t < 2048; t += 512) w3s[t] = mw3[t];
    if (tid < 64) w4s[tid] = mw4[tid];
    if (tid < 128) b1s[tid] = mb1[tid];
    if (tid < 64) b2s[tid] = mb2[tid];
    if (tid < 32) b3s[tid] = mb3[tid];
    if (tid < 2) b4s[tid] = mb4[tid];
    __syncthreads();

    const int ptsPerBlock = (BATCH * NPTS) / gridDim.x;
    const int pbase = blockIdx.x * ptsPerBlock;
    float* f = fbuf + w * 192;
    float* h = hbuf + w * 128;

    for (int pt = pbase + w; pt < pbase + ptsPerBlock; pt += 16) {
        for (int t = lane; t < 64; t += 32) {
            f[t]       = x1[(size_t)pt * 64 + t];
            f[64 + t]  = x2[(size_t)pt * 64 + t];
            f[128 + t] = x3[(size_t)pt * 64 + t];
        }
        __syncwarp();
        float4 a1 = *(const float4*)&b1s[4 * lane];
        for (int j = 0; j < 192; j += 4) {
            float4 xv = *(const float4*)&f[j];
            const float* wb = &w1s[j * 128 + 4 * lane];
            float4 w0 = *(const float4*)(wb);
            float4 w1v = *(const float4*)(wb + 128);
            float4 w2v = *(const float4*)(wb + 256);
            float4 w3v = *(const float4*)(wb + 384);
            a1.x = fmaf(xv.x, w0.x, a1.x); a1.y = fmaf(xv.x, w0.y, a1.y);
            a1.z = fmaf(xv.x, w0.z, a1.z); a1.w = fmaf(xv.x, w0.w, a1.w);
            a1.x = fmaf(xv.y, w1v.x, a1.x); a1.y = fmaf(xv.y, w1v.y, a1.y);
            a1.z = fmaf(xv.y, w1v.z, a1.z); a1.w = fmaf(xv.y, w1v.w, a1.w);
            a1.x = fmaf(xv.z, w2v.x, a1.x); a1.y = fmaf(xv.z, w2v.y, a1.y);
            a1.z = fmaf(xv.z, w2v.z, a1.z); a1.w = fmaf(xv.z, w2v.w, a1.w);
            a1.x = fmaf(xv.w, w3v.x, a1.x); a1.y = fmaf(xv.w, w3v.y, a1.y);
            a1.z = fmaf(xv.w, w3v.z, a1.z); a1.w = fmaf(xv.w, w3v.w, a1.w);
        }
        h[4 * lane]     = fmaxf(a1.x, 0.f);
        h[4 * lane + 1] = fmaxf(a1.y, 0.f);
        h[4 * lane + 2] = fmaxf(a1.z, 0.f);
        h[4 * lane + 3] = fmaxf(a1.w, 0.f);
        __syncwarp();
        float2 a2 = *(const float2*)&b2s[2 * lane];
        for (int j = 0; j < 128; j += 4) {
            float4 hv = *(const float4*)&h[j];
            const float* wb = &w2s[j * 64 + 2 * lane];
            float2 w0 = *(const float2*)(wb);
            float2 w1v = *(const float2*)(wb + 64);
            float2 w2v = *(const float2*)(wb + 128);
            float2 w3v = *(const float2*)(wb + 192);
            a2.x = fmaf(hv.x, w0.x, a2.x); a2.y = fmaf(hv.x, w0.y, a2.y);
            a2.x = fmaf(hv.y, w1v.x, a2.x); a2.y = fmaf(hv.y, w1v.y, a2.y);
            a2.x = fmaf(hv.z, w2v.x, a2.x); a2.y = fmaf(hv.z, w2v.y, a2.y);
            a2.x = fmaf(hv.w, w3v.x, a2.x); a2.y = fmaf(hv.w, w3v.y, a2.y);
        }
        __syncwarp();
        f[2 * lane]     = fmaxf(a2.x, 0.f);
        f[2 * lane + 1] = fmaxf(a2.y, 0.f);
        __syncwarp();
        float a3 = b3s[lane];
        for (int j = 0; j < 64; j++) a3 = fmaf(f[j], w3s[j * 32 + lane], a3);
        a3 = fmaxf(a3, 0.f);
        __syncwarp();
        h[lane] = a3;
        __syncwarp();
        float o = 0.f;
        if (lane < 2) {
            o = b4s[lane];
            for (int j = 0; j < 32; j++) o = fmaf(h[j], w4s[j * 2 + lane], o);
        }
        float oo = __shfl_xor_sync(0xffffffffu, o, 1);
        if (lane < 2) {
            float mm = fmaxf(o, oo);
            float lse = mm + logf(expf(o - mm) + expf(oo - mm));
            out[(size_t)pt * 2 + lane] = o - lse;
        }
        __syncwarp();
    }
}

// ---------------- launch -------------------------------------------------------
static constexpr size_t EC_SMEM =
    (size_t)(CH * CH + CH + 8 * 8 * CH) * 4 + 8 * KK * 4;
static constexpr size_t MLP_SMEM =
    (size_t)(24576 + 8192 + 2048 + 64 + 128 + 64 + 32 + 4 + 16 * 192 + 16 * 128) * 4;

extern "C" void kernel_launch(void* const* d_in, const int* in_sizes, int n_in,
                              void* d_out, int out_size) {
    (void)in_sizes; (void)n_in; (void)out_size;
    const float* x    = (const float*)d_in[0];
    const float* c1w1 = (const float*)d_in[1];
    const float* c1b1 = (const float*)d_in[2];
    const float* c1w2 = (const float*)d_in[3];
    const float* c1b2 = (const float*)d_in[4];
    const float* c2w1 = (const float*)d_in[5];
    const float* c2b1 = (const float*)d_in[6];
    const float* c2w2 = (const float*)d_in[7];
    const float* c2b2 = (const float*)d_in[8];
    const float* c3w1 = (const float*)d_in[9];
    const float* c3b1 = (const float*)d_in[10];
    const float* c3w2 = (const float*)d_in[11];
    const float* c3b2 = (const float*)d_in[12];
    const float* mw1  = (const float*)d_in[13];
    const float* mb1  = (const float*)d_in[14];
    const float* mw2  = (const float*)d_in[15];
    const float* mb2  = (const float*)d_in[16];
    const float* mw3  = (const float*)d_in[17];
    const float* mb3  = (const float*)d_in[18];
    const float* mw4  = (const float*)d_in[19];
    const float* mb4  = (const float*)d_in[20];
    float* outp = (float*)d_out;

    float *x1p, *x2p, *x3p, *xtp, *basep, *yp;
    int* idxp;
    cudaGetSymbolAddress((void**)&x1p, g_x1);
    cudaGetSymbolAddress((void**)&x2p, g_x2);
    cudaGetSymbolAddress((void**)&x3p, g_x3);
    cudaGetSymbolAddress((void**)&xtp, g_xt);
    cudaGetSymbolAddress((void**)&basep, g_base);
    cudaGetSymbolAddress((void**)&yp, g_y);
    cudaGetSymbolAddress((void**)&idxp, g_idx);

    cudaFuncSetAttribute(edgeconv_kernel,
                         cudaFuncAttributeMaxDynamicSharedMemorySize, (int)EC_SMEM);
    cudaFuncSetAttribute(mlp_kernel,
                         cudaFuncAttributeMaxDynamicSharedMemorySize, (int)MLP_SMEM);

    const int nblk_knn  = BATCH * NPTS / 8;   // 8192
    const int nblk_ec   = BATCH * NPTS / 32;  // 2048
    const int nblk_yb   = BATCH * NPTS / 64;  // 1024
    const int nblk_tr   = BATCH * (NPTS / 64);// 1024

    knn_kernel<1><<<nblk_knn, 256>>>(x, idxp);
    yb_kernel<1><<<nblk_yb, 256>>>(x, c1w1, c1b1, basep, yp);
    edgeconv_kernel<<<nblk_ec, 256, EC_SMEM>>>(idxp, basep, yp, c1w2, c1b2, x1p);

    transpose_kernel<<<nblk_tr, 256>>>(x1p, xtp);
    knn_t_kernel<<<nblk_knn, 256>>>(xtp, idxp);
    yb_kernel<64><<<nblk_yb, 256>>>(x1p, c2w1, c2b1, basep, yp);
    edgeconv_kernel<<<nblk_ec, 256, EC_SMEM>>>(idxp, basep, yp, c2w2, c2b2, x2p);

    transpose_kernel<<<nblk_tr, 256>>>(x2p, xtp);
    knn_t_kernel<<<nblk_knn, 256>>>(xtp, idxp);
    yb_kernel<64><<<nblk_yb, 256>>>(x2p, c3w1, c3b1, basep, yp);
    edgeconv_kernel<<<nblk_ec, 256, EC_SMEM>>>(idxp, basep, yp, c3w2, c3b2, x3p);

    mlp_kernel<<<128, 512, MLP_SMEM>>>(x1p, x2p, x3p, mw1, mb1, mw2, mb2,
                                       mw3, mb3, mw4, mb4, outp);
}

// round 10
// speedup vs baseline: 2.5144x; 1.0632x over previous
#include <cuda_runtime.h>
#include <math.h>
#include <float.h>

#define BATCH 64
#define NPTS  1024
#define KK    16
#define CH    64

// ---------------- scratch (static device globals; no allocation) ----------------
__device__ __align__(16) float g_x1[BATCH * NPTS * CH];
__device__ __align__(16) float g_x2[BATCH * NPTS * CH];
__device__ __align__(16) float g_x3[BATCH * NPTS * CH];
__device__ __align__(16) float g_xt[BATCH * NPTS * CH];   // transposed features
__device__ __align__(16) float g_base[BATCH * NPTS * CH]; // b1 + x@w1a - x@w1b
__device__ __align__(16) float g_y[BATCH * NPTS * CH];    // x@w1b
__device__ int g_idx[BATCH * NPTS * KK];

// ---------------- warp bitonic sort of 32 (value,index) pairs, lex ascending ----
__device__ __forceinline__ void bitonic32(float& sv, int& si, int lane) {
#pragma unroll
    for (int size = 2; size <= 32; size <<= 1) {
#pragma unroll
        for (int stride = size >> 1; stride > 0; stride >>= 1) {
            float ov = __shfl_xor_sync(0xffffffffu, sv, stride);
            int oi = __shfl_xor_sync(0xffffffffu, si, stride);
            bool dirDesc = (lane & size) != 0;
            bool iAmLower = (lane & stride) == 0;
            bool wantSmaller = iAmLower != dirDesc;
            bool otherLess = (ov < sv) || (ov == sv && oi < si);
            if (wantSmaller == otherLess) { sv = ov; si = oi; }
        }
    }
}

// ---------------- warp top-16 selection from a 1024 row (exact lex) -------------
__device__ __forceinline__ void warp_select16(float* row, int lane,
                                              int* __restrict__ outp) {
    float v[32];
#pragma unroll
    for (int r = 0; r < 32; r++) v[r] = row[lane + 32 * r];

    float lv = v[0];
    int li = lane;
#pragma unroll
    for (int r = 1; r < 32; r++) {
        if (v[r] < lv) { lv = v[r]; li = lane + 32 * r; }
    }
    float sv = lv; int si = li;
    bitonic32(sv, si, lane);
    float Tv = __shfl_sync(0xffffffffu, sv, 15);
    int   Ti = __shfl_sync(0xffffffffu, si, 15);

    int cnt = 0;
#pragma unroll
    for (int r = 0; r < 32; r++) {
        int idx = lane + 32 * r;
        bool le = (v[r] < Tv) || (v[r] == Tv && idx <= Ti);
        cnt += le ? 1 : 0;
    }
    int total = __reduce_add_sync(0xffffffffu, cnt);

    if (total <= 32) {
        int pre = cnt;
#pragma unroll
        for (int o = 1; o < 32; o <<= 1) {
            int n = __shfl_up_sync(0xffffffffu, pre, o);
            if (lane >= o) pre += n;
        }
        pre -= cnt;
        float* candV = row;
        int* candI = (int*)(row + 32);
        int off = pre;
#pragma unroll
        for (int r = 0; r < 32; r++) {
            int idx = lane + 32 * r;
            bool le = (v[r] < Tv) || (v[r] == Tv && idx <= Ti);
            if (le) { candV[off] = v[r]; candI[off] = idx; off++; }
        }
        __syncwarp();
        float cv = FLT_MAX;
        int ci = 0x7FFFFFFF;
        if (lane < total) { cv = candV[lane]; ci = candI[lane]; }
        bitonic32(cv, ci, lane);
        if (lane < KK) outp[lane] = ci;
    } else {
        for (int k = 0; k < KK; k++) {
            float bv = v[0];
            int br = 0;
#pragma unroll
            for (int r = 1; r < 32; r++) {
                if (v[r] < bv) { bv = v[r]; br = r; }
            }
            int bi = lane + 32 * br;
#pragma unroll
            for (int o = 16; o > 0; o >>= 1) {
                float ov = __shfl_xor_sync(0xffffffffu, bv, o);
                int oi = __shfl_xor_sync(0xffffffffu, bi, o);
                if (ov < bv || (ov == bv && oi < bi)) { bv = ov; bi = oi; }
            }
            if (lane == 0) outp[k] = bi;
            if ((bi & 31) == lane) {
                int rr = bi >> 5;
#pragma unroll
                for (int r = 0; r < 32; r++)
                    if (r == rr) v[r] = FLT_MAX;
            }
        }
    }
}

// ---------------- kNN (D=1): sort-based window selection ------------------------
// One block per batch. Bitonic-sort (value, index) lex-ascending; the top-16 of
// a query at sorted rank r lies within ranks [r-15, r+15] (1-D contiguity; same
// -value runs are index-sorted so tie-break selections stay in-window; same
// -value index swaps are feature-identical in D=1).
__global__ void __launch_bounds__(512) knn1_kernel(const float* __restrict__ x,
                                                   int* __restrict__ idx_out) {
    __shared__ float sv[NPTS];
    __shared__ int si[NPTS];
    const int b = blockIdx.x;
    const int tid = threadIdx.x;  // 512

    for (int t = tid; t < NPTS; t += 512) {
        sv[t] = x[(size_t)b * NPTS + t];
        si[t] = t;
    }
    __syncthreads();

    // bitonic sort, lex ascending
    for (int size = 2; size <= NPTS; size <<= 1) {
        for (int stride = size >> 1; stride > 0; stride >>= 1) {
            int i = ((tid & ~(stride - 1)) << 1) | (tid & (stride - 1));
            int j = i | stride;
            float va = sv[i], vb = sv[j];
            int ia = si[i], ib = si[j];
            bool agtb = (va > vb) || (va == vb && ia > ib);
            bool asc = ((i & size) == 0);
            if (agtb == asc) { sv[i] = vb; si[i] = ib; sv[j] = va; si[j] = ia; }
            __syncthreads();
        }
    }

    // per-point window selection: 16 warps x 64 points each
    const int w = tid >> 5, lane = tid & 31;
    for (int r = w * 64; r < w * 64 + 64; r++) {
        float xi = sv[r];
        int q = r - 15 + lane;  // lane 0..31 -> ranks r-15..r+16
        bool valid = (q >= 0) && (q < NPTS);
        float cv = FLT_MAX;
        int ci = 0x7FFFFFFF;
        if (valid) {
            float xj = sv[q];
            cv = (xi * xi + xj * xj) - 2.f * (xi * xj);
            ci = si[q];
        }
        bitonic32(cv, ci, lane);
        int orig = si[r];
        if (lane < KK)
            idx_out[((size_t)(b * NPTS + orig)) * KK + lane] = ci;
    }
}

// ---------------- transpose: [NPTS, CH] -> [CH, NPTS] per batch ------------------
__global__ void __launch_bounds__(256) transpose_kernel(const float* __restrict__ feat,
                                                        float* __restrict__ featT) {
    __shared__ float tile[64 * 65];
    const int tid = threadIdx.x;
    const int bpB = NPTS / 64;
    const int b = blockIdx.x / bpB;
    const int row0 = (blockIdx.x % bpB) * 64;
    const float* fb = feat + ((size_t)b * NPTS + row0) * CH;
    for (int t = tid; t < 64 * 64; t += 256) {
        int r = t >> 6, c = t & 63;
        tile[c * 65 + r] = fb[r * CH + c];
    }
    __syncthreads();
    float* ob = featT + (size_t)b * CH * NPTS + row0;
    for (int t = tid; t < 64 * 64; t += 256) {
        int c = t >> 6, r = t & 63;
        ob[(size_t)c * NPTS + r] = tile[c * 65 + r];
    }
}

// ---------------- kNN (CH=64) on transposed features: coalesced loads -----------
__global__ void __launch_bounds__(256, 4) knn_t_kernel(const float* __restrict__ featT,
                                                       int* __restrict__ idx_out) {
    constexpr int PB = 8;
    __shared__ __align__(16) float dist[PB][NPTS];
    __shared__ __align__(16) float xqT[CH * PB];
    __shared__ float sqi[PB];

    const int tid = threadIdx.x;
    const int gbase = blockIdx.x * PB;
    const int b = gbase / NPTS;
    const int i0 = gbase % NPTS;
    const float* ftb = featT + (size_t)b * CH * NPTS;

    for (int t = tid; t < CH * PB; t += 256) {
        int c = t >> 3, p = t & 7;
        xqT[t] = ftb[(size_t)c * NPTS + i0 + p];
    }
    __syncthreads();
    if (tid < PB) {
        float s = 0.f;
        for (int c = 0; c < CH; c++) { float q = xqT[c * 8 + tid]; s = fmaf(q, q, s); }
        sqi[tid] = s;
    }
    __syncthreads();

    const float4* ft4 = (const float4*)ftb;
    float dot[PB][4];
    float sqj[4];
#pragma unroll
    for (int p = 0; p < PB; p++)
#pragma unroll
        for (int jj = 0; jj < 4; jj++) dot[p][jj] = 0.f;
#pragma unroll
    for (int jj = 0; jj < 4; jj++) sqj[jj] = 0.f;

    for (int c = 0; c < CH; c++) {
        float4 v = ft4[c * (NPTS / 4) + tid];
        sqj[0] = fmaf(v.x, v.x, sqj[0]);
        sqj[1] = fmaf(v.y, v.y, sqj[1]);
        sqj[2] = fmaf(v.z, v.z, sqj[2]);
        sqj[3] = fmaf(v.w, v.w, sqj[3]);
        float4 q0 = *(const float4*)&xqT[c * 8];
        float4 q1 = *(const float4*)&xqT[c * 8 + 4];
        float q[8] = {q0.x, q0.y, q0.z, q0.w, q1.x, q1.y, q1.z, q1.w};
#pragma unroll
        for (int p = 0; p < PB; p++) {
            dot[p][0] = fmaf(v.x, q[p], dot[p][0]);
            dot[p][1] = fmaf(v.y, q[p], dot[p][1]);
            dot[p][2] = fmaf(v.z, q[p], dot[p][2]);
            dot[p][3] = fmaf(v.w, q[p], dot[p][3]);
        }
    }
    const int j0 = tid * 4;
#pragma unroll
    for (int p = 0; p < PB; p++) {
        float4 dv;
        dv.x = sqi[p] + sqj[0] - 2.f * dot[p][0];
        dv.y = sqi[p] + sqj[1] - 2.f * dot[p][1];
        dv.z = sqi[p] + sqj[2] - 2.f * dot[p][2];
        dv.w = sqi[p] + sqj[3] - 2.f * dot[p][3];
        *(float4*)&dist[p][j0] = dv;
    }
    __syncthreads();

    const int g = tid >> 5, lane = tid & 31;
    warp_select16(dist[g], lane, &idx_out[((size_t)(b * NPTS + i0 + g)) * KK]);
}

// ---------------- Y/base precompute -------------------------------------------
template <int D>
__global__ void __launch_bounds__(256) yb_kernel(
    const float* __restrict__ feat, const float* __restrict__ w1,
    const float* __restrict__ b1, float* __restrict__ baseo,
    float* __restrict__ yo) {
    __shared__ float w1as[D * CH];
    __shared__ float w1bs[D * CH];
    __shared__ float b1s[CH];
    const int tid = threadIdx.x, p = tid >> 5, lane = tid & 31;
    for (int t = tid; t < D * CH; t += 256) {
        w1as[t] = w1[t];
        w1bs[t] = w1[D * CH + t];
    }
    if (tid < CH) b1s[tid] = b1[tid];
    __syncthreads();
    const int k0 = 2 * lane;
    for (int g = 0; g < 8; g++) {
        int i = blockIdx.x * 64 + g * 8 + p;
        const float* fx = feat + (size_t)i * D;
        float zx = 0.f, zy = 0.f, yx = 0.f, yy = 0.f;
        if constexpr (D == 1) {
            float xv = fx[0];
            float2 wa = *(const float2*)&w1as[k0];
            float2 wb = *(const float2*)&w1bs[k0];
            zx = xv * wa.x; zy = xv * wa.y;
            yx = xv * wb.x; yy = xv * wb.y;
        } else {
            float xr[D / 32];
#pragma unroll
            for (int h = 0; h < D / 32; h++) xr[h] = fx[h * 32 + lane];
#pragma unroll
            for (int h = 0; h < D / 32; h++) {
                for (int j = 0; j < 32; j++) {
                    float xv = __shfl_sync(0xffffffffu, xr[h], j);
                    float2 wa = *(const float2*)&w1as[(h * 32 + j) * CH + k0];
                    float2 wb = *(const float2*)&w1bs[(h * 32 + j) * CH + k0];
                    zx = fmaf(xv, wa.x, zx); zy = fmaf(xv, wa.y, zy);
                    yx = fmaf(xv, wb.x, yx); yy = fmaf(xv, wb.y, yy);
                }
            }
        }
        *(float2*)&baseo[(size_t)i * CH + k0] =
            make_float2(b1s[k0] + zx - yx, b1s[k0 + 1] + zy - yy);
        *(float2*)&yo[(size_t)i * CH + k0] = make_float2(yx, yy);
    }
}

// ---------------- EdgeConv: h1 = relu(base_i + Y_j); out = max_k h1@w2 + b2 -----
__global__ void __launch_bounds__(256, 4) edgeconv_kernel(
    const int* __restrict__ idx, const float* __restrict__ basep,
    const float* __restrict__ yp, const float* __restrict__ w2,
    const float* __restrict__ b2, float* __restrict__ out) {
    constexpr int PTS = 8;
    constexpr int NB = 8;
    constexpr int GROUPS = 4;
    extern __shared__ float s[];
    float* w2s = s;
    float* b2s = w2s + CH * CH;
    float* ys  = b2s + CH;
    int* nbr   = (int*)(ys + PTS * NB * CH);

    const int tid = threadIdx.x;
    const int p = tid >> 5, lane = tid & 31;

    for (int t = tid; t < CH * CH; t += 256) w2s[t] = w2[t];
    if (tid < CH) b2s[tid] = b2[tid];
    __syncthreads();

    const int k0 = 2 * lane;

    for (int grp = 0; grp < GROUPS; grp++) {
        const int gbase = blockIdx.x * (PTS * GROUPS) + grp * PTS;
        const int b = gbase / NPTS;
        const int i = (gbase % NPTS) + p;
        const int gi = b * NPTS + i;
        const float* yb = yp + (size_t)b * NPTS * CH;

        if (lane < KK) nbr[p * KK + lane] = idx[(size_t)gi * KK + lane];
        __syncwarp();

        float2 bse = *(const float2*)&basep[(size_t)gi * CH + k0];
        float bx = bse.x, by = bse.y;
        float mx = -FLT_MAX, my = -FLT_MAX;

        for (int c0 = 0; c0 < KK; c0 += NB) {
            for (int t = lane; t < NB * (CH / 4); t += 32) {
                int nb = t >> 4, c4 = t & 15;
                float4 vv = *(const float4*)(yb +
                    (size_t)nbr[p * KK + c0 + nb] * CH + 4 * c4);
                *(float4*)&ys[(p * NB + nb) * CH + 4 * c4] = vv;
            }
            __syncwarp();

#pragma unroll
            for (int nb = 0; nb < NB; nb++) {
                float2 h = *(const float2*)&ys[(p * NB + nb) * CH + k0];
                h.x = fmaxf(bx + h.x, 0.f);
                h.y = fmaxf(by + h.y, 0.f);
                *(float2*)&ys[(p * NB + nb) * CH + k0] = h;
            }
            __syncwarp();

            float2 acc[NB];
#pragma unroll
            for (int nb = 0; nb < NB; nb++) acc[nb] = make_float2(0.f, 0.f);
            const float* hbase = &ys[p * NB * CH];
            for (int j = 0; j < CH; j += 4) {
                const float* wb = &w2s[j * CH + k0];
                float2 wv0 = *(const float2*)(wb);
                float2 wv1 = *(const float2*)(wb + CH);
                float2 wv2 = *(const float2*)(wb + 2 * CH);
                float2 wv3 = *(const float2*)(wb + 3 * CH);
#pragma unroll
                for (int nb = 0; nb < NB; nb++) {
                    float4 hv = *(const float4*)(hbase + nb * CH + j);
                    acc[nb].x = fmaf(hv.x, wv0.x, acc[nb].x);
                    acc[nb].y = fmaf(hv.x, wv0.y, acc[nb].y);
                    acc[nb].x = fmaf(hv.y, wv1.x, acc[nb].x);
                    acc[nb].y = fmaf(hv.y, wv1.y, acc[nb].y);
                    acc[nb].x = fmaf(hv.z, wv2.x, acc[nb].x);
                    acc[nb].y = fmaf(hv.z, wv2.y, acc[nb].y);
                    acc[nb].x = fmaf(hv.w, wv3.x, acc[nb].x);
                    acc[nb].y = fmaf(hv.w, wv3.y, acc[nb].y);
                }
            }
#pragma unroll
            for (int nb = 0; nb < NB; nb++) {
                mx = fmaxf(mx, acc[nb].x);
                my = fmaxf(my, acc[nb].y);
            }
            __syncwarp();
        }

        size_t ob = (size_t)gi * CH;
        out[ob + k0]     = mx + b2s[k0];
        out[ob + k0 + 1] = my + b2s[k0 + 1];
    }
}

// ---------------- final MLP: 192 -> 128 -> 64 -> 32 -> 2, log_softmax ------------
__global__ void __launch_bounds__(512) mlp_kernel(
    const float* __restrict__ x1, const float* __restrict__ x2,
    const float* __restrict__ x3,
    const float* __restrict__ mw1, const float* __restrict__ mb1,
    const float* __restrict__ mw2, const float* __restrict__ mb2,
    const float* __restrict__ mw3, const float* __restrict__ mb3,
    const float* __restrict__ mw4, const float* __restrict__ mb4,
    float* __restrict__ out) {
    extern __shared__ float s[];
    float* w1s = s;
    float* w2s = w1s + 24576;
    float* w3s = w2s + 8192;
    float* w4s = w3s + 2048;
    float* b1s = w4s + 64;
    float* b2s = b1s + 128;
    float* b3s = b2s + 64;
    float* b4s = b3s + 32;
    float* fbuf = b4s + 4;
    float* hbuf = fbuf + 16 * 192;

    const int tid = threadIdx.x;
    const int w = tid >> 5, lane = tid & 31;
    for (int t = tid; t < 24576; t += 512) w1s[t] = mw1[t];
    for (int t = tid; t < 8192; t += 512) w2s[t] = mw2[t];
    for (int t = tid; t < 2048; t += 512) w3s[t] = mw3[t];
    if (tid < 64) w4s[tid] = mw4[tid];
    if (tid < 128) b1s[tid] = mb1[tid];
    if (tid < 64) b2s[tid] = mb2[tid];
    if (tid < 32) b3s[tid] = mb3[tid];
    if (tid < 2) b4s[tid] = mb4[tid];
    __syncthreads();

    const int total = BATCH * NPTS;
    const int ptsPerBlock = (total + gridDim.x - 1) / gridDim.x;
    const int pbase = blockIdx.x * ptsPerBlock;
    const int pend = min(pbase + ptsPerBlock, total);
    float* f = fbuf + w * 192;
    float* h = hbuf + w * 128;

    for (int pt = pbase + w; pt < pend; pt += 16) {
        for (int t = lane; t < 64; t += 32) {
            f[t]       = x1[(size_t)pt * 64 + t];
            f[64 + t]  = x2[(size_t)pt * 64 + t];
            f[128 + t] = x3[(size_t)pt * 64 + t];
        }
        __syncwarp();
        float4 a1 = *(const float4*)&b1s[4 * lane];
        for (int j = 0; j < 192; j += 4) {
            float4 xv = *(const float4*)&f[j];
            const float* wb = &w1s[j * 128 + 4 * lane];
            float4 w0 = *(const float4*)(wb);
            float4 w1v = *(const float4*)(wb + 128);
            float4 w2v = *(const float4*)(wb + 256);
            float4 w3v = *(const float4*)(wb + 384);
            a1.x = fmaf(xv.x, w0.x, a1.x); a1.y = fmaf(xv.x, w0.y, a1.y);
            a1.z = fmaf(xv.x, w0.z, a1.z); a1.w = fmaf(xv.x, w0.w, a1.w);
            a1.x = fmaf(xv.y, w1v.x, a1.x); a1.y = fmaf(xv.y, w1v.y, a1.y);
            a1.z = fmaf(xv.y, w1v.z, a1.z); a1.w = fmaf(xv.y, w1v.w, a1.w);
            a1.x = fmaf(xv.z, w2v.x, a1.x); a1.y = fmaf(xv.z, w2v.y, a1.y);
            a1.z = fmaf(xv.z, w2v.z, a1.z); a1.w = fmaf(xv.z, w2v.w, a1.w);
            a1.x = fmaf(xv.w, w3v.x, a1.x); a1.y = fmaf(xv.w, w3v.y, a1.y);
            a1.z = fmaf(xv.w, w3v.z, a1.z); a1.w = fmaf(xv.w, w3v.w, a1.w);
        }
        h[4 * lane]     = fmaxf(a1.x, 0.f);
        h[4 * lane + 1] = fmaxf(a1.y, 0.f);
        h[4 * lane + 2] = fmaxf(a1.z, 0.f);
        h[4 * lane + 3] = fmaxf(a1.w, 0.f);
        __syncwarp();
        float2 a2 = *(const float2*)&b2s[2 * lane];
        for (int j = 0; j < 128; j += 4) {
            float4 hv = *(const float4*)&h[j];
            const float* wb = &w2s[j * 64 + 2 * lane];
            float2 w0 = *(const float2*)(wb);
            float2 w1v = *(const float2*)(wb + 64);
            float2 w2v = *(const float2*)(wb + 128);
            float2 w3v = *(const float2*)(wb + 192);
            a2.x = fmaf(hv.x, w0.x, a2.x); a2.y = fmaf(hv.x, w0.y, a2.y);
            a2.x = fmaf(hv.y, w1v.x, a2.x); a2.y = fmaf(hv.y, w1v.y, a2.y);
            a2.x = fmaf(hv.z, w2v.x, a2.x); a2.y = fmaf(hv.z, w2v.y, a2.y);
            a2.x = fmaf(hv.w, w3v.x, a2.x); a2.y = fmaf(hv.w, w3v.y, a2.y);
        }
        __syncwarp();
        f[2 * lane]     = fmaxf(a2.x, 0.f);
        f[2 * lane + 1] = fmaxf(a2.y, 0.f);
        __syncwarp();
        float a3 = b3s[lane];
        for (int j = 0; j < 64; j++) a3 = fmaf(f[j], w3s[j * 32 + lane], a3);
        a3 = fmaxf(a3, 0.f);
        __syncwarp();
        h[lane] = a3;
        __syncwarp();
        float o = 0.f;
        if (lane < 2) {
            o = b4s[lane];
            for (int j = 0; j < 32; j++) o = fmaf(h[j], w4s[j * 2 + lane], o);
        }
        float oo = __shfl_xor_sync(0xffffffffu, o, 1);
        if (lane < 2) {
            float mm = fmaxf(o, oo);
            float lse = mm + logf(expf(o - mm) + expf(oo - mm));
            out[(size_t)pt * 2 + lane] = o - lse;
        }
        __syncwarp();
    }
}

// ---------------- launch -------------------------------------------------------
static constexpr size_t EC_SMEM =
    (size_t)(CH * CH + CH + 8 * 8 * CH) * 4 + 8 * KK * 4;
static constexpr size_t MLP_SMEM =
    (size_t)(24576 + 8192 + 2048 + 64 + 128 + 64 + 32 + 4 + 16 * 192 + 16 * 128) * 4;

extern "C" void kernel_launch(void* const* d_in, const int* in_sizes, int n_in,
                              void* d_out, int out_size) {
    (void)in_sizes; (void)n_in; (void)out_size;
    const float* x    = (const float*)d_in[0];
    const float* c1w1 = (const float*)d_in[1];
    const float* c1b1 = (const float*)d_in[2];
    const float* c1w2 = (const float*)d_in[3];
    const float* c1b2 = (const float*)d_in[4];
    const float* c2w1 = (const float*)d_in[5];
    const float* c2b1 = (const float*)d_in[6];
    const float* c2w2 = (const float*)d_in[7];
    const float* c2b2 = (const float*)d_in[8];
    const float* c3w1 = (const float*)d_in[9];
    const float* c3b1 = (const float*)d_in[10];
    const float* c3w2 = (const float*)d_in[11];
    const float* c3b2 = (const float*)d_in[12];
    const float* mw1  = (const float*)d_in[13];
    const float* mb1  = (const float*)d_in[14];
    const float* mw2  = (const float*)d_in[15];
    const float* mb2  = (const float*)d_in[16];
    const float* mw3  = (const float*)d_in[17];
    const float* mb3  = (const float*)d_in[18];
    const float* mw4  = (const float*)d_in[19];
    const float* mb4  = (const float*)d_in[20];
    float* outp = (float*)d_out;

    float *x1p, *x2p, *x3p, *xtp, *basep, *yp;
    int* idxp;
    cudaGetSymbolAddress((void**)&x1p, g_x1);
    cudaGetSymbolAddress((void**)&x2p, g_x2);
    cudaGetSymbolAddress((void**)&x3p, g_x3);
    cudaGetSymbolAddress((void**)&xtp, g_xt);
    cudaGetSymbolAddress((void**)&basep, g_base);
    cudaGetSymbolAddress((void**)&yp, g_y);
    cudaGetSymbolAddress((void**)&idxp, g_idx);

    cudaFuncSetAttribute(edgeconv_kernel,
                         cudaFuncAttributeMaxDynamicSharedMemorySize, (int)EC_SMEM);
    cudaFuncSetAttribute(mlp_kernel,
                         cudaFuncAttributeMaxDynamicSharedMemorySize, (int)MLP_SMEM);

    const int nblk_knn  = BATCH * NPTS / 8;   // 8192
    const int nblk_ec   = BATCH * NPTS / 32;  // 2048
    const int nblk_yb   = BATCH * NPTS / 64;  // 1024
    const int nblk_tr   = BATCH * (NPTS / 64);// 1024

    knn1_kernel<<<BATCH, 512>>>(x, idxp);
    yb_kernel<1><<<nblk_yb, 256>>>(x, c1w1, c1b1, basep, yp);
    edgeconv_kernel<<<nblk_ec, 256, EC_SMEM>>>(idxp, basep, yp, c1w2, c1b2, x1p);

    transpose_kernel<<<nblk_tr, 256>>>(x1p, xtp);
    knn_t_kernel<<<nblk_knn, 256>>>(xtp, idxp);
    yb_kernel<64><<<nblk_yb, 256>>>(x1p, c2w1, c2b1, basep, yp);
    edgeconv_kernel<<<nblk_ec, 256, EC_SMEM>>>(idxp, basep, yp, c2w2, c2b2, x2p);

    transpose_kernel<<<nblk_tr, 256>>>(x2p, xtp);
    knn_t_kernel<<<nblk_knn, 256>>>(xtp, idxp);
    yb_kernel<64><<<nblk_yb, 256>>>(x2p, c3w1, c3b1, basep, yp);
    edgeconv_kernel<<<nblk_ec, 256, EC_SMEM>>>(idxp, basep, yp, c3w2, c3b2, x3p);

    mlp_kernel<<<148, 512, MLP_SMEM>>>(x1p, x2p, x3p, mw1, mb1, mw2, mb2,
                                       mw3, mb3, mw4, mb4, outp);
}

// round 11
// speedup vs baseline: 2.5405x; 1.0104x over previous
#include <cuda_runtime.h>
#include <math.h>
#include <float.h>
#include <string.h>

#define BATCH 64
#define NPTS  1024
#define KK    16
#define CH    64

typedef unsigned long long ull;

// ---------------- packed f32x2 helpers (Blackwell FFMA2 path) -------------------
__device__ __forceinline__ ull pk2(float x) {  // broadcast pack (x, x)
    ull r;
    asm("mov.b64 %0, {%1, %1};" : "=l"(r) : "f"(x));
    return r;
}
__device__ __forceinline__ void fma2(ull& d, ull a, ull b) {
    asm("fma.rn.f32x2 %0, %1, %2, %0;" : "+l"(d) : "l"(a), "l"(b));
}
__device__ __forceinline__ float2 upk(ull v) {
    float2 r;
    asm("mov.b64 {%0, %1}, %2;" : "=f"(r.x), "=f"(r.y) : "l"(v));
    return r;
}
__device__ __forceinline__ ull ld2(const float* p) {  // adjacent pair (p[0], p[1])
    ull r;
    memcpy(&r, p, 8);
    return r;
}

// ---------------- scratch (static device globals; no allocation) ----------------
__device__ __align__(16) float g_x1[BATCH * NPTS * CH];
__device__ __align__(16) float g_x2[BATCH * NPTS * CH];
__device__ __align__(16) float g_x3[BATCH * NPTS * CH];
__device__ __align__(16) float g_xt[BATCH * NPTS * CH];   // transposed features
__device__ __align__(16) float g_base[BATCH * NPTS * CH]; // b1 + x@w1a - x@w1b
__device__ __align__(16) float g_y[BATCH * NPTS * CH];    // x@w1b
__device__ int g_idx[BATCH * NPTS * KK];

// ---------------- warp bitonic sort of 32 (value,index) pairs, lex ascending ----
__device__ __forceinline__ void bitonic32(float& sv, int& si, int lane) {
#pragma unroll
    for (int size = 2; size <= 32; size <<= 1) {
#pragma unroll
        for (int stride = size >> 1; stride > 0; stride >>= 1) {
            float ov = __shfl_xor_sync(0xffffffffu, sv, stride);
            int oi = __shfl_xor_sync(0xffffffffu, si, stride);
            bool dirDesc = (lane & size) != 0;
            bool iAmLower = (lane & stride) == 0;
            bool wantSmaller = iAmLower != dirDesc;
            bool otherLess = (ov < sv) || (ov == sv && oi < si);
            if (wantSmaller == otherLess) { sv = ov; si = oi; }
        }
    }
}

// ---------------- warp top-16 selection from a 1024 row (exact lex) -------------
__device__ __forceinline__ void warp_select16(float* row, int lane,
                                              int* __restrict__ outp) {
    float v[32];
#pragma unroll
    for (int r = 0; r < 32; r++) v[r] = row[lane + 32 * r];

    float lv = v[0];
    int li = lane;
#pragma unroll
    for (int r = 1; r < 32; r++) {
        if (v[r] < lv) { lv = v[r]; li = lane + 32 * r; }
    }
    float sv = lv; int si = li;
    bitonic32(sv, si, lane);
    float Tv = __shfl_sync(0xffffffffu, sv, 15);
    int   Ti = __shfl_sync(0xffffffffu, si, 15);

    int cnt = 0;
#pragma unroll
    for (int r = 0; r < 32; r++) {
        int idx = lane + 32 * r;
        bool le = (v[r] < Tv) || (v[r] == Tv && idx <= Ti);
        cnt += le ? 1 : 0;
    }
    int total = __reduce_add_sync(0xffffffffu, cnt);

    if (total <= 32) {
        int pre = cnt;
#pragma unroll
        for (int o = 1; o < 32; o <<= 1) {
            int n = __shfl_up_sync(0xffffffffu, pre, o);
            if (lane >= o) pre += n;
        }
        pre -= cnt;
        float* candV = row;
        int* candI = (int*)(row + 32);
        int off = pre;
#pragma unroll
        for (int r = 0; r < 32; r++) {
            int idx = lane + 32 * r;
            bool le = (v[r] < Tv) || (v[r] == Tv && idx <= Ti);
            if (le) { candV[off] = v[r]; candI[off] = idx; off++; }
        }
        __syncwarp();
        float cv = FLT_MAX;
        int ci = 0x7FFFFFFF;
        if (lane < total) { cv = candV[lane]; ci = candI[lane]; }
        bitonic32(cv, ci, lane);
        if (lane < KK) outp[lane] = ci;
    } else {
        for (int k = 0; k < KK; k++) {
            float bv = v[0];
            int br = 0;
#pragma unroll
            for (int r = 1; r < 32; r++) {
                if (v[r] < bv) { bv = v[r]; br = r; }
            }
            int bi = lane + 32 * br;
#pragma unroll
            for (int o = 16; o > 0; o >>= 1) {
                float ov = __shfl_xor_sync(0xffffffffu, bv, o);
                int oi = __shfl_xor_sync(0xffffffffu, bi, o);
                if (ov < bv || (ov == bv && oi < bi)) { bv = ov; bi = oi; }
            }
            if (lane == 0) outp[k] = bi;
            if ((bi & 31) == lane) {
                int rr = bi >> 5;
#pragma unroll
                for (int r = 0; r < 32; r++)
                    if (r == rr) v[r] = FLT_MAX;
            }
        }
    }
}

// ---------------- kNN (D=1): sort-based window selection ------------------------
__global__ void __launch_bounds__(512) knn1_kernel(const float* __restrict__ x,
                                                   int* __restrict__ idx_out) {
    __shared__ float sv[NPTS];
    __shared__ int si[NPTS];
    const int b = blockIdx.x;
    const int tid = threadIdx.x;  // 512

    for (int t = tid; t < NPTS; t += 512) {
        sv[t] = x[(size_t)b * NPTS + t];
        si[t] = t;
    }
    __syncthreads();

    for (int size = 2; size <= NPTS; size <<= 1) {
        for (int stride = size >> 1; stride > 0; stride >>= 1) {
            int i = ((tid & ~(stride - 1)) << 1) | (tid & (stride - 1));
            int j = i | stride;
            float va = sv[i], vb = sv[j];
            int ia = si[i], ib = si[j];
            bool agtb = (va > vb) || (va == vb && ia > ib);
            bool asc = ((i & size) == 0);
            if (agtb == asc) { sv[i] = vb; si[i] = ib; sv[j] = va; si[j] = ia; }
            __syncthreads();
        }
    }

    const int w = tid >> 5, lane = tid & 31;
    for (int r = w * 64; r < w * 64 + 64; r++) {
        float xi = sv[r];
        int q = r - 15 + lane;
        bool valid = (q >= 0) && (q < NPTS);
        float cv = FLT_MAX;
        int ci = 0x7FFFFFFF;
        if (valid) {
            float xj = sv[q];
            cv = (xi * xi + xj * xj) - 2.f * (xi * xj);
            ci = si[q];
        }
        bitonic32(cv, ci, lane);
        int orig = si[r];
        if (lane < KK)
            idx_out[((size_t)(b * NPTS + orig)) * KK + lane] = ci;
    }
}

// ---------------- transpose: [NPTS, CH] -> [CH, NPTS] per batch ------------------
__global__ void __launch_bounds__(256) transpose_kernel(const float* __restrict__ feat,
                                                        float* __restrict__ featT) {
    __shared__ float tile[64 * 65];
    const int tid = threadIdx.x;
    const int bpB = NPTS / 64;
    const int b = blockIdx.x / bpB;
    const int row0 = (blockIdx.x % bpB) * 64;
    const float* fb = feat + ((size_t)b * NPTS + row0) * CH;
    for (int t = tid; t < 64 * 64; t += 256) {
        int r = t >> 6, c = t & 63;
        tile[c * 65 + r] = fb[r * CH + c];
    }
    __syncthreads();
    float* ob = featT + (size_t)b * CH * NPTS + row0;
    for (int t = tid; t < 64 * 64; t += 256) {
        int c = t >> 6, r = t & 63;
        ob[(size_t)c * NPTS + r] = tile[c * 65 + r];
    }
}

// ---------------- kNN (CH=64), coalesced + FFMA2 packed distance ----------------
__global__ void __launch_bounds__(256, 4) knn_t_kernel(const float* __restrict__ featT,
                                                       int* __restrict__ idx_out) {
    constexpr int PB = 8;
    __shared__ __align__(16) float dist[PB][NPTS];
    __shared__ __align__(16) float xqT[CH * PB];
    __shared__ float sqi[PB];

    const int tid = threadIdx.x;
    const int gbase = blockIdx.x * PB;
    const int b = gbase / NPTS;
    const int i0 = gbase % NPTS;
    const float* ftb = featT + (size_t)b * CH * NPTS;

    for (int t = tid; t < CH * PB; t += 256) {
        int c = t >> 3, p = t & 7;
        xqT[t] = ftb[(size_t)c * NPTS + i0 + p];
    }
    __syncthreads();
    if (tid < PB) {
        float s = 0.f;
        for (int c = 0; c < CH; c++) { float q = xqT[c * 8 + tid]; s = fmaf(q, q, s); }
        sqi[tid] = s;
    }
    __syncthreads();

    const float4* ft4 = (const float4*)ftb;
    ull dot2[PB][2];  // (jj0,jj1), (jj2,jj3)
    ull sq2[2];
#pragma unroll
    for (int p = 0; p < PB; p++) { dot2[p][0] = 0ull; dot2[p][1] = 0ull; }
    sq2[0] = 0ull; sq2[1] = 0ull;

    for (int c = 0; c < CH; c++) {
        float4 v = ft4[c * (NPTS / 4) + tid];
        ull vlo, vhi;
        memcpy(&vlo, &v.x, 8);
        memcpy(&vhi, &v.z, 8);
        fma2(sq2[0], vlo, vlo);
        fma2(sq2[1], vhi, vhi);
        float4 q0 = *(const float4*)&xqT[c * 8];
        float4 q1 = *(const float4*)&xqT[c * 8 + 4];
        float q[8] = {q0.x, q0.y, q0.z, q0.w, q1.x, q1.y, q1.z, q1.w};
#pragma unroll
        for (int p = 0; p < PB; p++) {
            ull qq = pk2(q[p]);
            fma2(dot2[p][0], vlo, qq);
            fma2(dot2[p][1], vhi, qq);
        }
    }
    float2 sa = upk(sq2[0]), sb = upk(sq2[1]);
    const float sqj[4] = {sa.x, sa.y, sb.x, sb.y};
    const int j0 = tid * 4;
#pragma unroll
    for (int p = 0; p < PB; p++) {
        float2 d0 = upk(dot2[p][0]), d1 = upk(dot2[p][1]);
        float4 dv;
        dv.x = sqi[p] + sqj[0] - 2.f * d0.x;
        dv.y = sqi[p] + sqj[1] - 2.f * d0.y;
        dv.z = sqi[p] + sqj[2] - 2.f * d1.x;
        dv.w = sqi[p] + sqj[3] - 2.f * d1.y;
        *(float4*)&dist[p][j0] = dv;
    }
    __syncthreads();

    const int g = tid >> 5, lane = tid & 31;
    warp_select16(dist[g], lane, &idx_out[((size_t)(b * NPTS + i0 + g)) * KK]);
}

// ---------------- Y/base precompute -------------------------------------------
template <int D>
__global__ void __launch_bounds__(256) yb_kernel(
    const float* __restrict__ feat, const float* __restrict__ w1,
    const float* __restrict__ b1, float* __restrict__ baseo,
    float* __restrict__ yo) {
    __shared__ float w1as[D * CH];
    __shared__ float w1bs[D * CH];
    __shared__ float b1s[CH];
    const int tid = threadIdx.x, p = tid >> 5, lane = tid & 31;
    for (int t = tid; t < D * CH; t += 256) {
        w1as[t] = w1[t];
        w1bs[t] = w1[D * CH + t];
    }
    if (tid < CH) b1s[tid] = b1[tid];
    __syncthreads();
    const int k0 = 2 * lane;
    for (int g = 0; g < 8; g++) {
        int i = blockIdx.x * 64 + g * 8 + p;
        const float* fx = feat + (size_t)i * D;
        float zx = 0.f, zy = 0.f, yx = 0.f, yy = 0.f;
        if constexpr (D == 1) {
            float xv = fx[0];
            float2 wa = *(const float2*)&w1as[k0];
            float2 wb = *(const float2*)&w1bs[k0];
            zx = xv * wa.x; zy = xv * wa.y;
            yx = xv * wb.x; yy = xv * wb.y;
        } else {
            float xr[D / 32];
#pragma unroll
            for (int h = 0; h < D / 32; h++) xr[h] = fx[h * 32 + lane];
#pragma unroll
            for (int h = 0; h < D / 32; h++) {
                for (int j = 0; j < 32; j++) {
                    float xv = __shfl_sync(0xffffffffu, xr[h], j);
                    float2 wa = *(const float2*)&w1as[(h * 32 + j) * CH + k0];
                    float2 wb = *(const float2*)&w1bs[(h * 32 + j) * CH + k0];
                    zx = fmaf(xv, wa.x, zx); zy = fmaf(xv, wa.y, zy);
                    yx = fmaf(xv, wb.x, yx); yy = fmaf(xv, wb.y, yy);
                }
            }
        }
        *(float2*)&baseo[(size_t)i * CH + k0] =
            make_float2(b1s[k0] + zx - yx, b1s[k0 + 1] + zy - yy);
        *(float2*)&yo[(size_t)i * CH + k0] = make_float2(yx, yy);
    }
}

// ---------------- EdgeConv: h1 = relu(base_i + Y_j); out = max_k h1@w2 + b2 -----
// FFMA2-packed stage-2 (acc holds the lane's 2 adjacent channels).
__global__ void __launch_bounds__(256, 4) edgeconv_kernel(
    const int* __restrict__ idx, const float* __restrict__ basep,
    const float* __restrict__ yp, const float* __restrict__ w2,
    const float* __restrict__ b2, float* __restrict__ out) {
    constexpr int PTS = 8;
    constexpr int NB = 8;
    constexpr int GROUPS = 4;
    extern __shared__ float s[];
    float* w2s = s;
    float* b2s = w2s + CH * CH;
    float* ys  = b2s + CH;
    int* nbr   = (int*)(ys + PTS * NB * CH);

    const int tid = threadIdx.x;
    const int p = tid >> 5, lane = tid & 31;

    for (int t = tid; t < CH * CH; t += 256) w2s[t] = w2[t];
    if (tid < CH) b2s[tid] = b2[tid];
    __syncthreads();

    const int k0 = 2 * lane;

    for (int grp = 0; grp < GROUPS; grp++) {
        const int gbase = blockIdx.x * (PTS * GROUPS) + grp * PTS;
        const int b = gbase / NPTS;
        const int i = (gbase % NPTS) + p;
        const int gi = b * NPTS + i;
        const float* yb = yp + (size_t)b * NPTS * CH;

        if (lane < KK) nbr[p * KK + lane] = idx[(size_t)gi * KK + lane];
        __syncwarp();

        float2 bse = *(const float2*)&basep[(size_t)gi * CH + k0];
        float bx = bse.x, by = bse.y;
        float mx = -FLT_MAX, my = -FLT_MAX;

        for (int c0 = 0; c0 < KK; c0 += NB) {
            for (int t = lane; t < NB * (CH / 4); t += 32) {
                int nb = t >> 4, c4 = t & 15;
                float4 vv = *(const float4*)(yb +
                    (size_t)nbr[p * KK + c0 + nb] * CH + 4 * c4);
                *(float4*)&ys[(p * NB + nb) * CH + 4 * c4] = vv;
            }
            __syncwarp();

#pragma unroll
            for (int nb = 0; nb < NB; nb++) {
                float2 h = *(const float2*)&ys[(p * NB + nb) * CH + k0];
                h.x = fmaxf(bx + h.x, 0.f);
                h.y = fmaxf(by + h.y, 0.f);
                *(float2*)&ys[(p * NB + nb) * CH + k0] = h;
            }
            __syncwarp();

            ull acc2[NB];
#pragma unroll
            for (int nb = 0; nb < NB; nb++) acc2[nb] = 0ull;
            const float* hbase = &ys[p * NB * CH];
            for (int j = 0; j < CH; j += 4) {
                const float* wb = &w2s[j * CH + k0];
                ull w0 = ld2(wb);
                ull w1 = ld2(wb + CH);
                ull w2v = ld2(wb + 2 * CH);
                ull w3v = ld2(wb + 3 * CH);
#pragma unroll
                for (int nb = 0; nb < NB; nb++) {
                    float4 hv = *(const float4*)(hbase + nb * CH + j);
                    fma2(acc2[nb], pk2(hv.x), w0);
                    fma2(acc2[nb], pk2(hv.y), w1);
                    fma2(acc2[nb], pk2(hv.z), w2v);
                    fma2(acc2[nb], pk2(hv.w), w3v);
                }
            }
#pragma unroll
            for (int nb = 0; nb < NB; nb++) {
                float2 a = upk(acc2[nb]);
                mx = fmaxf(mx, a.x);
                my = fmaxf(my, a.y);
            }
            __syncwarp();
        }

        size_t ob = (size_t)gi * CH;
        out[ob + k0]     = mx + b2s[k0];
        out[ob + k0 + 1] = my + b2s[k0 + 1];
    }
}

// ---------------- final MLP: 192 -> 128 -> 64 -> 32 -> 2, log_softmax ------------
__global__ void __launch_bounds__(512) mlp_kernel(
    const float* __restrict__ x1, const float* __restrict__ x2,
    const float* __restrict__ x3,
    const float* __restrict__ mw1, const float* __restrict__ mb1,
    const float* __restrict__ mw2, const float* __restrict__ mb2,
    const float* __restrict__ mw3, const float* __restrict__ mb3,
    const float* __restrict__ mw4, const float* __restrict__ mb4,
    float* __restrict__ out) {
    extern __shared__ float s[];
    float* w1s = s;
    float* w2s = w1s + 24576;
    float* w3s = w2s + 8192;
    float* w4s = w3s + 2048;
    float* b1s = w4s + 64;
    float* b2s = b1s + 128;
    float* b3s = b2s + 64;
    float* b4s = b3s + 32;
    float* fbuf = b4s + 4;
    float* hbuf = fbuf + 16 * 192;

    const int tid = threadIdx.x;
    const int w = tid >> 5, lane = tid & 31;
    for (int t = tid; t < 24576; t += 512) w1s[t] = mw1[t];
    for (int t = tid; t < 8192; t += 512) w2s[t] = mw2[t];
    for (int t = tid; t < 2048; t += 512) w3s[t] = mw3[t];
    if (tid < 64) w4s[tid] = mw4[tid];
    if (tid < 128) b1s[tid] = mb1[tid];
    if (tid < 64) b2s[tid] = mb2[tid];
    if (tid < 32) b3s[tid] = mb3[tid];
    if (tid < 2) b4s[tid] = mb4[tid];
    __syncthreads();

    const int total = BATCH * NPTS;
    const int ptsPerBlock = (total + gridDim.x - 1) / gridDim.x;
    const int pbase = blockIdx.x * ptsPerBlock;
    const int pend = min(pbase + ptsPerBlock, total);
    float* f = fbuf + w * 192;
    float* h = hbuf + w * 128;

    for (int pt = pbase + w; pt < pend; pt += 16) {
        for (int t = lane; t < 64; t += 32) {
            f[t]       = x1[(size_t)pt * 64 + t];
            f[64 + t]  = x2[(size_t)pt * 64 + t];
            f[128 + t] = x3[(size_t)pt * 64 + t];
        }
        __syncwarp();
        // layer 1: 192 -> 128, lane owns 4 channels (2 packed pairs)
        ull a1lo = ld2(&b1s[4 * lane]);
        ull a1hi = ld2(&b1s[4 * lane + 2]);
        for (int j = 0; j < 192; j += 4) {
            float4 xv = *(const float4*)&f[j];
            const float* wb = &w1s[j * 128 + 4 * lane];
            float4 w0 = *(const float4*)(wb);
            float4 w1v = *(const float4*)(wb + 128);
            float4 w2v = *(const float4*)(wb + 256);
            float4 w3v = *(const float4*)(wb + 384);
            ull xx;
            xx = pk2(xv.x);
            { ull wl, wh; memcpy(&wl, &w0.x, 8); memcpy(&wh, &w0.z, 8);
              fma2(a1lo, xx, wl); fma2(a1hi, xx, wh); }
            xx = pk2(xv.y);
            { ull wl, wh; memcpy(&wl, &w1v.x, 8); memcpy(&wh, &w1v.z, 8);
              fma2(a1lo, xx, wl); fma2(a1hi, xx, wh); }
            xx = pk2(xv.z);
            { ull wl, wh; memcpy(&wl, &w2v.x, 8); memcpy(&wh, &w2v.z, 8);
              fma2(a1lo, xx, wl); fma2(a1hi, xx, wh); }
            xx = pk2(xv.w);
            { ull wl, wh; memcpy(&wl, &w3v.x, 8); memcpy(&wh, &w3v.z, 8);
              fma2(a1lo, xx, wl); fma2(a1hi, xx, wh); }
        }
        {
            float2 alo = upk(a1lo), ahi = upk(a1hi);
            h[4 * lane]     = fmaxf(alo.x, 0.f);
            h[4 * lane + 1] = fmaxf(alo.y, 0.f);
            h[4 * lane + 2] = fmaxf(ahi.x, 0.f);
            h[4 * lane + 3] = fmaxf(ahi.y, 0.f);
        }
        __syncwarp();
        // layer 2: 128 -> 64, lane owns 2 channels (1 packed pair)
        ull a2p = ld2(&b2s[2 * lane]);
        for (int j = 0; j < 128; j += 4) {
            float4 hv = *(const float4*)&h[j];
            const float* wb = &w2s[j * 64 + 2 * lane];
            fma2(a2p, pk2(hv.x), ld2(wb));
            fma2(a2p, pk2(hv.y), ld2(wb + 64));
            fma2(a2p, pk2(hv.z), ld2(wb + 128));
            fma2(a2p, pk2(hv.w), ld2(wb + 192));
        }
        __syncwarp();
        {
            float2 a2 = upk(a2p);
            f[2 * lane]     = fmaxf(a2.x, 0.f);
            f[2 * lane + 1] = fmaxf(a2.y, 0.f);
        }
        __syncwarp();
        // layer 3: 64 -> 32
        float a3 = b3s[lane];
        for (int j = 0; j < 64; j++) a3 = fmaf(f[j], w3s[j * 32 + lane], a3);
        a3 = fmaxf(a3, 0.f);
        __syncwarp();
        h[lane] = a3;
        __syncwarp();
        // layer 4 + log_softmax (2 classes)
        float o = 0.f;
        if (lane < 2) {
            o = b4s[lane];
            for (int j = 0; j < 32; j++) o = fmaf(h[j], w4s[j * 2 + lane], o);
        }
        float oo = __shfl_xor_sync(0xffffffffu, o, 1);
        if (lane < 2) {
            float mm = fmaxf(o, oo);
            float lse = mm + logf(expf(o - mm) + expf(oo - mm));
            out[(size_t)pt * 2 + lane] = o - lse;
        }
        __syncwarp();
    }
}

// ---------------- launch -------------------------------------------------------
static constexpr size_t EC_SMEM =
    (size_t)(CH * CH + CH + 8 * 8 * CH) * 4 + 8 * KK * 4;
static constexpr size_t MLP_SMEM =
    (size_t)(24576 + 8192 + 2048 + 64 + 128 + 64 + 32 + 4 + 16 * 192 + 16 * 128) * 4;

extern "C" void kernel_launch(void* const* d_in, const int* in_sizes, int n_in,
                              void* d_out, int out_size) {
    (void)in_sizes; (void)n_in; (void)out_size;
    const float* x    = (const float*)d_in[0];
    const float* c1w1 = (const float*)d_in[1];
    const float* c1b1 = (const float*)d_in[2];
    const float* c1w2 = (const float*)d_in[3];
    const float* c1b2 = (const float*)d_in[4];
    const float* c2w1 = (const float*)d_in[5];
    const float* c2b1 = (const float*)d_in[6];
    const float* c2w2 = (const float*)d_in[7];
    const float* c2b2 = (const float*)d_in[8];
    const float* c3w1 = (const float*)d_in[9];
    const float* c3b1 = (const float*)d_in[10];
    const float* c3w2 = (const float*)d_in[11];
    const float* c3b2 = (const float*)d_in[12];
    const float* mw1  = (const float*)d_in[13];
    const float* mb1  = (const float*)d_in[14];
    const float* mw2  = (const float*)d_in[15];
    const float* mb2  = (const float*)d_in[16];
    const float* mw3  = (const float*)d_in[17];
    const float* mb3  = (const float*)d_in[18];
    const float* mw4  = (const float*)d_in[19];
    const float* mb4  = (const float*)d_in[20];
    float* outp = (float*)d_out;

    float *x1p, *x2p, *x3p, *xtp, *basep, *yp;
    int* idxp;
    cudaGetSymbolAddress((void**)&x1p, g_x1);
    cudaGetSymbolAddress((void**)&x2p, g_x2);
    cudaGetSymbolAddress((void**)&x3p, g_x3);
    cudaGetSymbolAddress((void**)&xtp, g_xt);
    cudaGetSymbolAddress((void**)&basep, g_base);
    cudaGetSymbolAddress((void**)&yp, g_y);
    cudaGetSymbolAddress((void**)&idxp, g_idx);

    cudaFuncSetAttribute(edgeconv_kernel,
                         cudaFuncAttributeMaxDynamicSharedMemorySize, (int)EC_SMEM);
    cudaFuncSetAttribute(mlp_kernel,
                         cudaFuncAttributeMaxDynamicSharedMemorySize, (int)MLP_SMEM);

    const int nblk_knn  = BATCH * NPTS / 8;   // 8192
    const int nblk_ec   = BATCH * NPTS / 32;  // 2048
    const int nblk_yb   = BATCH * NPTS / 64;  // 1024
    const int nblk_tr   = BATCH * (NPTS / 64);// 1024

    knn1_kernel<<<BATCH, 512>>>(x, idxp);
    yb_kernel<1><<<nblk_yb, 256>>>(x, c1w1, c1b1, basep, yp);
    edgeconv_kernel<<<nblk_ec, 256, EC_SMEM>>>(idxp, basep, yp, c1w2, c1b2, x1p);

    transpose_kernel<<<nblk_tr, 256>>>(x1p, xtp);
    knn_t_kernel<<<nblk_knn, 256>>>(xtp, idxp);
    yb_kernel<64><<<nblk_yb, 256>>>(x1p, c2w1, c2b1, basep, yp);
    edgeconv_kernel<<<nblk_ec, 256, EC_SMEM>>>(idxp, basep, yp, c2w2, c2b2, x2p);

    transpose_kernel<<<nblk_tr, 256>>>(x2p, xtp);
    knn_t_kernel<<<nblk_knn, 256>>>(xtp, idxp);
    yb_kernel<64><<<nblk_yb, 256>>>(x2p, c3w1, c3b1, basep, yp);
    edgeconv_kernel<<<nblk_ec, 256, EC_SMEM>>>(idxp, basep, yp, c3w2, c3b2, x3p);

    mlp_kernel<<<148, 512, MLP_SMEM>>>(x1p, x2p, x3p, mw1, mb1, mw2, mb2,
                                       mw3, mb3, mw4, mb4, outp);
}